// round 12
// baseline (speedup 1.0000x reference)
#include <cuda_runtime.h>
#include <cuda_bf16.h>
#include <math.h>
#include <stdint.h>

// ---------------- problem constants ----------------
#define Bsz   64
#define IMGSZ 384
#define PATCH 16
#define CH    192
#define KNN   5
#define HGRID 24
#define NNODE 576
#define BN    (Bsz * NNODE)  // 36864
#define EDG   (BN * KNN)     // 184320
#define HID   768
#define PHID  1024
#define XELEM ((size_t)Bsz * 3 * IMGSZ * IMGSZ)   // 28,311,552

// ---------------- scratch ----------------
__device__ uint32_t g_wth [768 * 192];
__device__ uint32_t g_wtl [768 * 192];
__device__ uint32_t g_xh  [XELEM];
__device__ uint32_t g_xl  [XELEM];
__device__ float    g_nf  [(size_t)BN * CH];
__device__ uint32_t g_nfh [(size_t)BN * CH];
__device__ uint32_t g_nfl [(size_t)BN * CH];
__device__ float    g_sq  [BN];
__device__ float    g_d2  [(size_t)Bsz * NNODE * NNODE];
__device__ int      g_idx [BN * KNN];
__device__ float    g_P   [(size_t)BN * CH];
__device__ float    g_Q   [(size_t)BN * CH];
__device__ float    g_att [EDG];
__device__ float    g_h   [(size_t)BN * CH];
__device__ float    g_hm  [(size_t)BN * CH];
__device__ float    g_u   [(size_t)BN * HID];
__device__ float    g_t   [(size_t)BN * CH];
__device__ float    g_g   [Bsz * CH];
__device__ float    g_p   [Bsz * PHID];

__device__ __forceinline__ float gelu_exact(float v) {
    return 0.5f * v * (1.0f + erff(v * 0.70710678118654752f));
}
__device__ __forceinline__ uint32_t f2tf32(float x) {
    uint32_t r; asm("cvt.rna.tf32.f32 %0, %1;" : "=r"(r) : "f"(x)); return r;
}
__device__ __forceinline__ void split_tf32(float x, uint32_t& hi, uint32_t& lo) {
    hi = f2tf32(x);
    lo = f2tf32(x - __uint_as_float(hi));
}
__device__ __forceinline__ uint32_t smem_u32(const void* p) {
    return (uint32_t)__cvta_generic_to_shared(p);
}
__device__ __forceinline__ void ldsm4(uint32_t& r0, uint32_t& r1, uint32_t& r2,
                                      uint32_t& r3, uint32_t a) {
    asm volatile("ldmatrix.sync.aligned.m8n8.x4.shared.b16 {%0,%1,%2,%3}, [%4];"
                 : "=r"(r0), "=r"(r1), "=r"(r2), "=r"(r3) : "r"(a));
}
__device__ __forceinline__ uint32_t pkbf2(float a, float b) {
    __nv_bfloat162 t = __floats2bfloat162_rn(a, b);
    return *(uint32_t*)&t;
}
__device__ __forceinline__ void cp16(uint32_t dst, const void* src) {
    asm volatile("cp.async.cg.shared.global [%0], [%1], 16;" :: "r"(dst), "l"(src));
}
__device__ __forceinline__ void cp4(uint32_t dst, const void* src) {
    asm volatile("cp.async.ca.shared.global [%0], [%1], 4;" :: "r"(dst), "l"(src));
}
__device__ __forceinline__ void cp_commit() { asm volatile("cp.async.commit_group;"); }
__device__ __forceinline__ void cp_wait1()  { asm volatile("cp.async.wait_group 1;"); }
__device__ __forceinline__ void cp_wait0()  { asm volatile("cp.async.wait_group 0;"); }

#define MMA_TF32(acc, a0, a1, a2, a3, b0, b1)                                \
    asm volatile(                                                            \
        "mma.sync.aligned.m16n8k8.row.col.f32.tf32.tf32.f32 "               \
        "{%0,%1,%2,%3}, {%4,%5,%6,%7}, {%8,%9}, {%0,%1,%2,%3};"             \
        : "+f"(acc[0]), "+f"(acc[1]), "+f"(acc[2]), "+f"(acc[3])             \
        : "r"(a0), "r"(a1), "r"(a2), "r"(a3), "r"(b0), "r"(b1))
#define MMA_BF16(acc, a0, a1, a2, a3, b0, b1)                                \
    asm volatile(                                                            \
        "mma.sync.aligned.m16n8k16.row.col.f32.bf16.bf16.f32 "              \
        "{%0,%1,%2,%3}, {%4,%5,%6,%7}, {%8,%9}, {%0,%1,%2,%3};"             \
        : "+f"(acc[0]), "+f"(acc[1]), "+f"(acc[2]), "+f"(acc[3])             \
        : "r"(a0), "r"(a1), "r"(a2), "r"(a3), "r"(b0), "r"(b1))

#define LDSM_OFFS()                                                          \
    const int lrA = lane & 15;                                               \
    const int lcA = (lane >> 4) * 4;                                         \
    const int lrB = ((lane >> 4) << 3) + (lane & 7);                         \
    const int lcB = ((lane >> 3) & 1) * 4

// =================================================================
// pre-split kernels
// =================================================================
__global__ void split_x_kernel(const float* __restrict__ x,
                               uint32_t* __restrict__ xh, uint32_t* __restrict__ xl)
{
    size_t i = (size_t)blockIdx.x * blockDim.x + threadIdx.x;
    if (i >= XELEM / 4) return;
    float4 v = ((const float4*)x)[i];
    uint4 h, l;
    split_tf32(v.x, h.x, l.x);
    split_tf32(v.y, h.y, l.y);
    split_tf32(v.z, h.z, l.z);
    split_tf32(v.w, h.w, l.w);
    ((uint4*)xh)[i] = h;
    ((uint4*)xl)[i] = l;
}

__global__ void transpose_w_kernel(const float* __restrict__ w,
                                   uint32_t* __restrict__ wth, uint32_t* __restrict__ wtl)
{
    int i = blockIdx.x * blockDim.x + threadIdx.x;
    if (i >= 192 * 768) return;
    int n = i / 768, k = i % 768;
    uint32_t h, l;
    split_tf32(w[i], h, l);
    wth[k * 192 + n] = h;
    wtl[k * 192 + n] = l;
}

// =================================================================
// gram via tf32x3 + symmetry + cp.async double buffering.
// Dynamic smem: 2 stages x 4 arrays x 64x36 words = 73728 B.
// MMA order identical to R11 -> d2 bit-identical.
// =================================================================
__global__ __launch_bounds__(128) void gram_x3_sym_kernel(
    const uint32_t* __restrict__ nfh, const uint32_t* __restrict__ nfl,
    const float* __restrict__ sq, float* __restrict__ d2)
{
    extern __shared__ uint32_t DSM[];
    const int b = blockIdx.z;
    const uint32_t* Abh = nfh + (size_t)b * NNODE * CH;
    const uint32_t* Abl = nfl + (size_t)b * NNODE * CH;

    int p = blockIdx.x, ti = 0;
    while (p >= 9 - ti) { p -= 9 - ti; ti++; }
    const int tj = ti + p;
    const int r0b = ti * 64, c0b = tj * 64;

    const int tid  = threadIdx.x;
    const int lane = tid & 31, wid = tid >> 5;
    const int wm = (wid >> 1) * 32, wn = (wid & 1) * 32;
    const int row = tid >> 1, kq = (tid & 1) * 16;
    const int g = lane >> 2, cq = lane & 3;
    LDSM_OFFS();
    const uint32_t base = smem_u32(DSM);
    // stage layout (bytes): Ah +0, Al +9216, Bh +18432, Bl +27648; stage stride 36864

    auto fill = [&](int k0, int st) {
        uint32_t sb = base + (uint32_t)st * 36864u;
        const size_t ra = (size_t)(r0b + row) * CH + k0 + kq;
        const size_t rb = (size_t)(c0b + row) * CH + k0 + kq;
#pragma unroll
        for (int i = 0; i < 4; i++) {
            uint32_t off = (uint32_t)(row * 36 + kq + i * 4) * 4;
            cp16(sb + off,          Abh + ra + i * 4);
            cp16(sb + 9216 + off,   Abl + ra + i * 4);
            cp16(sb + 18432 + off,  Abh + rb + i * 4);
            cp16(sb + 27648 + off,  Abl + rb + i * 4);
        }
        cp_commit();
    };

    float acc[2][4][4] = {};

    fill(0, 0);
    for (int s = 0; s < 6; s++) {
        if (s + 1 < 6) fill((s + 1) * 32, (s + 1) & 1);
        if (s + 1 < 6) cp_wait1(); else cp_wait0();
        __syncthreads();

        uint32_t sb = base + (uint32_t)(s & 1) * 36864u;
        const uint32_t bAh = sb, bAl = sb + 9216, bBh = sb + 18432, bBl = sb + 27648;
#pragma unroll
        for (int kk = 0; kk < 32; kk += 8) {
            uint32_t ah[2][4], al[2][4], bh[4][2], bl[4][2];
#pragma unroll
            for (int im = 0; im < 2; im++) {
                uint32_t off = ((wm + im * 16 + lrA) * 36 + kk + lcA) * 4;
                ldsm4(ah[im][0], ah[im][1], ah[im][2], ah[im][3], bAh + off);
                ldsm4(al[im][0], al[im][1], al[im][2], al[im][3], bAl + off);
            }
#pragma unroll
            for (int q = 0; q < 2; q++) {
                uint32_t off = ((wn + q * 16 + lrB) * 36 + kk + lcB) * 4;
                ldsm4(bh[2*q][0], bh[2*q][1], bh[2*q+1][0], bh[2*q+1][1], bBh + off);
                ldsm4(bl[2*q][0], bl[2*q][1], bl[2*q+1][0], bl[2*q+1][1], bBl + off);
            }
#pragma unroll
            for (int im = 0; im < 2; im++)
#pragma unroll
                for (int in = 0; in < 4; in++) {
                    MMA_TF32(acc[im][in], ah[im][0], ah[im][1], ah[im][2], ah[im][3],
                             bh[in][0], bh[in][1]);
                    MMA_TF32(acc[im][in], ah[im][0], ah[im][1], ah[im][2], ah[im][3],
                             bl[in][0], bl[in][1]);
                    MMA_TF32(acc[im][in], al[im][0], al[im][1], al[im][2], al[im][3],
                             bh[in][0], bh[in][1]);
                }
        }
        __syncthreads();
    }

#pragma unroll
    for (int im = 0; im < 2; im++)
#pragma unroll
        for (int in = 0; in < 4; in++) {
            int cbase = c0b + wn + in * 8 + 2 * cq;
#pragma unroll
            for (int half = 0; half < 2; half++) {
                int r = r0b + wm + im * 16 + g + half * 8;
#pragma unroll
                for (int jj = 0; jj < 2; jj++) {
                    int c = cbase + jj;
                    float v = sq[b * NNODE + c] - 2.0f * acc[im][in][half * 2 + jj];
                    if (r == c) v = 3.0e38f;
                    d2[((size_t)b * NNODE + r) * NNODE + c] = v;
                }
            }
        }

    if (ti != tj) {
        float* T = (float*)DSM;
#pragma unroll
        for (int im = 0; im < 2; im++)
#pragma unroll
            for (int in = 0; in < 4; in++) {
                int cl = wn + in * 8 + 2 * cq;
#pragma unroll
                for (int half = 0; half < 2; half++) {
                    int rl = wm + im * 16 + g + half * 8;
                    T[(cl    ) * 68 + rl] = acc[im][in][half * 2 + 0];
                    T[(cl + 1) * 68 + rl] = acc[im][in][half * 2 + 1];
                }
            }
        __syncthreads();
        for (int i = tid; i < 64 * 16; i += 128) {
            int cl = i >> 4;
            int r4 = (i & 15) * 4;
            float4 dv = *(const float4*)&T[cl * 68 + r4];
            float4 sv = *(const float4*)&sq[b * NNODE + r0b + r4];
            float4 o;
            o.x = sv.x - 2.0f * dv.x;
            o.y = sv.y - 2.0f * dv.y;
            o.z = sv.z - 2.0f * dv.z;
            o.w = sv.w - 2.0f * dv.w;
            *(float4*)&d2[((size_t)b * NNODE + c0b + cl) * NNODE + r0b + r4] = o;
        }
    }
}

// =================================================================
// stem via tf32x3, pre-split inputs, cp.async double buffering.
// K-slab 32 (same ascending k order as R11's 16-slabs -> nf bit-identical).
// Dynamic smem: 2 stages x (128+128+64+64)x36 words = 110592 B.
// =================================================================
__global__ __launch_bounds__(256) void stem_x3_kernel(
    const uint32_t* __restrict__ xh, const uint32_t* __restrict__ xl,
    const uint32_t* __restrict__ wth, const uint32_t* __restrict__ wtl,
    float* __restrict__ C, uint32_t* __restrict__ Ch, uint32_t* __restrict__ Cl,
    const float* __restrict__ bias, const float* __restrict__ pos)
{
    extern __shared__ uint32_t DSM[];
    const int Nd = 192, Kd = 768;
    const int tid  = threadIdx.x;
    const int lane = tid & 31, wid = tid >> 5;
    const int wm = (wid >> 1) * 32, wn = (wid & 1) * 32;
    const int m0 = blockIdx.y * 128, n0 = blockIdx.x * 64;
    const int a_row = tid >> 1, kq = (tid & 1) * 16;
    const int b_n = tid & 63, b_k0 = (tid >> 6) * 8;
    const int g = lane >> 2, cq = lane & 3;
    LDSM_OFFS();
    const uint32_t base = smem_u32(DSM);
    // stage layout (bytes): Ah +0 (4608w), Al +18432, Bh +36864 (2304w), Bl +46080;
    // stage stride 55296 B

    const int m = m0 + a_row;
    const int bimg = m / NNODE;
    const int nsp = m % NNODE;
    const int py = nsp / HGRID, px = nsp % HGRID;
    const size_t xoff = (size_t)bimg * 3 * IMGSZ * IMGSZ
                      + (size_t)(py * PATCH) * IMGSZ + px * PATCH;

    auto fill = [&](int k0, int st) {
        uint32_t sb = base + (uint32_t)st * 55296u;
        // A: 16 contiguous values at (ci, ky, kx=0..15) where kg = k0 + kq
        int kg = k0 + kq;
        int ci = kg >> 8, ky = (kg >> 4) & 15;
        const uint32_t* srcA = xh + xoff + (size_t)ci * IMGSZ * IMGSZ + ky * IMGSZ;
        const uint32_t* srcAl = xl + xoff + (size_t)ci * IMGSZ * IMGSZ + ky * IMGSZ;
#pragma unroll
        for (int i = 0; i < 4; i++) {
            uint32_t off = (uint32_t)(a_row * 36 + kq + i * 4) * 4;
            cp16(sb + off,         srcA  + i * 4);
            cp16(sb + 18432 + off, srcAl + i * 4);
        }
        // B: 8 rows, 1 word each (stride Nd)
#pragma unroll
        for (int i = 0; i < 8; i++) {
            uint32_t off = (uint32_t)(b_n * 36 + b_k0 + i) * 4;
            size_t src = (size_t)(k0 + b_k0 + i) * Nd + n0 + b_n;
            cp4(sb + 36864 + off, wth + src);
            cp4(sb + 46080 + off, wtl + src);
        }
        cp_commit();
    };

    float acc[2][4][4] = {};

    fill(0, 0);
    const int NS = Kd / 32;   // 24 slabs
    for (int s = 0; s < NS; s++) {
        if (s + 1 < NS) fill((s + 1) * 32, (s + 1) & 1);
        if (s + 1 < NS) cp_wait1(); else cp_wait0();
        __syncthreads();

        uint32_t sb = base + (uint32_t)(s & 1) * 55296u;
        const uint32_t bAh = sb, bAl = sb + 18432, bBh = sb + 36864, bBl = sb + 46080;
#pragma unroll
        for (int kk = 0; kk < 32; kk += 8) {
            uint32_t ah[2][4], al[2][4], bh[4][2], bl[4][2];
#pragma unroll
            for (int im = 0; im < 2; im++) {
                uint32_t off = ((wm + im * 16 + lrA) * 36 + kk + lcA) * 4;
                ldsm4(ah[im][0], ah[im][1], ah[im][2], ah[im][3], bAh + off);
                ldsm4(al[im][0], al[im][1], al[im][2], al[im][3], bAl + off);
            }
#pragma unroll
            for (int q = 0; q < 2; q++) {
                uint32_t off = ((wn + q * 16 + lrB) * 36 + kk + lcB) * 4;
                ldsm4(bh[2*q][0], bh[2*q][1], bh[2*q+1][0], bh[2*q+1][1], bBh + off);
                ldsm4(bl[2*q][0], bl[2*q][1], bl[2*q+1][0], bl[2*q+1][1], bBl + off);
            }
#pragma unroll
            for (int im = 0; im < 2; im++)
#pragma unroll
                for (int in = 0; in < 4; in++) {
                    MMA_TF32(acc[im][in], ah[im][0], ah[im][1], ah[im][2], ah[im][3],
                             bh[in][0], bh[in][1]);
                    MMA_TF32(acc[im][in], ah[im][0], ah[im][1], ah[im][2], ah[im][3],
                             bl[in][0], bl[in][1]);
                    MMA_TF32(acc[im][in], al[im][0], al[im][1], al[im][2], al[im][3],
                             bh[in][0], bh[in][1]);
                }
        }
        __syncthreads();
    }

#pragma unroll
    for (int im = 0; im < 2; im++)
#pragma unroll
        for (int in = 0; in < 4; in++) {
            int cbase = n0 + wn + in * 8 + 2 * cq;
#pragma unroll
            for (int half = 0; half < 2; half++) {
                int mm = m0 + wm + im * 16 + g + half * 8;
                int sp = mm % NNODE;
#pragma unroll
                for (int jj = 0; jj < 2; jj++) {
                    int n = cbase + jj;
                    float v = acc[im][in][half * 2 + jj] + bias[n] + pos[n * NNODE + sp];
                    C[(size_t)mm * CH + n] = v;
                    uint32_t h, l;
                    split_tf32(v, h, l);
                    Ch[(size_t)mm * CH + n] = h;
                    Cl[(size_t)mm * CH + n] = l;
                }
            }
        }
}

// =================================================================
// tf32 GEMM + ldmatrix (P/Q path; unchanged). PRE=1: A pre-split hi.
// =================================================================
template <int EPI, int PRE>
__global__ __launch_bounds__(256) void tf32gemm_kernel(
    const void* __restrict__ Av, const float* __restrict__ B, float* __restrict__ C,
    int M, int N, int K,
    const float* __restrict__ bias, const float* __restrict__ gam,
    const float* __restrict__ bet,  const float* __restrict__ res)
{
    __shared__ uint32_t As[128][36];
    __shared__ uint32_t Bs[64][36];
    const int tid  = threadIdx.x;
    const int lane = tid & 31, wid = tid >> 5;
    const int wm = (wid >> 1) * 32;
    const int wn = (wid & 1) * 32;
    const int m0 = blockIdx.y * 128, n0 = blockIdx.x * 64;
    const int a_row = tid >> 1, a_k0 = (tid & 1) * 16;
    const int b_n = tid & 63, b_k0 = (tid >> 6) * 8;
    const int g = lane >> 2, cq = lane & 3;
    LDSM_OFFS();
    const uint32_t bA = smem_u32(&As[0][0]), bB = smem_u32(&Bs[0][0]);

    float acc[2][4][4] = {};

    for (int k0 = 0; k0 < K; k0 += 32) {
        if (PRE) {
            const uint32_t* Ai = (const uint32_t*)Av;
#pragma unroll
            for (int i = 0; i < 4; i++)
                *(uint4*)&As[a_row][a_k0 + i * 4] =
                    *(const uint4*)&Ai[(size_t)(m0 + a_row) * K + k0 + a_k0 + i * 4];
        } else {
            const float* A = (const float*)Av;
#pragma unroll
            for (int i = 0; i < 4; i++) {
                float4 v = *(const float4*)&A[(size_t)(m0 + a_row) * K + k0 + a_k0 + i * 4];
                As[a_row][a_k0 + i * 4 + 0] = f2tf32(v.x);
                As[a_row][a_k0 + i * 4 + 1] = f2tf32(v.y);
                As[a_row][a_k0 + i * 4 + 2] = f2tf32(v.z);
                As[a_row][a_k0 + i * 4 + 3] = f2tf32(v.w);
            }
        }
#pragma unroll
        for (int i = 0; i < 8; i++) {
            float v = B[(size_t)(k0 + b_k0 + i) * N + n0 + b_n];
            Bs[b_n][b_k0 + i] = f2tf32(v);
        }
        __syncthreads();

#pragma unroll
        for (int kk = 0; kk < 32; kk += 8) {
            uint32_t af[2][4], bf[4][2];
#pragma unroll
            for (int im = 0; im < 2; im++) {
                uint32_t off = ((wm + im * 16 + lrA) * 36 + kk + lcA) * 4;
                ldsm4(af[im][0], af[im][1], af[im][2], af[im][3], bA + off);
            }
#pragma unroll
            for (int q = 0; q < 2; q++) {
                uint32_t off = ((wn + q * 16 + lrB) * 36 + kk + lcB) * 4;
                ldsm4(bf[2*q][0], bf[2*q][1], bf[2*q+1][0], bf[2*q+1][1], bB + off);
            }
#pragma unroll
            for (int im = 0; im < 2; im++)
#pragma unroll
                for (int in = 0; in < 4; in++)
                    MMA_TF32(acc[im][in], af[im][0], af[im][1], af[im][2], af[im][3],
                             bf[in][0], bf[in][1]);
        }
        __syncthreads();
    }

#pragma unroll
    for (int im = 0; im < 2; im++)
#pragma unroll
        for (int in = 0; in < 4; in++) {
            int cbase = n0 + wn + in * 8 + 2 * cq;
#pragma unroll
            for (int half = 0; half < 2; half++) {
                int m = m0 + wm + im * 16 + g + half * 8;
#pragma unroll
                for (int jj = 0; jj < 2; jj++) {
                    int n = cbase + jj;
                    float v = acc[im][in][half * 2 + jj];
                    if (EPI == 1) v += bias[n];
                    if (EPI == 2) v = fmaxf(v + bias[n], 0.0f);
                    if (EPI == 3) v = gelu_exact((v + bias[n]) * gam[n] + bet[n]);
                    if (EPI == 4) v = res[(size_t)m * N + n] + (v + bias[n]) * gam[n] + bet[n];
                    C[(size_t)m * N + n] = v;
                }
            }
        }
}

// =================================================================
// bf16 GEMM (prediction path; unchanged from R11)
// =================================================================
template <int EPI>
__global__ __launch_bounds__(256) void bf16gemm_kernel(
    const float* __restrict__ A, const float* __restrict__ B, float* __restrict__ C,
    int M, int N, int K,
    const float* __restrict__ bias, const float* __restrict__ gam,
    const float* __restrict__ bet,  const float* __restrict__ res)
{
    __shared__ __nv_bfloat16 As[128][40];
    __shared__ __nv_bfloat16 Bs[64][40];
    const int tid  = threadIdx.x;
    const int lane = tid & 31, wid = tid >> 5;
    const int wm = (wid >> 1) * 32;
    const int wn = (wid & 1) * 32;
    const int m0 = blockIdx.y * 128, n0 = blockIdx.x * 64;
    const int a_row = tid >> 1, a_k0 = (tid & 1) * 16;
    const int b_n = tid & 63, b_k0 = (tid >> 6) * 8;
    const int g = lane >> 2, cq = lane & 3;
    const int lrA = lane & 15;
    const int lcA = (lane >> 4) * 8;
    const int lrB = ((lane >> 4) << 3) + (lane & 7);
    const int lcB = ((lane >> 3) & 1) * 8;
    const uint32_t bA = smem_u32(&As[0][0]), bB = smem_u32(&Bs[0][0]);

    float acc[2][4][4] = {};

    for (int k0 = 0; k0 < K; k0 += 32) {
        {
            const float* Ap = &A[(size_t)(m0 + a_row) * K + k0 + a_k0];
            float4 v0 = *(const float4*)(Ap + 0);
            float4 v1 = *(const float4*)(Ap + 4);
            float4 v2 = *(const float4*)(Ap + 8);
            float4 v3 = *(const float4*)(Ap + 12);
            uint4 u0, u1;
            u0.x = pkbf2(v0.x, v0.y); u0.y = pkbf2(v0.z, v0.w);
            u0.z = pkbf2(v1.x, v1.y); u0.w = pkbf2(v1.z, v1.w);
            u1.x = pkbf2(v2.x, v2.y); u1.y = pkbf2(v2.z, v2.w);
            u1.z = pkbf2(v3.x, v3.y); u1.w = pkbf2(v3.z, v3.w);
            *(uint4*)&As[a_row][a_k0 + 0] = u0;
            *(uint4*)&As[a_row][a_k0 + 8] = u1;
        }
        {
            float v[8];
#pragma unroll
            for (int i = 0; i < 8; i++)
                v[i] = B[(size_t)(k0 + b_k0 + i) * N + n0 + b_n];
            uint4 u;
            u.x = pkbf2(v[0], v[1]); u.y = pkbf2(v[2], v[3]);
            u.z = pkbf2(v[4], v[5]); u.w = pkbf2(v[6], v[7]);
            *(uint4*)&Bs[b_n][b_k0] = u;
        }
        __syncthreads();

#pragma unroll
        for (int kk = 0; kk < 32; kk += 16) {
            uint32_t af[2][4], bf[4][2];
#pragma unroll
            for (int im = 0; im < 2; im++) {
                uint32_t off = ((wm + im * 16 + lrA) * 40 + kk + lcA) * 2;
                ldsm4(af[im][0], af[im][1], af[im][2], af[im][3], bA + off);
            }
#pragma unroll
            for (int q = 0; q < 2; q++) {
                uint32_t off = ((wn + q * 16 + lrB) * 40 + kk + lcB) * 2;
                ldsm4(bf[2*q][0], bf[2*q][1], bf[2*q+1][0], bf[2*q+1][1], bB + off);
            }
#pragma unroll
            for (int im = 0; im < 2; im++)
#pragma unroll
                for (int in = 0; in < 4; in++)
                    MMA_BF16(acc[im][in], af[im][0], af[im][1], af[im][2], af[im][3],
                             bf[in][0], bf[in][1]);
        }
        __syncthreads();
    }

#pragma unroll
    for (int im = 0; im < 2; im++)
#pragma unroll
        for (int in = 0; in < 4; in++) {
            int cbase = n0 + wn + in * 8 + 2 * cq;
#pragma unroll
            for (int half = 0; half < 2; half++) {
                int m = m0 + wm + im * 16 + g + half * 8;
#pragma unroll
                for (int jj = 0; jj < 2; jj++) {
                    int n = cbase + jj;
                    float v = acc[im][in][half * 2 + jj];
                    if (EPI == 1) v += bias[n];
                    if (EPI == 2) v = fmaxf(v + bias[n], 0.0f);
                    if (EPI == 3) v = gelu_exact((v + bias[n]) * gam[n] + bet[n]);
                    if (EPI == 4) v = res[(size_t)m * N + n] + (v + bias[n]) * gam[n] + bet[n];
                    C[(size_t)m * N + n] = v;
                }
            }
        }
}

// ---------------- small-M SGEMM for pred head (M=64) ----------------
#define BM 64
#define BNT 64
#define BKT 16
template <int EPI>
__global__ __launch_bounds__(256) void sgemm_kernel(
    const float* __restrict__ A, const float* __restrict__ B, float* __restrict__ C,
    int M, int N, int K,
    const float* __restrict__ bias, const float* __restrict__ gam,
    const float* __restrict__ bet,  const float* __restrict__ res)
{
    __shared__ float As[BKT][BM];
    __shared__ float Bs[BKT][BNT];
    const int tid = threadIdx.x;
    const int tx = tid & 15, ty = tid >> 4;
    const int m0 = blockIdx.y * BM, n0 = blockIdx.x * BNT;
    const int a_m = tid >> 2, a_k = (tid & 3) * 4;
    const int b_k = tid >> 4, b_n = (tid & 15) * 4;

    float acc[4][4] = {};
    for (int k0 = 0; k0 < K; k0 += BKT) {
        float4 av = *(const float4*)&A[(size_t)(m0 + a_m) * K + k0 + a_k];
        As[a_k + 0][a_m] = av.x; As[a_k + 1][a_m] = av.y;
        As[a_k + 2][a_m] = av.z; As[a_k + 3][a_m] = av.w;
        float4 bv = *(const float4*)&B[(size_t)(k0 + b_k) * N + n0 + b_n];
        *(float4*)&Bs[b_k][b_n] = bv;
        __syncthreads();
#pragma unroll
        for (int k = 0; k < BKT; k++) {
            float ar[4], br[4];
#pragma unroll
            for (int i = 0; i < 4; i++) ar[i] = As[k][ty * 4 + i];
#pragma unroll
            for (int j = 0; j < 4; j++) br[j] = Bs[k][tx * 4 + j];
#pragma unroll
            for (int i = 0; i < 4; i++)
#pragma unroll
                for (int j = 0; j < 4; j++) acc[i][j] = fmaf(ar[i], br[j], acc[i][j]);
        }
        __syncthreads();
    }
#pragma unroll
    for (int i = 0; i < 4; i++) {
        int m = m0 + ty * 4 + i;
#pragma unroll
        for (int j = 0; j < 4; j++) {
            int n = n0 + tx * 4 + j;
            float v = acc[i][j];
            if (EPI == 1) v += bias[n];
            if (EPI == 2) v = fmaxf(v + bias[n], 0.0f);
            if (EPI == 3) v = gelu_exact((v + bias[n]) * gam[n] + bet[n]);
            if (EPI == 4) v = res[(size_t)m * N + n] + (v + bias[n]) * gam[n] + bet[n];
            C[(size_t)m * N + n] = v;
        }
    }
}

// ---------------- auxiliary kernels ----------------
__global__ void sq_kernel(const float* __restrict__ nf, float* __restrict__ sq) {
    int node = (blockIdx.x * blockDim.x + threadIdx.x) >> 5;
    int lane = threadIdx.x & 31;
    if (node >= BN) return;
    float s = 0.f;
#pragma unroll
    for (int j = 0; j < 6; j++) {
        float x = nf[(size_t)node * CH + lane + 32 * j];
        s = fmaf(x, x, s);
    }
#pragma unroll
    for (int off = 16; off; off >>= 1) s += __shfl_down_sync(0xffffffffu, s, off);
    if (lane == 0) sq[node] = s;
}

__global__ void topk_kernel(const float* __restrict__ d2, int* __restrict__ idx) {
    int row = (blockIdx.x * blockDim.x + threadIdx.x) >> 5;
    int lane = threadIdx.x & 31;
    if (row >= BN) return;
    const float* r = d2 + (size_t)row * NNODE;
    float v[18];
#pragma unroll
    for (int j = 0; j < 18; j++) v[j] = r[lane + 32 * j];
    int bimg = row / NNODE;
#pragma unroll
    for (int s = 0; s < 5; s++) {
        float bv = 3.4e38f; int bc = 1 << 30;
#pragma unroll
        for (int j = 0; j < 18; j++) {
            int c = lane + 32 * j;
            if (v[j] < bv) { bv = v[j]; bc = c; }
        }
#pragma unroll
        for (int off = 16; off; off >>= 1) {
            float ov = __shfl_down_sync(0xffffffffu, bv, off);
            int   oc = __shfl_down_sync(0xffffffffu, bc, off);
            if (ov < bv || (ov == bv && oc < bc)) { bv = ov; bc = oc; }
        }
        bc = __shfl_sync(0xffffffffu, bc, 0);
        if ((bc & 31) == lane) v[bc >> 5] = 3.4e38f;
        if (lane == 0) idx[row * KNN + s] = bimg * NNODE + bc;
    }
}

__global__ void edge_kernel(const float* __restrict__ P, const float* __restrict__ Q,
                            const int* __restrict__ idx,
                            const float* __restrict__ w2, const float* __restrict__ b2,
                            float* __restrict__ att, float* __restrict__ out)
{
    int node = (blockIdx.x * blockDim.x + threadIdx.x) >> 5;
    int lane = threadIdx.x & 31;
    if (node >= BN) return;
    float q[6], w[6];
#pragma unroll
    for (int j = 0; j < 6; j++) {
        q[j] = Q[(size_t)node * CH + lane + 32 * j];
        w[j] = w2[lane + 32 * j];
    }
    const float b2v = b2[0];
#pragma unroll
    for (int k = 0; k < KNN; k++) {
        int e = node * KNN + k;
        int src = idx[e];
        float s = 0.f;
#pragma unroll
        for (int j = 0; j < 6; j++) {
            float x = P[(size_t)src * CH + lane + 32 * j] + q[j];
            x = fmaxf(x, 0.f);
            s = fmaf(x, w[j], s);
        }
#pragma unroll
        for (int off = 16; off; off >>= 1) s += __shfl_down_sync(0xffffffffu, s, off);
        if (lane == 0) {
            float a = 1.0f / (1.0f + expf(-(s + b2v)));
            att[e] = a;
            out[e] = a;
        }
    }
}

__global__ void agg_kernel(const float* __restrict__ h, const int* __restrict__ idx,
                           const float* __restrict__ att, float* __restrict__ hm)
{
    int i = blockIdx.x;
    int c = threadIdx.x;
    float acc = h[(size_t)i * CH + c];
#pragma unroll
    for (int k = 0; k < KNN; k++) {
        int nb = idx[i * KNN + k];
        float a = att[i * KNN + k];
        acc = fmaf(a, h[(size_t)nb * CH + c], acc);
    }
    hm[(size_t)i * CH + c] = acc;
}

__global__ void pool_kernel(const float* __restrict__ t, float* __restrict__ g) {
    int b = blockIdx.x, c = threadIdx.x;
    float acc = 0.f;
    for (int n = 0; n < NNODE; n++) acc += t[((size_t)b * NNODE + n) * CH + c];
    g[b * CH + c] = acc * (1.0f / NNODE);
}

__global__ void pred_final_kernel(const float* __restrict__ p, const float* __restrict__ w2,
                                  const float* __restrict__ b2, float* __restrict__ out)
{
    int b = blockIdx.x, tid = threadIdx.x;
    float s = 0.f;
    for (int i = tid; i < PHID; i += 256) s = fmaf(p[(size_t)b * PHID + i], w2[i], s);
    __shared__ float red[256];
    red[tid] = s; __syncthreads();
    for (int st = 128; st; st >>= 1) { if (tid < st) red[tid] += red[tid + st]; __syncthreads(); }
    if (tid == 0) out[b] = red[0] + b2[0];
}

// ---------------- host launch ----------------
extern "C" void kernel_launch(void* const* d_in, const int* in_sizes, int n_in,
                              void* d_out, int out_size)
{
    const float* x        = (const float*)d_in[0];
    const float* stem_w   = (const float*)d_in[1];
    const float* stem_b   = (const float*)d_in[2];
    const float* pos      = (const float*)d_in[3];
    const float* att_w1   = (const float*)d_in[4];
    const float* att_b1   = (const float*)d_in[5];
    const float* att_w2   = (const float*)d_in[6];
    const float* att_b2   = (const float*)d_in[7];
    const float* gnn_w1   = (const float*)d_in[8];
    const float* gnn_b1   = (const float*)d_in[9];
    const float* gnn_w2   = (const float*)d_in[10];
    const float* gnn_b2   = (const float*)d_in[11];
    const float* ffn_w1   = (const float*)d_in[12];
    const float* ffn_b1   = (const float*)d_in[13];
    const float* ffn_g1   = (const float*)d_in[14];
    const float* ffn_be1  = (const float*)d_in[15];
    const float* ffn_w2   = (const float*)d_in[16];
    const float* ffn_b2   = (const float*)d_in[17];
    const float* ffn_g2   = (const float*)d_in[18];
    const float* ffn_be2  = (const float*)d_in[19];
    const float* pred_w1  = (const float*)d_in[20];
    const float* pred_b1  = (const float*)d_in[21];
    const float* pred_g   = (const float*)d_in[22];
    const float* pred_be  = (const float*)d_in[23];
    const float* pred_w2  = (const float*)d_in[24];
    const float* pred_b2  = (const float*)d_in[25];
    float* out = (float*)d_out;

    float *p_nf, *p_sq, *p_d2, *p_P, *p_Q, *p_att, *p_h, *p_hm, *p_u, *p_t, *p_g, *p_p;
    uint32_t *p_nfh, *p_nfl, *p_wth, *p_wtl, *p_xh, *p_xl;
    int* p_idx;
    cudaGetSymbolAddress((void**)&p_wth, g_wth);
    cudaGetSymbolAddress((void**)&p_wtl, g_wtl);
    cudaGetSymbolAddress((void**)&p_xh,  g_xh);
    cudaGetSymbolAddress((void**)&p_xl,  g_xl);
    cudaGetSymbolAddress((void**)&p_nf,  g_nf);
    cudaGetSymbolAddress((void**)&p_nfh, g_nfh);
    cudaGetSymbolAddress((void**)&p_nfl, g_nfl);
    cudaGetSymbolAddress((void**)&p_sq,  g_sq);
    cudaGetSymbolAddress((void**)&p_d2,  g_d2);
    cudaGetSymbolAddress((void**)&p_idx, g_idx);
    cudaGetSymbolAddress((void**)&p_P,   g_P);
    cudaGetSymbolAddress((void**)&p_Q,   g_Q);
    cudaGetSymbolAddress((void**)&p_att, g_att);
    cudaGetSymbolAddress((void**)&p_h,   g_h);
    cudaGetSymbolAddress((void**)&p_hm,  g_hm);
    cudaGetSymbolAddress((void**)&p_u,   g_u);
    cudaGetSymbolAddress((void**)&p_t,   g_t);
    cudaGetSymbolAddress((void**)&p_g,   g_g);
    cudaGetSymbolAddress((void**)&p_p,   g_p);

    cudaFuncSetAttribute(gram_x3_sym_kernel,
                         cudaFuncAttributeMaxDynamicSharedMemorySize, 73728);
    cudaFuncSetAttribute(stem_x3_kernel,
                         cudaFuncAttributeMaxDynamicSharedMemorySize, 110592);

    // ---- pre-split inputs ----
    transpose_w_kernel<<<(192 * 768 + 255) / 256, 256>>>(stem_w, p_wth, p_wtl);
    split_x_kernel<<<(int)((XELEM / 4 + 255) / 256), 256>>>(x, p_xh, p_xl);

    // ---- graph path (bit-identical numerics; pipelined) ----
    stem_x3_kernel<<<dim3(CH / 64, BN / 128), 256, 110592>>>(
        p_xh, p_xl, p_wth, p_wtl, p_nf, p_nfh, p_nfl, stem_b, pos);
    sq_kernel<<<(BN * 32 + 255) / 256, 256>>>(p_nf, p_sq);
    gram_x3_sym_kernel<<<dim3(45, 1, Bsz), 128, 73728>>>(p_nfh, p_nfl, p_sq, p_d2);
    topk_kernel<<<(BN * 32 + 255) / 256, 256>>>(p_d2, p_idx);

    // ---- edge attention (tf32; unchanged) ----
    tf32gemm_kernel<0,1><<<dim3(CH / 64, BN / 128), 256>>>(p_nfh, att_w1, p_P, BN, CH, CH,
                                                           nullptr, nullptr, nullptr, nullptr);
    tf32gemm_kernel<1,1><<<dim3(CH / 64, BN / 128), 256>>>(p_nfh, att_w1 + 192 * 192, p_Q,
                                                           BN, CH, CH,
                                                           att_b1, nullptr, nullptr, nullptr);
    edge_kernel<<<(BN * 32 + 255) / 256, 256>>>(p_P, p_Q, p_idx, att_w2, att_b2, p_att, out);

    // ---- prediction path (bf16 tensor cores; unchanged) ----
    agg_kernel<<<BN, CH>>>(p_nf, p_idx, p_att, p_hm);
    bf16gemm_kernel<2><<<dim3(CH / 64, BN / 128), 256>>>(p_hm, gnn_w1, p_h, BN, CH, CH,
                                                         gnn_b1, nullptr, nullptr, nullptr);
    agg_kernel<<<BN, CH>>>(p_h, p_idx, p_att, p_hm);
    bf16gemm_kernel<2><<<dim3(CH / 64, BN / 128), 256>>>(p_hm, gnn_w2, p_h, BN, CH, CH,
                                                         gnn_b2, nullptr, nullptr, nullptr);
    bf16gemm_kernel<3><<<dim3(HID / 64, BN / 128), 256>>>(p_h, ffn_w1, p_u, BN, HID, CH,
                                                          ffn_b1, ffn_g1, ffn_be1, nullptr);
    bf16gemm_kernel<4><<<dim3(CH / 64, BN / 128), 256>>>(p_u, ffn_w2, p_t, BN, CH, HID,
                                                         ffn_b2, ffn_g2, ffn_be2, p_h);

    pool_kernel<<<Bsz, CH>>>(p_t, p_g);
    sgemm_kernel<3><<<dim3(PHID / BNT, Bsz / BM), 256>>>(p_g, pred_w1, p_p, Bsz, PHID, CH,
                                                         pred_b1, pred_g, pred_be, nullptr);
    pred_final_kernel<<<Bsz, 256>>>(p_p, pred_w2, pred_b2, out + EDG);
}

// round 13
// speedup vs baseline: 1.1003x; 1.1003x over previous
#include <cuda_runtime.h>
#include <cuda_bf16.h>
#include <math.h>
#include <stdint.h>

// ---------------- problem constants ----------------
#define Bsz   64
#define IMGSZ 384
#define PATCH 16
#define CH    192
#define KNN   5
#define HGRID 24
#define NNODE 576
#define BN    (Bsz * NNODE)  // 36864
#define EDG   (BN * KNN)     // 184320
#define HID   768
#define PHID  1024

// ---------------- scratch ----------------
__device__ float    g_wt  [768 * 192];
__device__ float    g_nf  [(size_t)BN * CH];
__device__ uint32_t g_nfh [(size_t)BN * CH];
__device__ uint32_t g_nfl [(size_t)BN * CH];
__device__ float    g_sq  [BN];
__device__ float    g_d2  [(size_t)Bsz * NNODE * NNODE];
__device__ int      g_idx [BN * KNN];
__device__ float    g_P   [(size_t)BN * CH];
__device__ float    g_Q   [(size_t)BN * CH];
__device__ float    g_att [EDG];
__device__ float    g_h   [(size_t)BN * CH];
__device__ float    g_hm  [(size_t)BN * CH];
__device__ float    g_u   [(size_t)BN * HID];
__device__ float    g_t   [(size_t)BN * CH];
__device__ float    g_g   [Bsz * CH];
__device__ float    g_p   [Bsz * PHID];

__device__ __forceinline__ float gelu_exact(float v) {
    return 0.5f * v * (1.0f + erff(v * 0.70710678118654752f));
}
__device__ __forceinline__ uint32_t f2tf32(float x) {
    uint32_t r; asm("cvt.rna.tf32.f32 %0, %1;" : "=r"(r) : "f"(x)); return r;
}
__device__ __forceinline__ void split_tf32(float x, uint32_t& hi, uint32_t& lo) {
    hi = f2tf32(x);
    lo = f2tf32(x - __uint_as_float(hi));
}
__device__ __forceinline__ uint32_t smem_u32(const void* p) {
    return (uint32_t)__cvta_generic_to_shared(p);
}
__device__ __forceinline__ void ldsm4(uint32_t& r0, uint32_t& r1, uint32_t& r2,
                                      uint32_t& r3, uint32_t a) {
    asm volatile("ldmatrix.sync.aligned.m8n8.x4.shared.b16 {%0,%1,%2,%3}, [%4];"
                 : "=r"(r0), "=r"(r1), "=r"(r2), "=r"(r3) : "r"(a));
}
__device__ __forceinline__ uint32_t pkbf2(float a, float b) {
    __nv_bfloat162 t = __floats2bfloat162_rn(a, b);
    return *(uint32_t*)&t;
}
__device__ __forceinline__ void cp16(uint32_t dst, const void* src) {
    asm volatile("cp.async.cg.shared.global [%0], [%1], 16;" :: "r"(dst), "l"(src));
}
__device__ __forceinline__ void cp_commit() { asm volatile("cp.async.commit_group;"); }
__device__ __forceinline__ void cp_wait1()  { asm volatile("cp.async.wait_group 1;"); }
__device__ __forceinline__ void cp_wait0()  { asm volatile("cp.async.wait_group 0;"); }

#define MMA_TF32(acc, a0, a1, a2, a3, b0, b1)                                \
    asm volatile(                                                            \
        "mma.sync.aligned.m16n8k8.row.col.f32.tf32.tf32.f32 "               \
        "{%0,%1,%2,%3}, {%4,%5,%6,%7}, {%8,%9}, {%0,%1,%2,%3};"             \
        : "+f"(acc[0]), "+f"(acc[1]), "+f"(acc[2]), "+f"(acc[3])             \
        : "r"(a0), "r"(a1), "r"(a2), "r"(a3), "r"(b0), "r"(b1))
#define MMA_BF16(acc, a0, a1, a2, a3, b0, b1)                                \
    asm volatile(                                                            \
        "mma.sync.aligned.m16n8k16.row.col.f32.bf16.bf16.f32 "              \
        "{%0,%1,%2,%3}, {%4,%5,%6,%7}, {%8,%9}, {%0,%1,%2,%3};"             \
        : "+f"(acc[0]), "+f"(acc[1]), "+f"(acc[2]), "+f"(acc[3])             \
        : "r"(a0), "r"(a1), "r"(a2), "r"(a3), "r"(b0), "r"(b1))

#define LDSM_OFFS()                                                          \
    const int lrA = lane & 15;                                               \
    const int lcA = (lane >> 4) * 4;                                         \
    const int lrB = ((lane >> 4) << 3) + (lane & 7);                         \
    const int lcB = ((lane >> 3) & 1) * 4

// =================================================================
// gram via tf32x3 + symmetry + cp.async double buffering (only
// change vs R11). Fill = pure copies of pre-split nf; MMA order
// identical -> d2 bit-identical. Dynamic smem 73728 B.
// =================================================================
__global__ __launch_bounds__(128) void gram_x3_sym_kernel(
    const uint32_t* __restrict__ nfh, const uint32_t* __restrict__ nfl,
    const float* __restrict__ sq, float* __restrict__ d2)
{
    extern __shared__ uint32_t DSM[];
    const int b = blockIdx.z;
    const uint32_t* Abh = nfh + (size_t)b * NNODE * CH;
    const uint32_t* Abl = nfl + (size_t)b * NNODE * CH;

    int p = blockIdx.x, ti = 0;
    while (p >= 9 - ti) { p -= 9 - ti; ti++; }
    const int tj = ti + p;
    const int r0b = ti * 64, c0b = tj * 64;

    const int tid  = threadIdx.x;
    const int lane = tid & 31, wid = tid >> 5;
    const int wm = (wid >> 1) * 32, wn = (wid & 1) * 32;
    const int row = tid >> 1, kq = (tid & 1) * 16;
    const int g = lane >> 2, cq = lane & 3;
    LDSM_OFFS();
    const uint32_t base = smem_u32(DSM);
    // stage layout (bytes): Ah +0, Al +9216, Bh +18432, Bl +27648; stage stride 36864

    auto fill = [&](int k0, int st) {
        uint32_t sb = base + (uint32_t)st * 36864u;
        const size_t ra = (size_t)(r0b + row) * CH + k0 + kq;
        const size_t rb = (size_t)(c0b + row) * CH + k0 + kq;
#pragma unroll
        for (int i = 0; i < 4; i++) {
            uint32_t off = (uint32_t)(row * 36 + kq + i * 4) * 4;
            cp16(sb + off,          Abh + ra + i * 4);
            cp16(sb + 9216 + off,   Abl + ra + i * 4);
            cp16(sb + 18432 + off,  Abh + rb + i * 4);
            cp16(sb + 27648 + off,  Abl + rb + i * 4);
        }
        cp_commit();
    };

    float acc[2][4][4] = {};

    fill(0, 0);
    for (int s = 0; s < 6; s++) {
        if (s + 1 < 6) fill((s + 1) * 32, (s + 1) & 1);
        if (s + 1 < 6) cp_wait1(); else cp_wait0();
        __syncthreads();

        uint32_t sb = base + (uint32_t)(s & 1) * 36864u;
        const uint32_t bAh = sb, bAl = sb + 9216, bBh = sb + 18432, bBl = sb + 27648;
#pragma unroll
        for (int kk = 0; kk < 32; kk += 8) {
            uint32_t ah[2][4], al[2][4], bh[4][2], bl[4][2];
#pragma unroll
            for (int im = 0; im < 2; im++) {
                uint32_t off = ((wm + im * 16 + lrA) * 36 + kk + lcA) * 4;
                ldsm4(ah[im][0], ah[im][1], ah[im][2], ah[im][3], bAh + off);
                ldsm4(al[im][0], al[im][1], al[im][2], al[im][3], bAl + off);
            }
#pragma unroll
            for (int q = 0; q < 2; q++) {
                uint32_t off = ((wn + q * 16 + lrB) * 36 + kk + lcB) * 4;
                ldsm4(bh[2*q][0], bh[2*q][1], bh[2*q+1][0], bh[2*q+1][1], bBh + off);
                ldsm4(bl[2*q][0], bl[2*q][1], bl[2*q+1][0], bl[2*q+1][1], bBl + off);
            }
#pragma unroll
            for (int im = 0; im < 2; im++)
#pragma unroll
                for (int in = 0; in < 4; in++) {
                    MMA_TF32(acc[im][in], ah[im][0], ah[im][1], ah[im][2], ah[im][3],
                             bh[in][0], bh[in][1]);
                    MMA_TF32(acc[im][in], ah[im][0], ah[im][1], ah[im][2], ah[im][3],
                             bl[in][0], bl[in][1]);
                    MMA_TF32(acc[im][in], al[im][0], al[im][1], al[im][2], al[im][3],
                             bh[in][0], bh[in][1]);
                }
        }
        __syncthreads();
    }

#pragma unroll
    for (int im = 0; im < 2; im++)
#pragma unroll
        for (int in = 0; in < 4; in++) {
            int cbase = c0b + wn + in * 8 + 2 * cq;
#pragma unroll
            for (int half = 0; half < 2; half++) {
                int r = r0b + wm + im * 16 + g + half * 8;
#pragma unroll
                for (int jj = 0; jj < 2; jj++) {
                    int c = cbase + jj;
                    float v = sq[b * NNODE + c] - 2.0f * acc[im][in][half * 2 + jj];
                    if (r == c) v = 3.0e38f;
                    d2[((size_t)b * NNODE + r) * NNODE + c] = v;
                }
            }
        }

    if (ti != tj) {
        float* T = (float*)DSM;
#pragma unroll
        for (int im = 0; im < 2; im++)
#pragma unroll
            for (int in = 0; in < 4; in++) {
                int cl = wn + in * 8 + 2 * cq;
#pragma unroll
                for (int half = 0; half < 2; half++) {
                    int rl = wm + im * 16 + g + half * 8;
                    T[(cl    ) * 68 + rl] = acc[im][in][half * 2 + 0];
                    T[(cl + 1) * 68 + rl] = acc[im][in][half * 2 + 1];
                }
            }
        __syncthreads();
        for (int i = tid; i < 64 * 16; i += 128) {
            int cl = i >> 4;
            int r4 = (i & 15) * 4;
            float4 dv = *(const float4*)&T[cl * 68 + r4];
            float4 sv = *(const float4*)&sq[b * NNODE + r0b + r4];
            float4 o;
            o.x = sv.x - 2.0f * dv.x;
            o.y = sv.y - 2.0f * dv.y;
            o.z = sv.z - 2.0f * dv.z;
            o.w = sv.w - 2.0f * dv.w;
            *(float4*)&d2[((size_t)b * NNODE + c0b + cl) * NNODE + r0b + r4] = o;
        }
    }
}

// =================================================================
// tf32 GEMM + ldmatrix (P/Q path; R11). PRE=1: A pre-split hi.
// =================================================================
template <int EPI, int PRE>
__global__ __launch_bounds__(256) void tf32gemm_kernel(
    const void* __restrict__ Av, const float* __restrict__ B, float* __restrict__ C,
    int M, int N, int K,
    const float* __restrict__ bias, const float* __restrict__ gam,
    const float* __restrict__ bet,  const float* __restrict__ res)
{
    __shared__ uint32_t As[128][36];
    __shared__ uint32_t Bs[64][36];
    const int tid  = threadIdx.x;
    const int lane = tid & 31, wid = tid >> 5;
    const int wm = (wid >> 1) * 32;
    const int wn = (wid & 1) * 32;
    const int m0 = blockIdx.y * 128, n0 = blockIdx.x * 64;
    const int a_row = tid >> 1, a_k0 = (tid & 1) * 16;
    const int b_n = tid & 63, b_k0 = (tid >> 6) * 8;
    const int g = lane >> 2, cq = lane & 3;
    LDSM_OFFS();
    const uint32_t bA = smem_u32(&As[0][0]), bB = smem_u32(&Bs[0][0]);

    float acc[2][4][4] = {};

    for (int k0 = 0; k0 < K; k0 += 32) {
        if (PRE) {
            const uint32_t* Ai = (const uint32_t*)Av;
#pragma unroll
            for (int i = 0; i < 4; i++)
                *(uint4*)&As[a_row][a_k0 + i * 4] =
                    *(const uint4*)&Ai[(size_t)(m0 + a_row) * K + k0 + a_k0 + i * 4];
        } else {
            const float* A = (const float*)Av;
#pragma unroll
            for (int i = 0; i < 4; i++) {
                float4 v = *(const float4*)&A[(size_t)(m0 + a_row) * K + k0 + a_k0 + i * 4];
                As[a_row][a_k0 + i * 4 + 0] = f2tf32(v.x);
                As[a_row][a_k0 + i * 4 + 1] = f2tf32(v.y);
                As[a_row][a_k0 + i * 4 + 2] = f2tf32(v.z);
                As[a_row][a_k0 + i * 4 + 3] = f2tf32(v.w);
            }
        }
#pragma unroll
        for (int i = 0; i < 8; i++) {
            float v = B[(size_t)(k0 + b_k0 + i) * N + n0 + b_n];
            Bs[b_n][b_k0 + i] = f2tf32(v);
        }
        __syncthreads();

#pragma unroll
        for (int kk = 0; kk < 32; kk += 8) {
            uint32_t af[2][4], bf[4][2];
#pragma unroll
            for (int im = 0; im < 2; im++) {
                uint32_t off = ((wm + im * 16 + lrA) * 36 + kk + lcA) * 4;
                ldsm4(af[im][0], af[im][1], af[im][2], af[im][3], bA + off);
            }
#pragma unroll
            for (int q = 0; q < 2; q++) {
                uint32_t off = ((wn + q * 16 + lrB) * 36 + kk + lcB) * 4;
                ldsm4(bf[2*q][0], bf[2*q][1], bf[2*q+1][0], bf[2*q+1][1], bB + off);
            }
#pragma unroll
            for (int im = 0; im < 2; im++)
#pragma unroll
                for (int in = 0; in < 4; in++)
                    MMA_TF32(acc[im][in], af[im][0], af[im][1], af[im][2], af[im][3],
                             bf[in][0], bf[in][1]);
        }
        __syncthreads();
    }

#pragma unroll
    for (int im = 0; im < 2; im++)
#pragma unroll
        for (int in = 0; in < 4; in++) {
            int cbase = n0 + wn + in * 8 + 2 * cq;
#pragma unroll
            for (int half = 0; half < 2; half++) {
                int m = m0 + wm + im * 16 + g + half * 8;
#pragma unroll
                for (int jj = 0; jj < 2; jj++) {
                    int n = cbase + jj;
                    float v = acc[im][in][half * 2 + jj];
                    if (EPI == 1) v += bias[n];
                    if (EPI == 2) v = fmaxf(v + bias[n], 0.0f);
                    if (EPI == 3) v = gelu_exact((v + bias[n]) * gam[n] + bet[n]);
                    if (EPI == 4) v = res[(size_t)m * N + n] + (v + bias[n]) * gam[n] + bet[n];
                    C[(size_t)m * N + n] = v;
                }
            }
        }
}

// =================================================================
// bf16 GEMM (prediction path; R11 unchanged)
// =================================================================
template <int EPI>
__global__ __launch_bounds__(256) void bf16gemm_kernel(
    const float* __restrict__ A, const float* __restrict__ B, float* __restrict__ C,
    int M, int N, int K,
    const float* __restrict__ bias, const float* __restrict__ gam,
    const float* __restrict__ bet,  const float* __restrict__ res)
{
    __shared__ __nv_bfloat16 As[128][40];
    __shared__ __nv_bfloat16 Bs[64][40];
    const int tid  = threadIdx.x;
    const int lane = tid & 31, wid = tid >> 5;
    const int wm = (wid >> 1) * 32;
    const int wn = (wid & 1) * 32;
    const int m0 = blockIdx.y * 128, n0 = blockIdx.x * 64;
    const int a_row = tid >> 1, a_k0 = (tid & 1) * 16;
    const int b_n = tid & 63, b_k0 = (tid >> 6) * 8;
    const int g = lane >> 2, cq = lane & 3;
    const int lrA = lane & 15;
    const int lcA = (lane >> 4) * 8;
    const int lrB = ((lane >> 4) << 3) + (lane & 7);
    const int lcB = ((lane >> 3) & 1) * 8;
    const uint32_t bA = smem_u32(&As[0][0]), bB = smem_u32(&Bs[0][0]);

    float acc[2][4][4] = {};

    for (int k0 = 0; k0 < K; k0 += 32) {
        {
            const float* Ap = &A[(size_t)(m0 + a_row) * K + k0 + a_k0];
            float4 v0 = *(const float4*)(Ap + 0);
            float4 v1 = *(const float4*)(Ap + 4);
            float4 v2 = *(const float4*)(Ap + 8);
            float4 v3 = *(const float4*)(Ap + 12);
            uint4 u0, u1;
            u0.x = pkbf2(v0.x, v0.y); u0.y = pkbf2(v0.z, v0.w);
            u0.z = pkbf2(v1.x, v1.y); u0.w = pkbf2(v1.z, v1.w);
            u1.x = pkbf2(v2.x, v2.y); u1.y = pkbf2(v2.z, v2.w);
            u1.z = pkbf2(v3.x, v3.y); u1.w = pkbf2(v3.z, v3.w);
            *(uint4*)&As[a_row][a_k0 + 0] = u0;
            *(uint4*)&As[a_row][a_k0 + 8] = u1;
        }
        {
            float v[8];
#pragma unroll
            for (int i = 0; i < 8; i++)
                v[i] = B[(size_t)(k0 + b_k0 + i) * N + n0 + b_n];
            uint4 u;
            u.x = pkbf2(v[0], v[1]); u.y = pkbf2(v[2], v[3]);
            u.z = pkbf2(v[4], v[5]); u.w = pkbf2(v[6], v[7]);
            *(uint4*)&Bs[b_n][b_k0] = u;
        }
        __syncthreads();

#pragma unroll
        for (int kk = 0; kk < 32; kk += 16) {
            uint32_t af[2][4], bf[4][2];
#pragma unroll
            for (int im = 0; im < 2; im++) {
                uint32_t off = ((wm + im * 16 + lrA) * 40 + kk + lcA) * 2;
                ldsm4(af[im][0], af[im][1], af[im][2], af[im][3], bA + off);
            }
#pragma unroll
            for (int q = 0; q < 2; q++) {
                uint32_t off = ((wn + q * 16 + lrB) * 40 + kk + lcB) * 2;
                ldsm4(bf[2*q][0], bf[2*q][1], bf[2*q+1][0], bf[2*q+1][1], bB + off);
            }
#pragma unroll
            for (int im = 0; im < 2; im++)
#pragma unroll
                for (int in = 0; in < 4; in++)
                    MMA_BF16(acc[im][in], af[im][0], af[im][1], af[im][2], af[im][3],
                             bf[in][0], bf[in][1]);
        }
        __syncthreads();
    }

#pragma unroll
    for (int im = 0; im < 2; im++)
#pragma unroll
        for (int in = 0; in < 4; in++) {
            int cbase = n0 + wn + in * 8 + 2 * cq;
#pragma unroll
            for (int half = 0; half < 2; half++) {
                int m = m0 + wm + im * 16 + g + half * 8;
#pragma unroll
                for (int jj = 0; jj < 2; jj++) {
                    int n = cbase + jj;
                    float v = acc[im][in][half * 2 + jj];
                    if (EPI == 1) v += bias[n];
                    if (EPI == 2) v = fmaxf(v + bias[n], 0.0f);
                    if (EPI == 3) v = gelu_exact((v + bias[n]) * gam[n] + bet[n]);
                    if (EPI == 4) v = res[(size_t)m * N + n] + (v + bias[n]) * gam[n] + bet[n];
                    C[(size_t)m * N + n] = v;
                }
            }
        }
}

// =================================================================
// stem via tf32x3 + ldmatrix (R11 exact): epilogue writes nf + split
// =================================================================
__global__ __launch_bounds__(256) void stem_x3_kernel(
    const float* __restrict__ X, const float* __restrict__ Bw, float* __restrict__ C,
    uint32_t* __restrict__ Ch, uint32_t* __restrict__ Cl,
    const float* __restrict__ bias, const float* __restrict__ pos)
{
    const int Nd = 192, Kd = 768;
    __shared__ uint32_t Ah[128][20], Al[128][20];
    __shared__ uint32_t Bh[64][20],  Bl[64][20];
    const int tid  = threadIdx.x;
    const int lane = tid & 31, wid = tid >> 5;
    const int wm = (wid >> 1) * 32, wn = (wid & 1) * 32;
    const int m0 = blockIdx.y * 128, n0 = blockIdx.x * 64;
    const int a_row = tid >> 1, kq = (tid & 1) * 8;
    const int b_n = tid & 63, b_k0 = (tid >> 6) * 4;
    const int g = lane >> 2, cq = lane & 3;
    LDSM_OFFS();
    const uint32_t bAh = smem_u32(&Ah[0][0]), bAl = smem_u32(&Al[0][0]);
    const uint32_t bBh = smem_u32(&Bh[0][0]), bBl = smem_u32(&Bl[0][0]);

    const int m = m0 + a_row;
    const int bimg = m / NNODE;
    const int nsp = m % NNODE;
    const int py = nsp / HGRID, px = nsp % HGRID;
    const float* xbase = X + (size_t)bimg * 3 * IMGSZ * IMGSZ
                           + (size_t)(py * PATCH) * IMGSZ + px * PATCH;

    float acc[2][4][4] = {};

    for (int k0 = 0; k0 < Kd; k0 += 16) {
        {
            int kg = k0 + kq;
            int ci = kg >> 8, ky = (kg >> 4) & 15, kx = kg & 15;
            const float* xr = xbase + (size_t)ci * IMGSZ * IMGSZ + ky * IMGSZ + kx;
            float4 v0 = *(const float4*)xr;
            float4 v1 = *(const float4*)(xr + 4);
            uint32_t h, l;
            split_tf32(v0.x, h, l); Ah[a_row][kq + 0] = h; Al[a_row][kq + 0] = l;
            split_tf32(v0.y, h, l); Ah[a_row][kq + 1] = h; Al[a_row][kq + 1] = l;
            split_tf32(v0.z, h, l); Ah[a_row][kq + 2] = h; Al[a_row][kq + 2] = l;
            split_tf32(v0.w, h, l); Ah[a_row][kq + 3] = h; Al[a_row][kq + 3] = l;
            split_tf32(v1.x, h, l); Ah[a_row][kq + 4] = h; Al[a_row][kq + 4] = l;
            split_tf32(v1.y, h, l); Ah[a_row][kq + 5] = h; Al[a_row][kq + 5] = l;
            split_tf32(v1.z, h, l); Ah[a_row][kq + 6] = h; Al[a_row][kq + 6] = l;
            split_tf32(v1.w, h, l); Ah[a_row][kq + 7] = h; Al[a_row][kq + 7] = l;
        }
#pragma unroll
        for (int i = 0; i < 4; i++) {
            float v = Bw[(size_t)(k0 + b_k0 + i) * Nd + n0 + b_n];
            uint32_t h, l;
            split_tf32(v, h, l);
            Bh[b_n][b_k0 + i] = h; Bl[b_n][b_k0 + i] = l;
        }
        __syncthreads();

#pragma unroll
        for (int kk = 0; kk < 16; kk += 8) {
            uint32_t ah[2][4], al[2][4], bh[4][2], bl[4][2];
#pragma unroll
            for (int im = 0; im < 2; im++) {
                uint32_t off = ((wm + im * 16 + lrA) * 20 + kk + lcA) * 4;
                ldsm4(ah[im][0], ah[im][1], ah[im][2], ah[im][3], bAh + off);
                ldsm4(al[im][0], al[im][1], al[im][2], al[im][3], bAl + off);
            }
#pragma unroll
            for (int q = 0; q < 2; q++) {
                uint32_t off = ((wn + q * 16 + lrB) * 20 + kk + lcB) * 4;
                ldsm4(bh[2*q][0], bh[2*q][1], bh[2*q+1][0], bh[2*q+1][1], bBh + off);
                ldsm4(bl[2*q][0], bl[2*q][1], bl[2*q+1][0], bl[2*q+1][1], bBl + off);
            }
#pragma unroll
            for (int im = 0; im < 2; im++)
#pragma unroll
                for (int in = 0; in < 4; in++) {
                    MMA_TF32(acc[im][in], ah[im][0], ah[im][1], ah[im][2], ah[im][3],
                             bh[in][0], bh[in][1]);
                    MMA_TF32(acc[im][in], ah[im][0], ah[im][1], ah[im][2], ah[im][3],
                             bl[in][0], bl[in][1]);
                    MMA_TF32(acc[im][in], al[im][0], al[im][1], al[im][2], al[im][3],
                             bh[in][0], bh[in][1]);
                }
        }
        __syncthreads();
    }

#pragma unroll
    for (int im = 0; im < 2; im++)
#pragma unroll
        for (int in = 0; in < 4; in++) {
            int cbase = n0 + wn + in * 8 + 2 * cq;
#pragma unroll
            for (int half = 0; half < 2; half++) {
                int mm = m0 + wm + im * 16 + g + half * 8;
                int sp = mm % NNODE;
#pragma unroll
                for (int jj = 0; jj < 2; jj++) {
                    int n = cbase + jj;
                    float v = acc[im][in][half * 2 + jj] + bias[n] + pos[n * NNODE + sp];
                    C[(size_t)mm * CH + n] = v;
                    uint32_t h, l;
                    split_tf32(v, h, l);
                    Ch[(size_t)mm * CH + n] = h;
                    Cl[(size_t)mm * CH + n] = l;
                }
            }
        }
}

// ---------------- small-M SGEMM for pred head (M=64) ----------------
#define BM 64
#define BNT 64
#define BKT 16
template <int EPI>
__global__ __launch_bounds__(256) void sgemm_kernel(
    const float* __restrict__ A, const float* __restrict__ B, float* __restrict__ C,
    int M, int N, int K,
    const float* __restrict__ bias, const float* __restrict__ gam,
    const float* __restrict__ bet,  const float* __restrict__ res)
{
    __shared__ float As[BKT][BM];
    __shared__ float Bs[BKT][BNT];
    const int tid = threadIdx.x;
    const int tx = tid & 15, ty = tid >> 4;
    const int m0 = blockIdx.y * BM, n0 = blockIdx.x * BNT;
    const int a_m = tid >> 2, a_k = (tid & 3) * 4;
    const int b_k = tid >> 4, b_n = (tid & 15) * 4;

    float acc[4][4] = {};
    for (int k0 = 0; k0 < K; k0 += BKT) {
        float4 av = *(const float4*)&A[(size_t)(m0 + a_m) * K + k0 + a_k];
        As[a_k + 0][a_m] = av.x; As[a_k + 1][a_m] = av.y;
        As[a_k + 2][a_m] = av.z; As[a_k + 3][a_m] = av.w;
        float4 bv = *(const float4*)&B[(size_t)(k0 + b_k) * N + n0 + b_n];
        *(float4*)&Bs[b_k][b_n] = bv;
        __syncthreads();
#pragma unroll
        for (int k = 0; k < BKT; k++) {
            float ar[4], br[4];
#pragma unroll
            for (int i = 0; i < 4; i++) ar[i] = As[k][ty * 4 + i];
#pragma unroll
            for (int j = 0; j < 4; j++) br[j] = Bs[k][tx * 4 + j];
#pragma unroll
            for (int i = 0; i < 4; i++)
#pragma unroll
                for (int j = 0; j < 4; j++) acc[i][j] = fmaf(ar[i], br[j], acc[i][j]);
        }
        __syncthreads();
    }
#pragma unroll
    for (int i = 0; i < 4; i++) {
        int m = m0 + ty * 4 + i;
#pragma unroll
        for (int j = 0; j < 4; j++) {
            int n = n0 + tx * 4 + j;
            float v = acc[i][j];
            if (EPI == 1) v += bias[n];
            if (EPI == 2) v = fmaxf(v + bias[n], 0.0f);
            if (EPI == 3) v = gelu_exact((v + bias[n]) * gam[n] + bet[n]);
            if (EPI == 4) v = res[(size_t)m * N + n] + (v + bias[n]) * gam[n] + bet[n];
            C[(size_t)m * N + n] = v;
        }
    }
}

// ---------------- auxiliary kernels ----------------
__global__ void transpose_w_kernel(const float* __restrict__ w, float* __restrict__ wt) {
    int i = blockIdx.x * blockDim.x + threadIdx.x;
    if (i >= 192 * 768) return;
    int n = i / 768, k = i % 768;
    wt[k * 192 + n] = w[i];
}

__global__ void sq_kernel(const float* __restrict__ nf, float* __restrict__ sq) {
    int node = (blockIdx.x * blockDim.x + threadIdx.x) >> 5;
    int lane = threadIdx.x & 31;
    if (node >= BN) return;
    float s = 0.f;
#pragma unroll
    for (int j = 0; j < 6; j++) {
        float x = nf[(size_t)node * CH + lane + 32 * j];
        s = fmaf(x, x, s);
    }
#pragma unroll
    for (int off = 16; off; off >>= 1) s += __shfl_down_sync(0xffffffffu, s, off);
    if (lane == 0) sq[node] = s;
}

__global__ void topk_kernel(const float* __restrict__ d2, int* __restrict__ idx) {
    int row = (blockIdx.x * blockDim.x + threadIdx.x) >> 5;
    int lane = threadIdx.x & 31;
    if (row >= BN) return;
    const float* r = d2 + (size_t)row * NNODE;
    float v[18];
#pragma unroll
    for (int j = 0; j < 18; j++) v[j] = r[lane + 32 * j];
    int bimg = row / NNODE;
#pragma unroll
    for (int s = 0; s < 5; s++) {
        float bv = 3.4e38f; int bc = 1 << 30;
#pragma unroll
        for (int j = 0; j < 18; j++) {
            int c = lane + 32 * j;
            if (v[j] < bv) { bv = v[j]; bc = c; }
        }
#pragma unroll
        for (int off = 16; off; off >>= 1) {
            float ov = __shfl_down_sync(0xffffffffu, bv, off);
            int   oc = __shfl_down_sync(0xffffffffu, bc, off);
            if (ov < bv || (ov == bv && oc < bc)) { bv = ov; bc = oc; }
        }
        bc = __shfl_sync(0xffffffffu, bc, 0);
        if ((bc & 31) == lane) v[bc >> 5] = 3.4e38f;
        if (lane == 0) idx[row * KNN + s] = bimg * NNODE + bc;
    }
}

__global__ void edge_kernel(const float* __restrict__ P, const float* __restrict__ Q,
                            const int* __restrict__ idx,
                            const float* __restrict__ w2, const float* __restrict__ b2,
                            float* __restrict__ att, float* __restrict__ out)
{
    int node = (blockIdx.x * blockDim.x + threadIdx.x) >> 5;
    int lane = threadIdx.x & 31;
    if (node >= BN) return;
    float q[6], w[6];
#pragma unroll
    for (int j = 0; j < 6; j++) {
        q[j] = Q[(size_t)node * CH + lane + 32 * j];
        w[j] = w2[lane + 32 * j];
    }
    const float b2v = b2[0];
#pragma unroll
    for (int k = 0; k < KNN; k++) {
        int e = node * KNN + k;
        int src = idx[e];
        float s = 0.f;
#pragma unroll
        for (int j = 0; j < 6; j++) {
            float x = P[(size_t)src * CH + lane + 32 * j] + q[j];
            x = fmaxf(x, 0.f);
            s = fmaf(x, w[j], s);
        }
#pragma unroll
        for (int off = 16; off; off >>= 1) s += __shfl_down_sync(0xffffffffu, s, off);
        if (lane == 0) {
            float a = 1.0f / (1.0f + expf(-(s + b2v)));
            att[e] = a;
            out[e] = a;
        }
    }
}

__global__ void agg_kernel(const float* __restrict__ h, const int* __restrict__ idx,
                           const float* __restrict__ att, float* __restrict__ hm)
{
    int i = blockIdx.x;
    int c = threadIdx.x;
    float acc = h[(size_t)i * CH + c];
#pragma unroll
    for (int k = 0; k < KNN; k++) {
        int nb = idx[i * KNN + k];
        float a = att[i * KNN + k];
        acc = fmaf(a, h[(size_t)nb * CH + c], acc);
    }
    hm[(size_t)i * CH + c] = acc;
}

__global__ void pool_kernel(const float* __restrict__ t, float* __restrict__ g) {
    int b = blockIdx.x, c = threadIdx.x;
    float acc = 0.f;
    for (int n = 0; n < NNODE; n++) acc += t[((size_t)b * NNODE + n) * CH + c];
    g[b * CH + c] = acc * (1.0f / NNODE);
}

__global__ void pred_final_kernel(const float* __restrict__ p, const float* __restrict__ w2,
                                  const float* __restrict__ b2, float* __restrict__ out)
{
    int b = blockIdx.x, tid = threadIdx.x;
    float s = 0.f;
    for (int i = tid; i < PHID; i += 256) s = fmaf(p[(size_t)b * PHID + i], w2[i], s);
    __shared__ float red[256];
    red[tid] = s; __syncthreads();
    for (int st = 128; st; st >>= 1) { if (tid < st) red[tid] += red[tid + st]; __syncthreads(); }
    if (tid == 0) out[b] = red[0] + b2[0];
}

// ---------------- host launch ----------------
extern "C" void kernel_launch(void* const* d_in, const int* in_sizes, int n_in,
                              void* d_out, int out_size)
{
    const float* x        = (const float*)d_in[0];
    const float* stem_w   = (const float*)d_in[1];
    const float* stem_b   = (const float*)d_in[2];
    const float* pos      = (const float*)d_in[3];
    const float* att_w1   = (const float*)d_in[4];
    const float* att_b1   = (const float*)d_in[5];
    const float* att_w2   = (const float*)d_in[6];
    const float* att_b2   = (const float*)d_in[7];
    const float* gnn_w1   = (const float*)d_in[8];
    const float* gnn_b1   = (const float*)d_in[9];
    const float* gnn_w2   = (const float*)d_in[10];
    const float* gnn_b2   = (const float*)d_in[11];
    const float* ffn_w1   = (const float*)d_in[12];
    const float* ffn_b1   = (const float*)d_in[13];
    const float* ffn_g1   = (const float*)d_in[14];
    const float* ffn_be1  = (const float*)d_in[15];
    const float* ffn_w2   = (const float*)d_in[16];
    const float* ffn_b2   = (const float*)d_in[17];
    const float* ffn_g2   = (const float*)d_in[18];
    const float* ffn_be2  = (const float*)d_in[19];
    const float* pred_w1  = (const float*)d_in[20];
    const float* pred_b1  = (const float*)d_in[21];
    const float* pred_g   = (const float*)d_in[22];
    const float* pred_be  = (const float*)d_in[23];
    const float* pred_w2  = (const float*)d_in[24];
    const float* pred_b2  = (const float*)d_in[25];
    float* out = (float*)d_out;

    float *p_wt, *p_nf, *p_sq, *p_d2, *p_P, *p_Q, *p_att, *p_h, *p_hm, *p_u, *p_t, *p_g, *p_p;
    uint32_t *p_nfh, *p_nfl;
    int* p_idx;
    cudaGetSymbolAddress((void**)&p_wt,  g_wt);
    cudaGetSymbolAddress((void**)&p_nf,  g_nf);
    cudaGetSymbolAddress((void**)&p_nfh, g_nfh);
    cudaGetSymbolAddress((void**)&p_nfl, g_nfl);
    cudaGetSymbolAddress((void**)&p_sq,  g_sq);
    cudaGetSymbolAddress((void**)&p_d2,  g_d2);
    cudaGetSymbolAddress((void**)&p_idx, g_idx);
    cudaGetSymbolAddress((void**)&p_P,   g_P);
    cudaGetSymbolAddress((void**)&p_Q,   g_Q);
    cudaGetSymbolAddress((void**)&p_att, g_att);
    cudaGetSymbolAddress((void**)&p_h,   g_h);
    cudaGetSymbolAddress((void**)&p_hm,  g_hm);
    cudaGetSymbolAddress((void**)&p_u,   g_u);
    cudaGetSymbolAddress((void**)&p_t,   g_t);
    cudaGetSymbolAddress((void**)&p_g,   g_g);
    cudaGetSymbolAddress((void**)&p_p,   g_p);

    cudaFuncSetAttribute(gram_x3_sym_kernel,
                         cudaFuncAttributeMaxDynamicSharedMemorySize, 73728);

    transpose_w_kernel<<<(192 * 768 + 255) / 256, 256>>>(stem_w, p_wt);

    // ---- graph path (R11 stem; pipelined gram, bit-identical d2) ----
    stem_x3_kernel<<<dim3(CH / 64, BN / 128), 256>>>(x, p_wt, p_nf, p_nfh, p_nfl, stem_b, pos);
    sq_kernel<<<(BN * 32 + 255) / 256, 256>>>(p_nf, p_sq);
    gram_x3_sym_kernel<<<dim3(45, 1, Bsz), 128, 73728>>>(p_nfh, p_nfl, p_sq, p_d2);
    topk_kernel<<<(BN * 32 + 255) / 256, 256>>>(p_d2, p_idx);

    // ---- edge attention (tf32; R11) ----
    tf32gemm_kernel<0,1><<<dim3(CH / 64, BN / 128), 256>>>(p_nfh, att_w1, p_P, BN, CH, CH,
                                                           nullptr, nullptr, nullptr, nullptr);
    tf32gemm_kernel<1,1><<<dim3(CH / 64, BN / 128), 256>>>(p_nfh, att_w1 + 192 * 192, p_Q,
                                                           BN, CH, CH,
                                                           att_b1, nullptr, nullptr, nullptr);
    edge_kernel<<<(BN * 32 + 255) / 256, 256>>>(p_P, p_Q, p_idx, att_w2, att_b2, p_att, out);

    // ---- prediction path (bf16; R11) ----
    agg_kernel<<<BN, CH>>>(p_nf, p_idx, p_att, p_hm);
    bf16gemm_kernel<2><<<dim3(CH / 64, BN / 128), 256>>>(p_hm, gnn_w1, p_h, BN, CH, CH,
                                                         gnn_b1, nullptr, nullptr, nullptr);
    agg_kernel<<<BN, CH>>>(p_h, p_idx, p_att, p_hm);
    bf16gemm_kernel<2><<<dim3(CH / 64, BN / 128), 256>>>(p_hm, gnn_w2, p_h, BN, CH, CH,
                                                         gnn_b2, nullptr, nullptr, nullptr);
    bf16gemm_kernel<3><<<dim3(HID / 64, BN / 128), 256>>>(p_h, ffn_w1, p_u, BN, HID, CH,
                                                          ffn_b1, ffn_g1, ffn_be1, nullptr);
    bf16gemm_kernel<4><<<dim3(CH / 64, BN / 128), 256>>>(p_u, ffn_w2, p_t, BN, CH, HID,
                                                         ffn_b2, ffn_g2, ffn_be2, p_h);

    pool_kernel<<<Bsz, CH>>>(p_t, p_g);
    sgemm_kernel<3><<<dim3(PHID / BNT, Bsz / BM), 256>>>(p_g, pred_w1, p_p, Bsz, PHID, CH,
                                                         pred_b1, pred_g, pred_be, nullptr);
    pred_final_kernel<<<Bsz, 256>>>(p_p, pred_w2, pred_b2, out + EDG);
}

// round 14
// speedup vs baseline: 1.1292x; 1.0263x over previous
#include <cuda_runtime.h>
#include <cuda_bf16.h>
#include <math.h>
#include <stdint.h>

// ---------------- problem constants ----------------
#define Bsz   64
#define IMGSZ 384
#define PATCH 16
#define CH    192
#define KNN   5
#define HGRID 24
#define NNODE 576
#define BN    (Bsz * NNODE)  // 36864
#define EDG   (BN * KNN)     // 184320
#define HID   768
#define PHID  1024

// ---------------- scratch ----------------
__device__ float    g_wt  [768 * 192];
__device__ float    g_nf  [(size_t)BN * CH];
__device__ uint32_t g_nfh [(size_t)BN * CH];
__device__ uint32_t g_nfl [(size_t)BN * CH];
__device__ float    g_sq  [BN];
__device__ float    g_d2  [(size_t)Bsz * NNODE * NNODE];
__device__ int      g_idx [BN * KNN];
__device__ float    g_P   [(size_t)BN * CH];
__device__ float    g_Q   [(size_t)BN * CH];
__device__ float    g_att [EDG];
__device__ float    g_h   [(size_t)BN * CH];
__device__ float    g_hm  [(size_t)BN * CH];
__device__ float    g_u   [(size_t)BN * HID];
__device__ float    g_t   [(size_t)BN * CH];
__device__ float    g_g   [Bsz * CH];
__device__ float    g_p   [Bsz * PHID];

__device__ __forceinline__ float gelu_exact(float v) {
    return 0.5f * v * (1.0f + erff(v * 0.70710678118654752f));
}
__device__ __forceinline__ uint32_t f2tf32(float x) {
    uint32_t r; asm("cvt.rna.tf32.f32 %0, %1;" : "=r"(r) : "f"(x)); return r;
}
__device__ __forceinline__ void split_tf32(float x, uint32_t& hi, uint32_t& lo) {
    hi = f2tf32(x);
    lo = f2tf32(x - __uint_as_float(hi));
}
__device__ __forceinline__ uint32_t smem_u32(const void* p) {
    return (uint32_t)__cvta_generic_to_shared(p);
}
__device__ __forceinline__ void ldsm4(uint32_t& r0, uint32_t& r1, uint32_t& r2,
                                      uint32_t& r3, uint32_t a) {
    asm volatile("ldmatrix.sync.aligned.m8n8.x4.shared.b16 {%0,%1,%2,%3}, [%4];"
                 : "=r"(r0), "=r"(r1), "=r"(r2), "=r"(r3) : "r"(a));
}
__device__ __forceinline__ uint32_t pkbf2(float a, float b) {
    __nv_bfloat162 t = __floats2bfloat162_rn(a, b);
    return *(uint32_t*)&t;
}
__device__ __forceinline__ void cp16(uint32_t dst, const void* src) {
    asm volatile("cp.async.cg.shared.global [%0], [%1], 16;" :: "r"(dst), "l"(src));
}
__device__ __forceinline__ void cp_commit() { asm volatile("cp.async.commit_group;"); }
__device__ __forceinline__ void cp_wait1()  { asm volatile("cp.async.wait_group 1;"); }
__device__ __forceinline__ void cp_wait0()  { asm volatile("cp.async.wait_group 0;"); }

#define MMA_TF32(acc, a0, a1, a2, a3, b0, b1)                                \
    asm volatile(                                                            \
        "mma.sync.aligned.m16n8k8.row.col.f32.tf32.tf32.f32 "               \
        "{%0,%1,%2,%3}, {%4,%5,%6,%7}, {%8,%9}, {%0,%1,%2,%3};"             \
        : "+f"(acc[0]), "+f"(acc[1]), "+f"(acc[2]), "+f"(acc[3])             \
        : "r"(a0), "r"(a1), "r"(a2), "r"(a3), "r"(b0), "r"(b1))
#define MMA_BF16(acc, a0, a1, a2, a3, b0, b1)                                \
    asm volatile(                                                            \
        "mma.sync.aligned.m16n8k16.row.col.f32.bf16.bf16.f32 "              \
        "{%0,%1,%2,%3}, {%4,%5,%6,%7}, {%8,%9}, {%0,%1,%2,%3};"             \
        : "+f"(acc[0]), "+f"(acc[1]), "+f"(acc[2]), "+f"(acc[3])             \
        : "r"(a0), "r"(a1), "r"(a2), "r"(a3), "r"(b0), "r"(b1))

#define LDSM_OFFS()                                                          \
    const int lrA = lane & 15;                                               \
    const int lcA = (lane >> 4) * 4;                                         \
    const int lrB = ((lane >> 4) << 3) + (lane & 7);                         \
    const int lcB = ((lane >> 3) & 1) * 4

// =================================================================
// gram via tf32x3 + symmetry + cp.async double buffering with
// K-slab 16 (stage 20480 B, 2 stages = 40960 B -> ~5 CTAs/SM).
// Global 8-wide k-chunk MMA order identical -> d2 bit-identical.
// =================================================================
__global__ __launch_bounds__(128) void gram_x3_sym_kernel(
    const uint32_t* __restrict__ nfh, const uint32_t* __restrict__ nfl,
    const float* __restrict__ sq, float* __restrict__ d2)
{
    extern __shared__ uint32_t DSM[];
    const int b = blockIdx.z;
    const uint32_t* Abh = nfh + (size_t)b * NNODE * CH;
    const uint32_t* Abl = nfl + (size_t)b * NNODE * CH;

    int p = blockIdx.x, ti = 0;
    while (p >= 9 - ti) { p -= 9 - ti; ti++; }
    const int tj = ti + p;
    const int r0b = ti * 64, c0b = tj * 64;

    const int tid  = threadIdx.x;
    const int lane = tid & 31, wid = tid >> 5;
    const int wm = (wid >> 1) * 32, wn = (wid & 1) * 32;
    const int row = tid >> 1, kq = (tid & 1) * 8;   // 8-wide k halves
    const int g = lane >> 2, cq = lane & 3;
    LDSM_OFFS();
    const uint32_t base = smem_u32(DSM);
    // stage layout (bytes): Ah +0 (64x20w=5120B), Al +5120, Bh +10240, Bl +15360;
    // stage stride 20480

    auto fill = [&](int k0, int st) {
        uint32_t sb = base + (uint32_t)st * 20480u;
        const size_t ra = (size_t)(r0b + row) * CH + k0 + kq;
        const size_t rb = (size_t)(c0b + row) * CH + k0 + kq;
#pragma unroll
        for (int i = 0; i < 2; i++) {
            uint32_t off = (uint32_t)(row * 20 + kq + i * 4) * 4;
            cp16(sb + off,          Abh + ra + i * 4);
            cp16(sb + 5120 + off,   Abl + ra + i * 4);
            cp16(sb + 10240 + off,  Abh + rb + i * 4);
            cp16(sb + 15360 + off,  Abl + rb + i * 4);
        }
        cp_commit();
    };

    float acc[2][4][4] = {};

    const int NS = CH / 16;   // 12 slabs
    fill(0, 0);
    for (int s = 0; s < NS; s++) {
        if (s + 1 < NS) fill((s + 1) * 16, (s + 1) & 1);
        if (s + 1 < NS) cp_wait1(); else cp_wait0();
        __syncthreads();

        uint32_t sb = base + (uint32_t)(s & 1) * 20480u;
        const uint32_t bAh = sb, bAl = sb + 5120, bBh = sb + 10240, bBl = sb + 15360;
#pragma unroll
        for (int kk = 0; kk < 16; kk += 8) {
            uint32_t ah[2][4], al[2][4], bh[4][2], bl[4][2];
#pragma unroll
            for (int im = 0; im < 2; im++) {
                uint32_t off = ((wm + im * 16 + lrA) * 20 + kk + lcA) * 4;
                ldsm4(ah[im][0], ah[im][1], ah[im][2], ah[im][3], bAh + off);
                ldsm4(al[im][0], al[im][1], al[im][2], al[im][3], bAl + off);
            }
#pragma unroll
            for (int q = 0; q < 2; q++) {
                uint32_t off = ((wn + q * 16 + lrB) * 20 + kk + lcB) * 4;
                ldsm4(bh[2*q][0], bh[2*q][1], bh[2*q+1][0], bh[2*q+1][1], bBh + off);
                ldsm4(bl[2*q][0], bl[2*q][1], bl[2*q+1][0], bl[2*q+1][1], bBl + off);
            }
#pragma unroll
            for (int im = 0; im < 2; im++)
#pragma unroll
                for (int in = 0; in < 4; in++) {
                    MMA_TF32(acc[im][in], ah[im][0], ah[im][1], ah[im][2], ah[im][3],
                             bh[in][0], bh[in][1]);
                    MMA_TF32(acc[im][in], ah[im][0], ah[im][1], ah[im][2], ah[im][3],
                             bl[in][0], bl[in][1]);
                    MMA_TF32(acc[im][in], al[im][0], al[im][1], al[im][2], al[im][3],
                             bh[in][0], bh[in][1]);
                }
        }
        __syncthreads();
    }

#pragma unroll
    for (int im = 0; im < 2; im++)
#pragma unroll
        for (int in = 0; in < 4; in++) {
            int cbase = c0b + wn + in * 8 + 2 * cq;
#pragma unroll
            for (int half = 0; half < 2; half++) {
                int r = r0b + wm + im * 16 + g + half * 8;
#pragma unroll
                for (int jj = 0; jj < 2; jj++) {
                    int c = cbase + jj;
                    float v = sq[b * NNODE + c] - 2.0f * acc[im][in][half * 2 + jj];
                    if (r == c) v = 3.0e38f;
                    d2[((size_t)b * NNODE + r) * NNODE + c] = v;
                }
            }
        }

    if (ti != tj) {
        float* T = (float*)DSM;
#pragma unroll
        for (int im = 0; im < 2; im++)
#pragma unroll
            for (int in = 0; in < 4; in++) {
                int cl = wn + in * 8 + 2 * cq;
#pragma unroll
                for (int half = 0; half < 2; half++) {
                    int rl = wm + im * 16 + g + half * 8;
                    T[(cl    ) * 68 + rl] = acc[im][in][half * 2 + 0];
                    T[(cl + 1) * 68 + rl] = acc[im][in][half * 2 + 1];
                }
            }
        __syncthreads();
        for (int i = tid; i < 64 * 16; i += 128) {
            int cl = i >> 4;
            int r4 = (i & 15) * 4;
            float4 dv = *(const float4*)&T[cl * 68 + r4];
            float4 sv = *(const float4*)&sq[b * NNODE + r0b + r4];
            float4 o;
            o.x = sv.x - 2.0f * dv.x;
            o.y = sv.y - 2.0f * dv.y;
            o.z = sv.z - 2.0f * dv.z;
            o.w = sv.w - 2.0f * dv.w;
            *(float4*)&d2[((size_t)b * NNODE + c0b + cl) * NNODE + r0b + r4] = o;
        }
    }
}

// =================================================================
// tf32 GEMM + ldmatrix (P/Q path; R11). PRE=1: A pre-split hi.
// =================================================================
template <int EPI, int PRE>
__global__ __launch_bounds__(256) void tf32gemm_kernel(
    const void* __restrict__ Av, const float* __restrict__ B, float* __restrict__ C,
    int M, int N, int K,
    const float* __restrict__ bias, const float* __restrict__ gam,
    const float* __restrict__ bet,  const float* __restrict__ res)
{
    __shared__ uint32_t As[128][36];
    __shared__ uint32_t Bs[64][36];
    const int tid  = threadIdx.x;
    const int lane = tid & 31, wid = tid >> 5;
    const int wm = (wid >> 1) * 32;
    const int wn = (wid & 1) * 32;
    const int m0 = blockIdx.y * 128, n0 = blockIdx.x * 64;
    const int a_row = tid >> 1, a_k0 = (tid & 1) * 16;
    const int b_n = tid & 63, b_k0 = (tid >> 6) * 8;
    const int g = lane >> 2, cq = lane & 3;
    LDSM_OFFS();
    const uint32_t bA = smem_u32(&As[0][0]), bB = smem_u32(&Bs[0][0]);

    float acc[2][4][4] = {};

    for (int k0 = 0; k0 < K; k0 += 32) {
        if (PRE) {
            const uint32_t* Ai = (const uint32_t*)Av;
#pragma unroll
            for (int i = 0; i < 4; i++)
                *(uint4*)&As[a_row][a_k0 + i * 4] =
                    *(const uint4*)&Ai[(size_t)(m0 + a_row) * K + k0 + a_k0 + i * 4];
        } else {
            const float* A = (const float*)Av;
#pragma unroll
            for (int i = 0; i < 4; i++) {
                float4 v = *(const float4*)&A[(size_t)(m0 + a_row) * K + k0 + a_k0 + i * 4];
                As[a_row][a_k0 + i * 4 + 0] = f2tf32(v.x);
                As[a_row][a_k0 + i * 4 + 1] = f2tf32(v.y);
                As[a_row][a_k0 + i * 4 + 2] = f2tf32(v.z);
                As[a_row][a_k0 + i * 4 + 3] = f2tf32(v.w);
            }
        }
#pragma unroll
        for (int i = 0; i < 8; i++) {
            float v = B[(size_t)(k0 + b_k0 + i) * N + n0 + b_n];
            Bs[b_n][b_k0 + i] = f2tf32(v);
        }
        __syncthreads();

#pragma unroll
        for (int kk = 0; kk < 32; kk += 8) {
            uint32_t af[2][4], bf[4][2];
#pragma unroll
            for (int im = 0; im < 2; im++) {
                uint32_t off = ((wm + im * 16 + lrA) * 36 + kk + lcA) * 4;
                ldsm4(af[im][0], af[im][1], af[im][2], af[im][3], bA + off);
            }
#pragma unroll
            for (int q = 0; q < 2; q++) {
                uint32_t off = ((wn + q * 16 + lrB) * 36 + kk + lcB) * 4;
                ldsm4(bf[2*q][0], bf[2*q][1], bf[2*q+1][0], bf[2*q+1][1], bB + off);
            }
#pragma unroll
            for (int im = 0; im < 2; im++)
#pragma unroll
                for (int in = 0; in < 4; in++)
                    MMA_TF32(acc[im][in], af[im][0], af[im][1], af[im][2], af[im][3],
                             bf[in][0], bf[in][1]);
        }
        __syncthreads();
    }

#pragma unroll
    for (int im = 0; im < 2; im++)
#pragma unroll
        for (int in = 0; in < 4; in++) {
            int cbase = n0 + wn + in * 8 + 2 * cq;
#pragma unroll
            for (int half = 0; half < 2; half++) {
                int m = m0 + wm + im * 16 + g + half * 8;
#pragma unroll
                for (int jj = 0; jj < 2; jj++) {
                    int n = cbase + jj;
                    float v = acc[im][in][half * 2 + jj];
                    if (EPI == 1) v += bias[n];
                    if (EPI == 2) v = fmaxf(v + bias[n], 0.0f);
                    if (EPI == 3) v = gelu_exact((v + bias[n]) * gam[n] + bet[n]);
                    if (EPI == 4) v = res[(size_t)m * N + n] + (v + bias[n]) * gam[n] + bet[n];
                    C[(size_t)m * N + n] = v;
                }
            }
        }
}

// =================================================================
// bf16 GEMM (prediction path; R11 unchanged)
// =================================================================
template <int EPI>
__global__ __launch_bounds__(256) void bf16gemm_kernel(
    const float* __restrict__ A, const float* __restrict__ B, float* __restrict__ C,
    int M, int N, int K,
    const float* __restrict__ bias, const float* __restrict__ gam,
    const float* __restrict__ bet,  const float* __restrict__ res)
{
    __shared__ __nv_bfloat16 As[128][40];
    __shared__ __nv_bfloat16 Bs[64][40];
    const int tid  = threadIdx.x;
    const int lane = tid & 31, wid = tid >> 5;
    const int wm = (wid >> 1) * 32;
    const int wn = (wid & 1) * 32;
    const int m0 = blockIdx.y * 128, n0 = blockIdx.x * 64;
    const int a_row = tid >> 1, a_k0 = (tid & 1) * 16;
    const int b_n = tid & 63, b_k0 = (tid >> 6) * 8;
    const int g = lane >> 2, cq = lane & 3;
    const int lrA = lane & 15;
    const int lcA = (lane >> 4) * 8;
    const int lrB = ((lane >> 4) << 3) + (lane & 7);
    const int lcB = ((lane >> 3) & 1) * 8;
    const uint32_t bA = smem_u32(&As[0][0]), bB = smem_u32(&Bs[0][0]);

    float acc[2][4][4] = {};

    for (int k0 = 0; k0 < K; k0 += 32) {
        {
            const float* Ap = &A[(size_t)(m0 + a_row) * K + k0 + a_k0];
            float4 v0 = *(const float4*)(Ap + 0);
            float4 v1 = *(const float4*)(Ap + 4);
            float4 v2 = *(const float4*)(Ap + 8);
            float4 v3 = *(const float4*)(Ap + 12);
            uint4 u0, u1;
            u0.x = pkbf2(v0.x, v0.y); u0.y = pkbf2(v0.z, v0.w);
            u0.z = pkbf2(v1.x, v1.y); u0.w = pkbf2(v1.z, v1.w);
            u1.x = pkbf2(v2.x, v2.y); u1.y = pkbf2(v2.z, v2.w);
            u1.z = pkbf2(v3.x, v3.y); u1.w = pkbf2(v3.z, v3.w);
            *(uint4*)&As[a_row][a_k0 + 0] = u0;
            *(uint4*)&As[a_row][a_k0 + 8] = u1;
        }
        {
            float v[8];
#pragma unroll
            for (int i = 0; i < 8; i++)
                v[i] = B[(size_t)(k0 + b_k0 + i) * N + n0 + b_n];
            uint4 u;
            u.x = pkbf2(v[0], v[1]); u.y = pkbf2(v[2], v[3]);
            u.z = pkbf2(v[4], v[5]); u.w = pkbf2(v[6], v[7]);
            *(uint4*)&Bs[b_n][b_k0] = u;
        }
        __syncthreads();

#pragma unroll
        for (int kk = 0; kk < 32; kk += 16) {
            uint32_t af[2][4], bf[4][2];
#pragma unroll
            for (int im = 0; im < 2; im++) {
                uint32_t off = ((wm + im * 16 + lrA) * 40 + kk + lcA) * 2;
                ldsm4(af[im][0], af[im][1], af[im][2], af[im][3], bA + off);
            }
#pragma unroll
            for (int q = 0; q < 2; q++) {
                uint32_t off = ((wn + q * 16 + lrB) * 40 + kk + lcB) * 2;
                ldsm4(bf[2*q][0], bf[2*q][1], bf[2*q+1][0], bf[2*q+1][1], bB + off);
            }
#pragma unroll
            for (int im = 0; im < 2; im++)
#pragma unroll
                for (int in = 0; in < 4; in++)
                    MMA_BF16(acc[im][in], af[im][0], af[im][1], af[im][2], af[im][3],
                             bf[in][0], bf[in][1]);
        }
        __syncthreads();
    }

#pragma unroll
    for (int im = 0; im < 2; im++)
#pragma unroll
        for (int in = 0; in < 4; in++) {
            int cbase = n0 + wn + in * 8 + 2 * cq;
#pragma unroll
            for (int half = 0; half < 2; half++) {
                int m = m0 + wm + im * 16 + g + half * 8;
#pragma unroll
                for (int jj = 0; jj < 2; jj++) {
                    int n = cbase + jj;
                    float v = acc[im][in][half * 2 + jj];
                    if (EPI == 1) v += bias[n];
                    if (EPI == 2) v = fmaxf(v + bias[n], 0.0f);
                    if (EPI == 3) v = gelu_exact((v + bias[n]) * gam[n] + bet[n]);
                    if (EPI == 4) v = res[(size_t)m * N + n] + (v + bias[n]) * gam[n] + bet[n];
                    C[(size_t)m * N + n] = v;
                }
            }
        }
}

// =================================================================
// stem via tf32x3 + ldmatrix (R11 exact): epilogue writes nf + split
// =================================================================
__global__ __launch_bounds__(256) void stem_x3_kernel(
    const float* __restrict__ X, const float* __restrict__ Bw, float* __restrict__ C,
    uint32_t* __restrict__ Ch, uint32_t* __restrict__ Cl,
    const float* __restrict__ bias, const float* __restrict__ pos)
{
    const int Nd = 192, Kd = 768;
    __shared__ uint32_t Ah[128][20], Al[128][20];
    __shared__ uint32_t Bh[64][20],  Bl[64][20];
    const int tid  = threadIdx.x;
    const int lane = tid & 31, wid = tid >> 5;
    const int wm = (wid >> 1) * 32, wn = (wid & 1) * 32;
    const int m0 = blockIdx.y * 128, n0 = blockIdx.x * 64;
    const int a_row = tid >> 1, kq = (tid & 1) * 8;
    const int b_n = tid & 63, b_k0 = (tid >> 6) * 4;
    const int g = lane >> 2, cq = lane & 3;
    LDSM_OFFS();
    const uint32_t bAh = smem_u32(&Ah[0][0]), bAl = smem_u32(&Al[0][0]);
    const uint32_t bBh = smem_u32(&Bh[0][0]), bBl = smem_u32(&Bl[0][0]);

    const int m = m0 + a_row;
    const int bimg = m / NNODE;
    const int nsp = m % NNODE;
    const int py = nsp / HGRID, px = nsp % HGRID;
    const float* xbase = X + (size_t)bimg * 3 * IMGSZ * IMGSZ
                           + (size_t)(py * PATCH) * IMGSZ + px * PATCH;

    float acc[2][4][4] = {};

    for (int k0 = 0; k0 < Kd; k0 += 16) {
        {
            int kg = k0 + kq;
            int ci = kg >> 8, ky = (kg >> 4) & 15, kx = kg & 15;
            const float* xr = xbase + (size_t)ci * IMGSZ * IMGSZ + ky * IMGSZ + kx;
            float4 v0 = *(const float4*)xr;
            float4 v1 = *(const float4*)(xr + 4);
            uint32_t h, l;
            split_tf32(v0.x, h, l); Ah[a_row][kq + 0] = h; Al[a_row][kq + 0] = l;
            split_tf32(v0.y, h, l); Ah[a_row][kq + 1] = h; Al[a_row][kq + 1] = l;
            split_tf32(v0.z, h, l); Ah[a_row][kq + 2] = h; Al[a_row][kq + 2] = l;
            split_tf32(v0.w, h, l); Ah[a_row][kq + 3] = h; Al[a_row][kq + 3] = l;
            split_tf32(v1.x, h, l); Ah[a_row][kq + 4] = h; Al[a_row][kq + 4] = l;
            split_tf32(v1.y, h, l); Ah[a_row][kq + 5] = h; Al[a_row][kq + 5] = l;
            split_tf32(v1.z, h, l); Ah[a_row][kq + 6] = h; Al[a_row][kq + 6] = l;
            split_tf32(v1.w, h, l); Ah[a_row][kq + 7] = h; Al[a_row][kq + 7] = l;
        }
#pragma unroll
        for (int i = 0; i < 4; i++) {
            float v = Bw[(size_t)(k0 + b_k0 + i) * Nd + n0 + b_n];
            uint32_t h, l;
            split_tf32(v, h, l);
            Bh[b_n][b_k0 + i] = h; Bl[b_n][b_k0 + i] = l;
        }
        __syncthreads();

#pragma unroll
        for (int kk = 0; kk < 16; kk += 8) {
            uint32_t ah[2][4], al[2][4], bh[4][2], bl[4][2];
#pragma unroll
            for (int im = 0; im < 2; im++) {
                uint32_t off = ((wm + im * 16 + lrA) * 20 + kk + lcA) * 4;
                ldsm4(ah[im][0], ah[im][1], ah[im][2], ah[im][3], bAh + off);
                ldsm4(al[im][0], al[im][1], al[im][2], al[im][3], bAl + off);
            }
#pragma unroll
            for (int q = 0; q < 2; q++) {
                uint32_t off = ((wn + q * 16 + lrB) * 20 + kk + lcB) * 4;
                ldsm4(bh[2*q][0], bh[2*q][1], bh[2*q+1][0], bh[2*q+1][1], bBh + off);
                ldsm4(bl[2*q][0], bl[2*q][1], bl[2*q+1][0], bl[2*q+1][1], bBl + off);
            }
#pragma unroll
            for (int im = 0; im < 2; im++)
#pragma unroll
                for (int in = 0; in < 4; in++) {
                    MMA_TF32(acc[im][in], ah[im][0], ah[im][1], ah[im][2], ah[im][3],
                             bh[in][0], bh[in][1]);
                    MMA_TF32(acc[im][in], ah[im][0], ah[im][1], ah[im][2], ah[im][3],
                             bl[in][0], bl[in][1]);
                    MMA_TF32(acc[im][in], al[im][0], al[im][1], al[im][2], al[im][3],
                             bh[in][0], bh[in][1]);
                }
        }
        __syncthreads();
    }

#pragma unroll
    for (int im = 0; im < 2; im++)
#pragma unroll
        for (int in = 0; in < 4; in++) {
            int cbase = n0 + wn + in * 8 + 2 * cq;
#pragma unroll
            for (int half = 0; half < 2; half++) {
                int mm = m0 + wm + im * 16 + g + half * 8;
                int sp = mm % NNODE;
#pragma unroll
                for (int jj = 0; jj < 2; jj++) {
                    int n = cbase + jj;
                    float v = acc[im][in][half * 2 + jj] + bias[n] + pos[n * NNODE + sp];
                    C[(size_t)mm * CH + n] = v;
                    uint32_t h, l;
                    split_tf32(v, h, l);
                    Ch[(size_t)mm * CH + n] = h;
                    Cl[(size_t)mm * CH + n] = l;
                }
            }
        }
}

// ---------------- small-M SGEMM for pred head (M=64) ----------------
#define BM 64
#define BNT 64
#define BKT 16
template <int EPI>
__global__ __launch_bounds__(256) void sgemm_kernel(
    const float* __restrict__ A, const float* __restrict__ B, float* __restrict__ C,
    int M, int N, int K,
    const float* __restrict__ bias, const float* __restrict__ gam,
    const float* __restrict__ bet,  const float* __restrict__ res)
{
    __shared__ float As[BKT][BM];
    __shared__ float Bs[BKT][BNT];
    const int tid = threadIdx.x;
    const int tx = tid & 15, ty = tid >> 4;
    const int m0 = blockIdx.y * BM, n0 = blockIdx.x * BNT;
    const int a_m = tid >> 2, a_k = (tid & 3) * 4;
    const int b_k = tid >> 4, b_n = (tid & 15) * 4;

    float acc[4][4] = {};
    for (int k0 = 0; k0 < K; k0 += BKT) {
        float4 av = *(const float4*)&A[(size_t)(m0 + a_m) * K + k0 + a_k];
        As[a_k + 0][a_m] = av.x; As[a_k + 1][a_m] = av.y;
        As[a_k + 2][a_m] = av.z; As[a_k + 3][a_m] = av.w;
        float4 bv = *(const float4*)&B[(size_t)(k0 + b_k) * N + n0 + b_n];
        *(float4*)&Bs[b_k][b_n] = bv;
        __syncthreads();
#pragma unroll
        for (int k = 0; k < BKT; k++) {
            float ar[4], br[4];
#pragma unroll
            for (int i = 0; i < 4; i++) ar[i] = As[k][ty * 4 + i];
#pragma unroll
            for (int j = 0; j < 4; j++) br[j] = Bs[k][tx * 4 + j];
#pragma unroll
            for (int i = 0; i < 4; i++)
#pragma unroll
                for (int j = 0; j < 4; j++) acc[i][j] = fmaf(ar[i], br[j], acc[i][j]);
        }
        __syncthreads();
    }
#pragma unroll
    for (int i = 0; i < 4; i++) {
        int m = m0 + ty * 4 + i;
#pragma unroll
        for (int j = 0; j < 4; j++) {
            int n = n0 + tx * 4 + j;
            float v = acc[i][j];
            if (EPI == 1) v += bias[n];
            if (EPI == 2) v = fmaxf(v + bias[n], 0.0f);
            if (EPI == 3) v = gelu_exact((v + bias[n]) * gam[n] + bet[n]);
            if (EPI == 4) v = res[(size_t)m * N + n] + (v + bias[n]) * gam[n] + bet[n];
            C[(size_t)m * N + n] = v;
        }
    }
}

// ---------------- auxiliary kernels ----------------
__global__ void transpose_w_kernel(const float* __restrict__ w, float* __restrict__ wt) {
    int i = blockIdx.x * blockDim.x + threadIdx.x;
    if (i >= 192 * 768) return;
    int n = i / 768, k = i % 768;
    wt[k * 192 + n] = w[i];
}

__global__ void sq_kernel(const float* __restrict__ nf, float* __restrict__ sq) {
    int node = (blockIdx.x * blockDim.x + threadIdx.x) >> 5;
    int lane = threadIdx.x & 31;
    if (node >= BN) return;
    float s = 0.f;
#pragma unroll
    for (int j = 0; j < 6; j++) {
        float x = nf[(size_t)node * CH + lane + 32 * j];
        s = fmaf(x, x, s);
    }
#pragma unroll
    for (int off = 16; off; off >>= 1) s += __shfl_down_sync(0xffffffffu, s, off);
    if (lane == 0) sq[node] = s;
}

__global__ void topk_kernel(const float* __restrict__ d2, int* __restrict__ idx) {
    int row = (blockIdx.x * blockDim.x + threadIdx.x) >> 5;
    int lane = threadIdx.x & 31;
    if (row >= BN) return;
    const float* r = d2 + (size_t)row * NNODE;
    float v[18];
#pragma unroll
    for (int j = 0; j < 18; j++) v[j] = r[lane + 32 * j];
    int bimg = row / NNODE;
#pragma unroll
    for (int s = 0; s < 5; s++) {
        float bv = 3.4e38f; int bc = 1 << 30;
#pragma unroll
        for (int j = 0; j < 18; j++) {
            int c = lane + 32 * j;
            if (v[j] < bv) { bv = v[j]; bc = c; }
        }
#pragma unroll
        for (int off = 16; off; off >>= 1) {
            float ov = __shfl_down_sync(0xffffffffu, bv, off);
            int   oc = __shfl_down_sync(0xffffffffu, bc, off);
            if (ov < bv || (ov == bv && oc < bc)) { bv = ov; bc = oc; }
        }
        bc = __shfl_sync(0xffffffffu, bc, 0);
        if ((bc & 31) == lane) v[bc >> 5] = 3.4e38f;
        if (lane == 0) idx[row * KNN + s] = bimg * NNODE + bc;
    }
}

__global__ void edge_kernel(const float* __restrict__ P, const float* __restrict__ Q,
                            const int* __restrict__ idx,
                            const float* __restrict__ w2, const float* __restrict__ b2,
                            float* __restrict__ att, float* __restrict__ out)
{
    int node = (blockIdx.x * blockDim.x + threadIdx.x) >> 5;
    int lane = threadIdx.x & 31;
    if (node >= BN) return;
    float q[6], w[6];
#pragma unroll
    for (int j = 0; j < 6; j++) {
        q[j] = Q[(size_t)node * CH + lane + 32 * j];
        w[j] = w2[lane + 32 * j];
    }
    const float b2v = b2[0];
#pragma unroll
    for (int k = 0; k < KNN; k++) {
        int e = node * KNN + k;
        int src = idx[e];
        float s = 0.f;
#pragma unroll
        for (int j = 0; j < 6; j++) {
            float x = P[(size_t)src * CH + lane + 32 * j] + q[j];
            x = fmaxf(x, 0.f);
            s = fmaf(x, w[j], s);
        }
#pragma unroll
        for (int off = 16; off; off >>= 1) s += __shfl_down_sync(0xffffffffu, s, off);
        if (lane == 0) {
            float a = 1.0f / (1.0f + expf(-(s + b2v)));
            att[e] = a;
            out[e] = a;
        }
    }
}

__global__ void agg_kernel(const float* __restrict__ h, const int* __restrict__ idx,
                           const float* __restrict__ att, float* __restrict__ hm)
{
    int i = blockIdx.x;
    int c = threadIdx.x;
    float acc = h[(size_t)i * CH + c];
#pragma unroll
    for (int k = 0; k < KNN; k++) {
        int nb = idx[i * KNN + k];
        float a = att[i * KNN + k];
        acc = fmaf(a, h[(size_t)nb * CH + c], acc);
    }
    hm[(size_t)i * CH + c] = acc;
}

__global__ void pool_kernel(const float* __restrict__ t, float* __restrict__ g) {
    int b = blockIdx.x, c = threadIdx.x;
    float acc = 0.f;
    for (int n = 0; n < NNODE; n++) acc += t[((size_t)b * NNODE + n) * CH + c];
    g[b * CH + c] = acc * (1.0f / NNODE);
}

__global__ void pred_final_kernel(const float* __restrict__ p, const float* __restrict__ w2,
                                  const float* __restrict__ b2, float* __restrict__ out)
{
    int b = blockIdx.x, tid = threadIdx.x;
    float s = 0.f;
    for (int i = tid; i < PHID; i += 256) s = fmaf(p[(size_t)b * PHID + i], w2[i], s);
    __shared__ float red[256];
    red[tid] = s; __syncthreads();
    for (int st = 128; st; st >>= 1) { if (tid < st) red[tid] += red[tid + st]; __syncthreads(); }
    if (tid == 0) out[b] = red[0] + b2[0];
}

// ---------------- host launch ----------------
extern "C" void kernel_launch(void* const* d_in, const int* in_sizes, int n_in,
                              void* d_out, int out_size)
{
    const float* x        = (const float*)d_in[0];
    const float* stem_w   = (const float*)d_in[1];
    const float* stem_b   = (const float*)d_in[2];
    const float* pos      = (const float*)d_in[3];
    const float* att_w1   = (const float*)d_in[4];
    const float* att_b1   = (const float*)d_in[5];
    const float* att_w2   = (const float*)d_in[6];
    const float* att_b2   = (const float*)d_in[7];
    const float* gnn_w1   = (const float*)d_in[8];
    const float* gnn_b1   = (const float*)d_in[9];
    const float* gnn_w2   = (const float*)d_in[10];
    const float* gnn_b2   = (const float*)d_in[11];
    const float* ffn_w1   = (const float*)d_in[12];
    const float* ffn_b1   = (const float*)d_in[13];
    const float* ffn_g1   = (const float*)d_in[14];
    const float* ffn_be1  = (const float*)d_in[15];
    const float* ffn_w2   = (const float*)d_in[16];
    const float* ffn_b2   = (const float*)d_in[17];
    const float* ffn_g2   = (const float*)d_in[18];
    const float* ffn_be2  = (const float*)d_in[19];
    const float* pred_w1  = (const float*)d_in[20];
    const float* pred_b1  = (const float*)d_in[21];
    const float* pred_g   = (const float*)d_in[22];
    const float* pred_be  = (const float*)d_in[23];
    const float* pred_w2  = (const float*)d_in[24];
    const float* pred_b2  = (const float*)d_in[25];
    float* out = (float*)d_out;

    float *p_wt, *p_nf, *p_sq, *p_d2, *p_P, *p_Q, *p_att, *p_h, *p_hm, *p_u, *p_t, *p_g, *p_p;
    uint32_t *p_nfh, *p_nfl;
    int* p_idx;
    cudaGetSymbolAddress((void**)&p_wt,  g_wt);
    cudaGetSymbolAddress((void**)&p_nf,  g_nf);
    cudaGetSymbolAddress((void**)&p_nfh, g_nfh);
    cudaGetSymbolAddress((void**)&p_nfl, g_nfl);
    cudaGetSymbolAddress((void**)&p_sq,  g_sq);
    cudaGetSymbolAddress((void**)&p_d2,  g_d2);
    cudaGetSymbolAddress((void**)&p_idx, g_idx);
    cudaGetSymbolAddress((void**)&p_P,   g_P);
    cudaGetSymbolAddress((void**)&p_Q,   g_Q);
    cudaGetSymbolAddress((void**)&p_att, g_att);
    cudaGetSymbolAddress((void**)&p_h,   g_h);
    cudaGetSymbolAddress((void**)&p_hm,  g_hm);
    cudaGetSymbolAddress((void**)&p_u,   g_u);
    cudaGetSymbolAddress((void**)&p_t,   g_t);
    cudaGetSymbolAddress((void**)&p_g,   g_g);
    cudaGetSymbolAddress((void**)&p_p,   g_p);

    cudaFuncSetAttribute(gram_x3_sym_kernel,
                         cudaFuncAttributeMaxDynamicSharedMemorySize, 40960);

    transpose_w_kernel<<<(192 * 768 + 255) / 256, 256>>>(stem_w, p_wt);

    // ---- graph path (slab-16 pipelined gram, bit-identical d2) ----
    stem_x3_kernel<<<dim3(CH / 64, BN / 128), 256>>>(x, p_wt, p_nf, p_nfh, p_nfl, stem_b, pos);
    sq_kernel<<<(BN * 32 + 255) / 256, 256>>>(p_nf, p_sq);
    gram_x3_sym_kernel<<<dim3(45, 1, Bsz), 128, 40960>>>(p_nfh, p_nfl, p_sq, p_d2);
    topk_kernel<<<(BN * 32 + 255) / 256, 256>>>(p_d2, p_idx);

    // ---- edge attention (tf32; R11) ----
    tf32gemm_kernel<0,1><<<dim3(CH / 64, BN / 128), 256>>>(p_nfh, att_w1, p_P, BN, CH, CH,
                                                           nullptr, nullptr, nullptr, nullptr);
    tf32gemm_kernel<1,1><<<dim3(CH / 64, BN / 128), 256>>>(p_nfh, att_w1 + 192 * 192, p_Q,
                                                           BN, CH, CH,
                                                           att_b1, nullptr, nullptr, nullptr);
    edge_kernel<<<(BN * 32 + 255) / 256, 256>>>(p_P, p_Q, p_idx, att_w2, att_b2, p_att, out);

    // ---- prediction path (bf16; R11) ----
    agg_kernel<<<BN, CH>>>(p_nf, p_idx, p_att, p_hm);
    bf16gemm_kernel<2><<<dim3(CH / 64, BN / 128), 256>>>(p_hm, gnn_w1, p_h, BN, CH, CH,
                                                         gnn_b1, nullptr, nullptr, nullptr);
    agg_kernel<<<BN, CH>>>(p_h, p_idx, p_att, p_hm);
    bf16gemm_kernel<2><<<dim3(CH / 64, BN / 128), 256>>>(p_hm, gnn_w2, p_h, BN, CH, CH,
                                                         gnn_b2, nullptr, nullptr, nullptr);
    bf16gemm_kernel<3><<<dim3(HID / 64, BN / 128), 256>>>(p_h, ffn_w1, p_u, BN, HID, CH,
                                                          ffn_b1, ffn_g1, ffn_be1, nullptr);
    bf16gemm_kernel<4><<<dim3(CH / 64, BN / 128), 256>>>(p_u, ffn_w2, p_t, BN, CH, HID,
                                                         ffn_b2, ffn_g2, ffn_be2, p_h);

    pool_kernel<<<Bsz, CH>>>(p_t, p_g);
    sgemm_kernel<3><<<dim3(PHID / BNT, Bsz / BM), 256>>>(p_g, pred_w1, p_p, Bsz, PHID, CH,
                                                         pred_b1, pred_g, pred_be, nullptr);
    pred_final_kernel<<<Bsz, 256>>>(p_p, pred_w2, pred_b2, out + EDG);
}

// round 15
// speedup vs baseline: 1.2437x; 1.1014x over previous
#include <cuda_runtime.h>
#include <cuda_bf16.h>
#include <math.h>
#include <stdint.h>

// ---------------- problem constants ----------------
#define Bsz   64
#define IMGSZ 384
#define PATCH 16
#define CH    192
#define KNN   5
#define HGRID 24
#define NNODE 576
#define BN    (Bsz * NNODE)  // 36864
#define EDG   (BN * KNN)     // 184320
#define HID   768
#define PHID  1024

// ---------------- scratch ----------------
__device__ float    g_wt  [768 * 192];
__device__ float    g_nf  [(size_t)BN * CH];
__device__ uint32_t g_nfh [(size_t)BN * CH];
__device__ float    g_sq  [BN];
__device__ float    g_d2  [(size_t)Bsz * NNODE * NNODE];
__device__ int      g_idx [BN * KNN];
__device__ float    g_P   [(size_t)BN * CH];
__device__ float    g_Q   [(size_t)BN * CH];
__device__ float    g_att [EDG];
__device__ float    g_h   [(size_t)BN * CH];
__device__ float    g_hm  [(size_t)BN * CH];
__device__ float    g_u   [(size_t)BN * HID];
__device__ float    g_t   [(size_t)BN * CH];
__device__ float    g_g   [Bsz * CH];
__device__ float    g_p   [Bsz * PHID];

__device__ __forceinline__ float gelu_exact(float v) {
    return 0.5f * v * (1.0f + erff(v * 0.70710678118654752f));
}
__device__ __forceinline__ uint32_t f2tf32(float x) {
    uint32_t r; asm("cvt.rna.tf32.f32 %0, %1;" : "=r"(r) : "f"(x)); return r;
}
__device__ __forceinline__ void split_tf32(float x, uint32_t& hi, uint32_t& lo) {
    hi = f2tf32(x);
    lo = f2tf32(x - __uint_as_float(hi));
}
// split 4 raw fragment regs (fp32 payload) -> hi/lo tf32 regs
__device__ __forceinline__ void split4(const uint32_t* r, uint32_t* h, uint32_t* l) {
#pragma unroll
    for (int i = 0; i < 4; i++) {
        float v = __uint_as_float(r[i]);
        split_tf32(v, h[i], l[i]);
    }
}
__device__ __forceinline__ void split2(const uint32_t* r, uint32_t* h, uint32_t* l) {
#pragma unroll
    for (int i = 0; i < 2; i++) {
        float v = __uint_as_float(r[i]);
        split_tf32(v, h[i], l[i]);
    }
}
__device__ __forceinline__ uint32_t smem_u32(const void* p) {
    return (uint32_t)__cvta_generic_to_shared(p);
}
__device__ __forceinline__ void ldsm4(uint32_t& r0, uint32_t& r1, uint32_t& r2,
                                      uint32_t& r3, uint32_t a) {
    asm volatile("ldmatrix.sync.aligned.m8n8.x4.shared.b16 {%0,%1,%2,%3}, [%4];"
                 : "=r"(r0), "=r"(r1), "=r"(r2), "=r"(r3) : "r"(a));
}
__device__ __forceinline__ uint32_t pkbf2(float a, float b) {
    __nv_bfloat162 t = __floats2bfloat162_rn(a, b);
    return *(uint32_t*)&t;
}
__device__ __forceinline__ void cp16(uint32_t dst, const void* src) {
    asm volatile("cp.async.cg.shared.global [%0], [%1], 16;" :: "r"(dst), "l"(src));
}
__device__ __forceinline__ void cp4(uint32_t dst, const void* src) {
    asm volatile("cp.async.ca.shared.global [%0], [%1], 4;" :: "r"(dst), "l"(src));
}
__device__ __forceinline__ void cp_commit() { asm volatile("cp.async.commit_group;"); }
__device__ __forceinline__ void cp_wait1()  { asm volatile("cp.async.wait_group 1;"); }
__device__ __forceinline__ void cp_wait0()  { asm volatile("cp.async.wait_group 0;"); }

#define MMA_TF32(acc, a0, a1, a2, a3, b0, b1)                                \
    asm volatile(                                                            \
        "mma.sync.aligned.m16n8k8.row.col.f32.tf32.tf32.f32 "               \
        "{%0,%1,%2,%3}, {%4,%5,%6,%7}, {%8,%9}, {%0,%1,%2,%3};"             \
        : "+f"(acc[0]), "+f"(acc[1]), "+f"(acc[2]), "+f"(acc[3])             \
        : "r"(a0), "r"(a1), "r"(a2), "r"(a3), "r"(b0), "r"(b1))
#define MMA_BF16(acc, a0, a1, a2, a3, b0, b1)                                \
    asm volatile(                                                            \
        "mma.sync.aligned.m16n8k16.row.col.f32.bf16.bf16.f32 "              \
        "{%0,%1,%2,%3}, {%4,%5,%6,%7}, {%8,%9}, {%0,%1,%2,%3};"             \
        : "+f"(acc[0]), "+f"(acc[1]), "+f"(acc[2]), "+f"(acc[3])             \
        : "r"(a0), "r"(a1), "r"(a2), "r"(a3), "r"(b0), "r"(b1))

#define LDSM_OFFS()                                                          \
    const int lrA = lane & 15;                                               \
    const int lcA = (lane >> 4) * 4;                                         \
    const int lrB = ((lane >> 4) << 3) + (lane & 7);                         \
    const int lcB = ((lane >> 3) & 1) * 4

// tf32x3 MMA chain on raw fragments (split in regs) — order identical
// to stored-hi/lo version -> results bit-identical.
__device__ __forceinline__ void mma_x3_frag(
    float acc[2][4][4], const uint32_t ar[2][4], const uint32_t br[4][2])
{
    uint32_t ah[2][4], al[2][4], bh[4][2], bl[4][2];
#pragma unroll
    for (int im = 0; im < 2; im++) split4(ar[im], ah[im], al[im]);
#pragma unroll
    for (int in = 0; in < 4; in++) split2(br[in], bh[in], bl[in]);
#pragma unroll
    for (int im = 0; im < 2; im++)
#pragma unroll
        for (int in = 0; in < 4; in++) {
            MMA_TF32(acc[im][in], ah[im][0], ah[im][1], ah[im][2], ah[im][3],
                     bh[in][0], bh[in][1]);
            MMA_TF32(acc[im][in], ah[im][0], ah[im][1], ah[im][2], ah[im][3],
                     bl[in][0], bl[in][1]);
            MMA_TF32(acc[im][in], al[im][0], al[im][1], al[im][2], al[im][3],
                     bh[in][0], bh[in][1]);
        }
}

// =================================================================
// gram: raw-stage tf32x3 + symmetry + cp.async pipeline, slab 16.
// Stage = Araw 64x20 + Braw 64x20 = 10240 B; 2 stages 20480 B.
// =================================================================
__global__ __launch_bounds__(128) void gram_x3_sym_kernel(
    const float* __restrict__ nf, const float* __restrict__ sq, float* __restrict__ d2)
{
    extern __shared__ uint32_t DSM[];
    const int b = blockIdx.z;
    const float* Ab = nf + (size_t)b * NNODE * CH;

    int p = blockIdx.x, ti = 0;
    while (p >= 9 - ti) { p -= 9 - ti; ti++; }
    const int tj = ti + p;
    const int r0b = ti * 64, c0b = tj * 64;

    const int tid  = threadIdx.x;
    const int lane = tid & 31, wid = tid >> 5;
    const int wm = (wid >> 1) * 32, wn = (wid & 1) * 32;
    const int row = tid >> 1, kq = (tid & 1) * 8;
    const int g = lane >> 2, cq = lane & 3;
    LDSM_OFFS();
    const uint32_t base = smem_u32(DSM);
    // stage layout: Araw +0 (5120B), Braw +5120; stage stride 10240

    auto fill = [&](int k0, int st) {
        uint32_t sb = base + (uint32_t)st * 10240u;
        const float* ra = Ab + (size_t)(r0b + row) * CH + k0 + kq;
        const float* rb = Ab + (size_t)(c0b + row) * CH + k0 + kq;
#pragma unroll
        for (int i = 0; i < 2; i++) {
            uint32_t off = (uint32_t)(row * 20 + kq + i * 4) * 4;
            cp16(sb + off,        ra + i * 4);
            cp16(sb + 5120 + off, rb + i * 4);
        }
        cp_commit();
    };

    float acc[2][4][4] = {};

    const int NS = CH / 16;   // 12
    fill(0, 0);
    for (int s = 0; s < NS; s++) {
        if (s + 1 < NS) fill((s + 1) * 16, (s + 1) & 1);
        if (s + 1 < NS) cp_wait1(); else cp_wait0();
        __syncthreads();

        uint32_t sb = base + (uint32_t)(s & 1) * 10240u;
        const uint32_t bA = sb, bB = sb + 5120;
#pragma unroll
        for (int kk = 0; kk < 16; kk += 8) {
            uint32_t ar[2][4], br[4][2];
#pragma unroll
            for (int im = 0; im < 2; im++) {
                uint32_t off = ((wm + im * 16 + lrA) * 20 + kk + lcA) * 4;
                ldsm4(ar[im][0], ar[im][1], ar[im][2], ar[im][3], bA + off);
            }
#pragma unroll
            for (int q = 0; q < 2; q++) {
                uint32_t off = ((wn + q * 16 + lrB) * 20 + kk + lcB) * 4;
                ldsm4(br[2*q][0], br[2*q][1], br[2*q+1][0], br[2*q+1][1], bB + off);
            }
            mma_x3_frag(acc, ar, br);
        }
        __syncthreads();
    }

#pragma unroll
    for (int im = 0; im < 2; im++)
#pragma unroll
        for (int in = 0; in < 4; in++) {
            int cbase = c0b + wn + in * 8 + 2 * cq;
#pragma unroll
            for (int half = 0; half < 2; half++) {
                int r = r0b + wm + im * 16 + g + half * 8;
#pragma unroll
                for (int jj = 0; jj < 2; jj++) {
                    int c = cbase + jj;
                    float v = sq[b * NNODE + c] - 2.0f * acc[im][in][half * 2 + jj];
                    if (r == c) v = 3.0e38f;
                    d2[((size_t)b * NNODE + r) * NNODE + c] = v;
                }
            }
        }

    if (ti != tj) {
        float* T = (float*)DSM;   // 64x68 floats = 17408 B <= 20480
#pragma unroll
        for (int im = 0; im < 2; im++)
#pragma unroll
            for (int in = 0; in < 4; in++) {
                int cl = wn + in * 8 + 2 * cq;
#pragma unroll
                for (int half = 0; half < 2; half++) {
                    int rl = wm + im * 16 + g + half * 8;
                    T[(cl    ) * 68 + rl] = acc[im][in][half * 2 + 0];
                    T[(cl + 1) * 68 + rl] = acc[im][in][half * 2 + 1];
                }
            }
        __syncthreads();
        for (int i = tid; i < 64 * 16; i += 128) {
            int cl = i >> 4;
            int r4 = (i & 15) * 4;
            float4 dv = *(const float4*)&T[cl * 68 + r4];
            float4 sv = *(const float4*)&sq[b * NNODE + r0b + r4];
            float4 o;
            o.x = sv.x - 2.0f * dv.x;
            o.y = sv.y - 2.0f * dv.y;
            o.z = sv.z - 2.0f * dv.z;
            o.w = sv.w - 2.0f * dv.w;
            *(float4*)&d2[((size_t)b * NNODE + c0b + cl) * NNODE + r0b + r4] = o;
        }
    }
}

// =================================================================
// stem: raw-stage tf32x3 + cp.async pipeline, slab 16.
// Stage = Araw 128x20 (10240B) + Braw 64x20 (5120B) = 15360 B;
// 2 stages 30720 B dynamic. Split in regs -> nf bit-identical.
// =================================================================
__global__ __launch_bounds__(256) void stem_x3_kernel(
    const float* __restrict__ X, const float* __restrict__ Bw, float* __restrict__ C,
    uint32_t* __restrict__ Ch,
    const float* __restrict__ bias, const float* __restrict__ pos)
{
    extern __shared__ uint32_t DSM[];
    const int Nd = 192, Kd = 768;
    const int tid  = threadIdx.x;
    const int lane = tid & 31, wid = tid >> 5;
    const int wm = (wid >> 1) * 32, wn = (wid & 1) * 32;
    const int m0 = blockIdx.y * 128, n0 = blockIdx.x * 64;
    const int a_row = tid >> 1, kq = (tid & 1) * 8;
    const int b_n = tid & 63, b_k0 = (tid >> 6) * 4;
    const int g = lane >> 2, cq = lane & 3;
    LDSM_OFFS();
    const uint32_t base = smem_u32(DSM);
    // stage layout: Araw +0 (10240B), Braw +10240 (5120B); stride 15360

    const int m = m0 + a_row;
    const int bimg = m / NNODE;
    const int nsp = m % NNODE;
    const int py = nsp / HGRID, px = nsp % HGRID;
    const float* xbase = X + (size_t)bimg * 3 * IMGSZ * IMGSZ
                           + (size_t)(py * PATCH) * IMGSZ + px * PATCH;

    auto fill = [&](int k0, int st) {
        uint32_t sb = base + (uint32_t)st * 15360u;
        int kg = k0 + kq;
        int ci = kg >> 8, ky = (kg >> 4) & 15, kx = kg & 15;
        const float* xr = xbase + (size_t)ci * IMGSZ * IMGSZ + ky * IMGSZ + kx;
#pragma unroll
        for (int i = 0; i < 2; i++) {
            uint32_t off = (uint32_t)(a_row * 20 + kq + i * 4) * 4;
            cp16(sb + off, xr + i * 4);
        }
#pragma unroll
        for (int i = 0; i < 4; i++) {
            uint32_t off = (uint32_t)(b_n * 20 + b_k0 + i) * 4;
            cp4(sb + 10240 + off, Bw + (size_t)(k0 + b_k0 + i) * Nd + n0 + b_n);
        }
        cp_commit();
    };

    float acc[2][4][4] = {};

    const int NS = Kd / 16;   // 48
    fill(0, 0);
    for (int s = 0; s < NS; s++) {
        if (s + 1 < NS) fill((s + 1) * 16, (s + 1) & 1);
        if (s + 1 < NS) cp_wait1(); else cp_wait0();
        __syncthreads();

        uint32_t sb = base + (uint32_t)(s & 1) * 15360u;
        const uint32_t bA = sb, bB = sb + 10240;
#pragma unroll
        for (int kk = 0; kk < 16; kk += 8) {
            uint32_t ar[2][4], br[4][2];
#pragma unroll
            for (int im = 0; im < 2; im++) {
                uint32_t off = ((wm + im * 16 + lrA) * 20 + kk + lcA) * 4;
                ldsm4(ar[im][0], ar[im][1], ar[im][2], ar[im][3], bA + off);
            }
#pragma unroll
            for (int q = 0; q < 2; q++) {
                uint32_t off = ((wn + q * 16 + lrB) * 20 + kk + lcB) * 4;
                ldsm4(br[2*q][0], br[2*q][1], br[2*q+1][0], br[2*q+1][1], bB + off);
            }
            mma_x3_frag(acc, ar, br);
        }
        __syncthreads();
    }

#pragma unroll
    for (int im = 0; im < 2; im++)
#pragma unroll
        for (int in = 0; in < 4; in++) {
            int cbase = n0 + wn + in * 8 + 2 * cq;
#pragma unroll
            for (int half = 0; half < 2; half++) {
                int mm = m0 + wm + im * 16 + g + half * 8;
                int sp = mm % NNODE;
#pragma unroll
                for (int jj = 0; jj < 2; jj++) {
                    int n = cbase + jj;
                    float v = acc[im][in][half * 2 + jj] + bias[n] + pos[n * NNODE + sp];
                    C[(size_t)mm * CH + n] = v;
                    Ch[(size_t)mm * CH + n] = f2tf32(v);
                }
            }
        }
}

// =================================================================
// tf32 GEMM + ldmatrix (P/Q path). PRE=1: A pre-converted tf32 hi.
// =================================================================
template <int EPI, int PRE>
__global__ __launch_bounds__(256) void tf32gemm_kernel(
    const void* __restrict__ Av, const float* __restrict__ B, float* __restrict__ C,
    int M, int N, int K,
    const float* __restrict__ bias, const float* __restrict__ gam,
    const float* __restrict__ bet,  const float* __restrict__ res)
{
    __shared__ uint32_t As[128][36];
    __shared__ uint32_t Bs[64][36];
    const int tid  = threadIdx.x;
    const int lane = tid & 31, wid = tid >> 5;
    const int wm = (wid >> 1) * 32;
    const int wn = (wid & 1) * 32;
    const int m0 = blockIdx.y * 128, n0 = blockIdx.x * 64;
    const int a_row = tid >> 1, a_k0 = (tid & 1) * 16;
    const int b_n = tid & 63, b_k0 = (tid >> 6) * 8;
    const int g = lane >> 2, cq = lane & 3;
    LDSM_OFFS();
    const uint32_t bA = smem_u32(&As[0][0]), bB = smem_u32(&Bs[0][0]);

    float acc[2][4][4] = {};

    for (int k0 = 0; k0 < K; k0 += 32) {
        if (PRE) {
            const uint32_t* Ai = (const uint32_t*)Av;
#pragma unroll
            for (int i = 0; i < 4; i++)
                *(uint4*)&As[a_row][a_k0 + i * 4] =
                    *(const uint4*)&Ai[(size_t)(m0 + a_row) * K + k0 + a_k0 + i * 4];
        } else {
            const float* A = (const float*)Av;
#pragma unroll
            for (int i = 0; i < 4; i++) {
                float4 v = *(const float4*)&A[(size_t)(m0 + a_row) * K + k0 + a_k0 + i * 4];
                As[a_row][a_k0 + i * 4 + 0] = f2tf32(v.x);
                As[a_row][a_k0 + i * 4 + 1] = f2tf32(v.y);
                As[a_row][a_k0 + i * 4 + 2] = f2tf32(v.z);
                As[a_row][a_k0 + i * 4 + 3] = f2tf32(v.w);
            }
        }
#pragma unroll
        for (int i = 0; i < 8; i++) {
            float v = B[(size_t)(k0 + b_k0 + i) * N + n0 + b_n];
            Bs[b_n][b_k0 + i] = f2tf32(v);
        }
        __syncthreads();

#pragma unroll
        for (int kk = 0; kk < 32; kk += 8) {
            uint32_t af[2][4], bf[4][2];
#pragma unroll
            for (int im = 0; im < 2; im++) {
                uint32_t off = ((wm + im * 16 + lrA) * 36 + kk + lcA) * 4;
                ldsm4(af[im][0], af[im][1], af[im][2], af[im][3], bA + off);
            }
#pragma unroll
            for (int q = 0; q < 2; q++) {
                uint32_t off = ((wn + q * 16 + lrB) * 36 + kk + lcB) * 4;
                ldsm4(bf[2*q][0], bf[2*q][1], bf[2*q+1][0], bf[2*q+1][1], bB + off);
            }
#pragma unroll
            for (int im = 0; im < 2; im++)
#pragma unroll
                for (int in = 0; in < 4; in++)
                    MMA_TF32(acc[im][in], af[im][0], af[im][1], af[im][2], af[im][3],
                             bf[in][0], bf[in][1]);
        }
        __syncthreads();
    }

#pragma unroll
    for (int im = 0; im < 2; im++)
#pragma unroll
        for (int in = 0; in < 4; in++) {
            int cbase = n0 + wn + in * 8 + 2 * cq;
#pragma unroll
            for (int half = 0; half < 2; half++) {
                int m = m0 + wm + im * 16 + g + half * 8;
#pragma unroll
                for (int jj = 0; jj < 2; jj++) {
                    int n = cbase + jj;
                    float v = acc[im][in][half * 2 + jj];
                    if (EPI == 1) v += bias[n];
                    if (EPI == 2) v = fmaxf(v + bias[n], 0.0f);
                    if (EPI == 3) v = gelu_exact((v + bias[n]) * gam[n] + bet[n]);
                    if (EPI == 4) v = res[(size_t)m * N + n] + (v + bias[n]) * gam[n] + bet[n];
                    C[(size_t)m * N + n] = v;
                }
            }
        }
}

// =================================================================
// bf16 GEMM (prediction path; unchanged)
// =================================================================
template <int EPI>
__global__ __launch_bounds__(256) void bf16gemm_kernel(
    const float* __restrict__ A, const float* __restrict__ B, float* __restrict__ C,
    int M, int N, int K,
    const float* __restrict__ bias, const float* __restrict__ gam,
    const float* __restrict__ bet,  const float* __restrict__ res)
{
    __shared__ __nv_bfloat16 As[128][40];
    __shared__ __nv_bfloat16 Bs[64][40];
    const int tid  = threadIdx.x;
    const int lane = tid & 31, wid = tid >> 5;
    const int wm = (wid >> 1) * 32;
    const int wn = (wid & 1) * 32;
    const int m0 = blockIdx.y * 128, n0 = blockIdx.x * 64;
    const int a_row = tid >> 1, a_k0 = (tid & 1) * 16;
    const int b_n = tid & 63, b_k0 = (tid >> 6) * 8;
    const int g = lane >> 2, cq = lane & 3;
    const int lrA = lane & 15;
    const int lcA = (lane >> 4) * 8;
    const int lrB = ((lane >> 4) << 3) + (lane & 7);
    const int lcB = ((lane >> 3) & 1) * 8;
    const uint32_t bA = smem_u32(&As[0][0]), bB = smem_u32(&Bs[0][0]);

    float acc[2][4][4] = {};

    for (int k0 = 0; k0 < K; k0 += 32) {
        {
            const float* Ap = &A[(size_t)(m0 + a_row) * K + k0 + a_k0];
            float4 v0 = *(const float4*)(Ap + 0);
            float4 v1 = *(const float4*)(Ap + 4);
            float4 v2 = *(const float4*)(Ap + 8);
            float4 v3 = *(const float4*)(Ap + 12);
            uint4 u0, u1;
            u0.x = pkbf2(v0.x, v0.y); u0.y = pkbf2(v0.z, v0.w);
            u0.z = pkbf2(v1.x, v1.y); u0.w = pkbf2(v1.z, v1.w);
            u1.x = pkbf2(v2.x, v2.y); u1.y = pkbf2(v2.z, v2.w);
            u1.z = pkbf2(v3.x, v3.y); u1.w = pkbf2(v3.z, v3.w);
            *(uint4*)&As[a_row][a_k0 + 0] = u0;
            *(uint4*)&As[a_row][a_k0 + 8] = u1;
        }
        {
            float v[8];
#pragma unroll
            for (int i = 0; i < 8; i++)
                v[i] = B[(size_t)(k0 + b_k0 + i) * N + n0 + b_n];
            uint4 u;
            u.x = pkbf2(v[0], v[1]); u.y = pkbf2(v[2], v[3]);
            u.z = pkbf2(v[4], v[5]); u.w = pkbf2(v[6], v[7]);
            *(uint4*)&Bs[b_n][b_k0] = u;
        }
        __syncthreads();

#pragma unroll
        for (int kk = 0; kk < 32; kk += 16) {
            uint32_t af[2][4], bf[4][2];
#pragma unroll
            for (int im = 0; im < 2; im++) {
                uint32_t off = ((wm + im * 16 + lrA) * 40 + kk + lcA) * 2;
                ldsm4(af[im][0], af[im][1], af[im][2], af[im][3], bA + off);
            }
#pragma unroll
            for (int q = 0; q < 2; q++) {
                uint32_t off = ((wn + q * 16 + lrB) * 40 + kk + lcB) * 2;
                ldsm4(bf[2*q][0], bf[2*q][1], bf[2*q+1][0], bf[2*q+1][1], bB + off);
            }
#pragma unroll
            for (int im = 0; im < 2; im++)
#pragma unroll
                for (int in = 0; in < 4; in++)
                    MMA_BF16(acc[im][in], af[im][0], af[im][1], af[im][2], af[im][3],
                             bf[in][0], bf[in][1]);
        }
        __syncthreads();
    }

#pragma unroll
    for (int im = 0; im < 2; im++)
#pragma unroll
        for (int in = 0; in < 4; in++) {
            int cbase = n0 + wn + in * 8 + 2 * cq;
#pragma unroll
            for (int half = 0; half < 2; half++) {
                int m = m0 + wm + im * 16 + g + half * 8;
#pragma unroll
                for (int jj = 0; jj < 2; jj++) {
                    int n = cbase + jj;
                    float v = acc[im][in][half * 2 + jj];
                    if (EPI == 1) v += bias[n];
                    if (EPI == 2) v = fmaxf(v + bias[n], 0.0f);
                    if (EPI == 3) v = gelu_exact((v + bias[n]) * gam[n] + bet[n]);
                    if (EPI == 4) v = res[(size_t)m * N + n] + (v + bias[n]) * gam[n] + bet[n];
                    C[(size_t)m * N + n] = v;
                }
            }
        }
}

// ---------------- small-M SGEMM for pred head (M=64) ----------------
#define BM 64
#define BNT 64
#define BKT 16
template <int EPI>
__global__ __launch_bounds__(256) void sgemm_kernel(
    const float* __restrict__ A, const float* __restrict__ B, float* __restrict__ C,
    int M, int N, int K,
    const float* __restrict__ bias, const float* __restrict__ gam,
    const float* __restrict__ bet,  const float* __restrict__ res)
{
    __shared__ float As[BKT][BM];
    __shared__ float Bs[BKT][BNT];
    const int tid = threadIdx.x;
    const int tx = tid & 15, ty = tid >> 4;
    const int m0 = blockIdx.y * BM, n0 = blockIdx.x * BNT;
    const int a_m = tid >> 2, a_k = (tid & 3) * 4;
    const int b_k = tid >> 4, b_n = (tid & 15) * 4;

    float acc[4][4] = {};
    for (int k0 = 0; k0 < K; k0 += BKT) {
        float4 av = *(const float4*)&A[(size_t)(m0 + a_m) * K + k0 + a_k];
        As[a_k + 0][a_m] = av.x; As[a_k + 1][a_m] = av.y;
        As[a_k + 2][a_m] = av.z; As[a_k + 3][a_m] = av.w;
        float4 bv = *(const float4*)&B[(size_t)(k0 + b_k) * N + n0 + b_n];
        *(float4*)&Bs[b_k][b_n] = bv;
        __syncthreads();
#pragma unroll
        for (int k = 0; k < BKT; k++) {
            float ar[4], br[4];
#pragma unroll
            for (int i = 0; i < 4; i++) ar[i] = As[k][ty * 4 + i];
#pragma unroll
            for (int j = 0; j < 4; j++) br[j] = Bs[k][tx * 4 + j];
#pragma unroll
            for (int i = 0; i < 4; i++)
#pragma unroll
                for (int j = 0; j < 4; j++) acc[i][j] = fmaf(ar[i], br[j], acc[i][j]);
        }
        __syncthreads();
    }
#pragma unroll
    for (int i = 0; i < 4; i++) {
        int m = m0 + ty * 4 + i;
#pragma unroll
        for (int j = 0; j < 4; j++) {
            int n = n0 + tx * 4 + j;
            float v = acc[i][j];
            if (EPI == 1) v += bias[n];
            if (EPI == 2) v = fmaxf(v + bias[n], 0.0f);
            if (EPI == 3) v = gelu_exact((v + bias[n]) * gam[n] + bet[n]);
            if (EPI == 4) v = res[(size_t)m * N + n] + (v + bias[n]) * gam[n] + bet[n];
            C[(size_t)m * N + n] = v;
        }
    }
}

// ---------------- auxiliary kernels ----------------
__global__ void transpose_w_kernel(const float* __restrict__ w, float* __restrict__ wt) {
    int i = blockIdx.x * blockDim.x + threadIdx.x;
    if (i >= 192 * 768) return;
    int n = i / 768, k = i % 768;
    wt[k * 192 + n] = w[i];
}

__global__ void sq_kernel(const float* __restrict__ nf, float* __restrict__ sq) {
    int node = (blockIdx.x * blockDim.x + threadIdx.x) >> 5;
    int lane = threadIdx.x & 31;
    if (node >= BN) return;
    float s = 0.f;
#pragma unroll
    for (int j = 0; j < 6; j++) {
        float x = nf[(size_t)node * CH + lane + 32 * j];
        s = fmaf(x, x, s);
    }
#pragma unroll
    for (int off = 16; off; off >>= 1) s += __shfl_down_sync(0xffffffffu, s, off);
    if (lane == 0) sq[node] = s;
}

__global__ void topk_kernel(const float* __restrict__ d2, int* __restrict__ idx) {
    int row = (blockIdx.x * blockDim.x + threadIdx.x) >> 5;
    int lane = threadIdx.x & 31;
    if (row >= BN) return;
    const float* r = d2 + (size_t)row * NNODE;
    float v[18];
#pragma unroll
    for (int j = 0; j < 18; j++) v[j] = r[lane + 32 * j];
    int bimg = row / NNODE;
#pragma unroll
    for (int s = 0; s < 5; s++) {
        float bv = 3.4e38f; int bc = 1 << 30;
#pragma unroll
        for (int j = 0; j < 18; j++) {
            int c = lane + 32 * j;
            if (v[j] < bv) { bv = v[j]; bc = c; }
        }
#pragma unroll
        for (int off = 16; off; off >>= 1) {
            float ov = __shfl_down_sync(0xffffffffu, bv, off);
            int   oc = __shfl_down_sync(0xffffffffu, bc, off);
            if (ov < bv || (ov == bv && oc < bc)) { bv = ov; bc = oc; }
        }
        bc = __shfl_sync(0xffffffffu, bc, 0);
        if ((bc & 31) == lane) v[bc >> 5] = 3.4e38f;
        if (lane == 0) idx[row * KNN + s] = bimg * NNODE + bc;
    }
}

__global__ void edge_kernel(const float* __restrict__ P, const float* __restrict__ Q,
                            const int* __restrict__ idx,
                            const float* __restrict__ w2, const float* __restrict__ b2,
                            float* __restrict__ att, float* __restrict__ out)
{
    int node = (blockIdx.x * blockDim.x + threadIdx.x) >> 5;
    int lane = threadIdx.x & 31;
    if (node >= BN) return;
    float q[6], w[6];
#pragma unroll
    for (int j = 0; j < 6; j++) {
        q[j] = Q[(size_t)node * CH + lane + 32 * j];
        w[j] = w2[lane + 32 * j];
    }
    const float b2v = b2[0];
#pragma unroll
    for (int k = 0; k < KNN; k++) {
        int e = node * KNN + k;
        int src = idx[e];
        float s = 0.f;
#pragma unroll
        for (int j = 0; j < 6; j++) {
            float x = P[(size_t)src * CH + lane + 32 * j] + q[j];
            x = fmaxf(x, 0.f);
            s = fmaf(x, w[j], s);
        }
#pragma unroll
        for (int off = 16; off; off >>= 1) s += __shfl_down_sync(0xffffffffu, s, off);
        if (lane == 0) {
            float a = 1.0f / (1.0f + expf(-(s + b2v)));
            att[e] = a;
            out[e] = a;
        }
    }
}

__global__ void agg_kernel(const float* __restrict__ h, const int* __restrict__ idx,
                           const float* __restrict__ att, float* __restrict__ hm)
{
    int i = blockIdx.x;
    int c = threadIdx.x;
    float acc = h[(size_t)i * CH + c];
#pragma unroll
    for (int k = 0; k < KNN; k++) {
        int nb = idx[i * KNN + k];
        float a = att[i * KNN + k];
        acc = fmaf(a, h[(size_t)nb * CH + c], acc);
    }
    hm[(size_t)i * CH + c] = acc;
}

__global__ void pool_kernel(const float* __restrict__ t, float* __restrict__ g) {
    int b = blockIdx.x, c = threadIdx.x;
    float acc = 0.f;
    for (int n = 0; n < NNODE; n++) acc += t[((size_t)b * NNODE + n) * CH + c];
    g[b * CH + c] = acc * (1.0f / NNODE);
}

__global__ void pred_final_kernel(const float* __restrict__ p, const float* __restrict__ w2,
                                  const float* __restrict__ b2, float* __restrict__ out)
{
    int b = blockIdx.x, tid = threadIdx.x;
    float s = 0.f;
    for (int i = tid; i < PHID; i += 256) s = fmaf(p[(size_t)b * PHID + i], w2[i], s);
    __shared__ float red[256];
    red[tid] = s; __syncthreads();
    for (int st = 128; st; st >>= 1) { if (tid < st) red[tid] += red[tid + st]; __syncthreads(); }
    if (tid == 0) out[b] = red[0] + b2[0];
}

// ---------------- host launch ----------------
extern "C" void kernel_launch(void* const* d_in, const int* in_sizes, int n_in,
                              void* d_out, int out_size)
{
    const float* x        = (const float*)d_in[0];
    const float* stem_w   = (const float*)d_in[1];
    const float* stem_b   = (const float*)d_in[2];
    const float* pos      = (const float*)d_in[3];
    const float* att_w1   = (const float*)d_in[4];
    const float* att_b1   = (const float*)d_in[5];
    const float* att_w2   = (const float*)d_in[6];
    const float* att_b2   = (const float*)d_in[7];
    const float* gnn_w1   = (const float*)d_in[8];
    const float* gnn_b1   = (const float*)d_in[9];
    const float* gnn_w2   = (const float*)d_in[10];
    const float* gnn_b2   = (const float*)d_in[11];
    const float* ffn_w1   = (const float*)d_in[12];
    const float* ffn_b1   = (const float*)d_in[13];
    const float* ffn_g1   = (const float*)d_in[14];
    const float* ffn_be1  = (const float*)d_in[15];
    const float* ffn_w2   = (const float*)d_in[16];
    const float* ffn_b2   = (const float*)d_in[17];
    const float* ffn_g2   = (const float*)d_in[18];
    const float* ffn_be2  = (const float*)d_in[19];
    const float* pred_w1  = (const float*)d_in[20];
    const float* pred_b1  = (const float*)d_in[21];
    const float* pred_g   = (const float*)d_in[22];
    const float* pred_be  = (const float*)d_in[23];
    const float* pred_w2  = (const float*)d_in[24];
    const float* pred_b2  = (const float*)d_in[25];
    float* out = (float*)d_out;

    float *p_wt, *p_nf, *p_sq, *p_d2, *p_P, *p_Q, *p_att, *p_h, *p_hm, *p_u, *p_t, *p_g, *p_p;
    uint32_t *p_nfh;
    int* p_idx;
    cudaGetSymbolAddress((void**)&p_wt,  g_wt);
    cudaGetSymbolAddress((void**)&p_nf,  g_nf);
    cudaGetSymbolAddress((void**)&p_nfh, g_nfh);
    cudaGetSymbolAddress((void**)&p_sq,  g_sq);
    cudaGetSymbolAddress((void**)&p_d2,  g_d2);
    cudaGetSymbolAddress((void**)&p_idx, g_idx);
    cudaGetSymbolAddress((void**)&p_P,   g_P);
    cudaGetSymbolAddress((void**)&p_Q,   g_Q);
    cudaGetSymbolAddress((void**)&p_att, g_att);
    cudaGetSymbolAddress((void**)&p_h,   g_h);
    cudaGetSymbolAddress((void**)&p_hm,  g_hm);
    cudaGetSymbolAddress((void**)&p_u,   g_u);
    cudaGetSymbolAddress((void**)&p_t,   g_t);
    cudaGetSymbolAddress((void**)&p_g,   g_g);
    cudaGetSymbolAddress((void**)&p_p,   g_p);

    cudaFuncSetAttribute(gram_x3_sym_kernel,
                         cudaFuncAttributeMaxDynamicSharedMemorySize, 20480);
    cudaFuncSetAttribute(stem_x3_kernel,
                         cudaFuncAttributeMaxDynamicSharedMemorySize, 30720);

    transpose_w_kernel<<<(192 * 768 + 255) / 256, 256>>>(stem_w, p_wt);

    // ---- graph path (raw-stage pipelined; bit-identical numerics) ----
    stem_x3_kernel<<<dim3(CH / 64, BN / 128), 256, 30720>>>(
        x, p_wt, p_nf, p_nfh, stem_b, pos);
    sq_kernel<<<(BN * 32 + 255) / 256, 256>>>(p_nf, p_sq);
    gram_x3_sym_kernel<<<dim3(45, 1, Bsz), 128, 20480>>>(p_nf, p_sq, p_d2);
    topk_kernel<<<(BN * 32 + 255) / 256, 256>>>(p_d2, p_idx);

    // ---- edge attention (tf32) ----
    tf32gemm_kernel<0,1><<<dim3(CH / 64, BN / 128), 256>>>(p_nfh, att_w1, p_P, BN, CH, CH,
                                                           nullptr, nullptr, nullptr, nullptr);
    tf32gemm_kernel<1,1><<<dim3(CH / 64, BN / 128), 256>>>(p_nfh, att_w1 + 192 * 192, p_Q,
                                                           BN, CH, CH,
                                                           att_b1, nullptr, nullptr, nullptr);
    edge_kernel<<<(BN * 32 + 255) / 256, 256>>>(p_P, p_Q, p_idx, att_w2, att_b2, p_att, out);

    // ---- prediction path (bf16) ----
    agg_kernel<<<BN, CH>>>(p_nf, p_idx, p_att, p_hm);
    bf16gemm_kernel<2><<<dim3(CH / 64, BN / 128), 256>>>(p_hm, gnn_w1, p_h, BN, CH, CH,
                                                         gnn_b1, nullptr, nullptr, nullptr);
    agg_kernel<<<BN, CH>>>(p_h, p_idx, p_att, p_hm);
    bf16gemm_kernel<2><<<dim3(CH / 64, BN / 128), 256>>>(p_hm, gnn_w2, p_h, BN, CH, CH,
                                                         gnn_b2, nullptr, nullptr, nullptr);
    bf16gemm_kernel<3><<<dim3(HID / 64, BN / 128), 256>>>(p_h, ffn_w1, p_u, BN, HID, CH,
                                                          ffn_b1, ffn_g1, ffn_be1, nullptr);
    bf16gemm_kernel<4><<<dim3(CH / 64, BN / 128), 256>>>(p_u, ffn_w2, p_t, BN, CH, HID,
                                                         ffn_b2, ffn_g2, ffn_be2, p_h);

    pool_kernel<<<Bsz, CH>>>(p_t, p_g);
    sgemm_kernel<3><<<dim3(PHID / BNT, Bsz / BM), 256>>>(p_g, pred_w1, p_p, Bsz, PHID, CH,
                                                         pred_b1, pred_g, pred_be, nullptr);
    pred_final_kernel<<<Bsz, 256>>>(p_p, pred_w2, pred_b2, out + EDG);
}

// round 16
// speedup vs baseline: 1.2490x; 1.0043x over previous
#include <cuda_runtime.h>
#include <cuda_bf16.h>
#include <math.h>
#include <stdint.h>

// ---------------- problem constants ----------------
#define Bsz   64
#define IMGSZ 384
#define PATCH 16
#define CH    192
#define KNN   5
#define HGRID 24
#define NNODE 576
#define BN    (Bsz * NNODE)  // 36864
#define EDG   (BN * KNN)     // 184320
#define HID   768
#define PHID  1024

// ---------------- scratch ----------------
__device__ float    g_wt  [768 * 192];
__device__ float    g_nf  [(size_t)BN * CH];
__device__ uint32_t g_nfh [(size_t)BN * CH];
__device__ float    g_sq  [BN];
__device__ float    g_d2  [(size_t)Bsz * NNODE * NNODE];
__device__ int      g_idx [BN * KNN];
__device__ float    g_P   [(size_t)BN * CH];
__device__ float    g_Q   [(size_t)BN * CH];
__device__ float    g_att [EDG];
__device__ float    g_h   [(size_t)BN * CH];
__device__ float    g_hm  [(size_t)BN * CH];
__device__ float    g_u   [(size_t)BN * HID];
__device__ float    g_t   [(size_t)BN * CH];
__device__ float    g_g   [Bsz * CH];
__device__ float    g_p   [Bsz * PHID];

__device__ __forceinline__ float gelu_exact(float v) {
    return 0.5f * v * (1.0f + erff(v * 0.70710678118654752f));
}
__device__ __forceinline__ uint32_t f2tf32(float x) {
    uint32_t r; asm("cvt.rna.tf32.f32 %0, %1;" : "=r"(r) : "f"(x)); return r;
}
__device__ __forceinline__ void split_tf32(float x, uint32_t& hi, uint32_t& lo) {
    hi = f2tf32(x);
    lo = f2tf32(x - __uint_as_float(hi));
}
__device__ __forceinline__ void split4(const uint32_t* r, uint32_t* h, uint32_t* l) {
#pragma unroll
    for (int i = 0; i < 4; i++) {
        float v = __uint_as_float(r[i]);
        split_tf32(v, h[i], l[i]);
    }
}
__device__ __forceinline__ void split2(const uint32_t* r, uint32_t* h, uint32_t* l) {
#pragma unroll
    for (int i = 0; i < 2; i++) {
        float v = __uint_as_float(r[i]);
        split_tf32(v, h[i], l[i]);
    }
}
__device__ __forceinline__ uint32_t smem_u32(const void* p) {
    return (uint32_t)__cvta_generic_to_shared(p);
}
__device__ __forceinline__ void ldsm4(uint32_t& r0, uint32_t& r1, uint32_t& r2,
                                      uint32_t& r3, uint32_t a) {
    asm volatile("ldmatrix.sync.aligned.m8n8.x4.shared.b16 {%0,%1,%2,%3}, [%4];"
                 : "=r"(r0), "=r"(r1), "=r"(r2), "=r"(r3) : "r"(a));
}
__device__ __forceinline__ uint32_t pkbf2(float a, float b) {
    __nv_bfloat162 t = __floats2bfloat162_rn(a, b);
    return *(uint32_t*)&t;
}
__device__ __forceinline__ void cp16(uint32_t dst, const void* src) {
    asm volatile("cp.async.cg.shared.global [%0], [%1], 16;" :: "r"(dst), "l"(src));
}
__device__ __forceinline__ void cp4(uint32_t dst, const void* src) {
    asm volatile("cp.async.ca.shared.global [%0], [%1], 4;" :: "r"(dst), "l"(src));
}
__device__ __forceinline__ void cp_commit() { asm volatile("cp.async.commit_group;"); }
__device__ __forceinline__ void cp_wait2()  { asm volatile("cp.async.wait_group 2;"); }
__device__ __forceinline__ void cp_wait1()  { asm volatile("cp.async.wait_group 1;"); }
__device__ __forceinline__ void cp_wait0()  { asm volatile("cp.async.wait_group 0;"); }

#define MMA_TF32(acc, a0, a1, a2, a3, b0, b1)                                \
    asm volatile(                                                            \
        "mma.sync.aligned.m16n8k8.row.col.f32.tf32.tf32.f32 "               \
        "{%0,%1,%2,%3}, {%4,%5,%6,%7}, {%8,%9}, {%0,%1,%2,%3};"             \
        : "+f"(acc[0]), "+f"(acc[1]), "+f"(acc[2]), "+f"(acc[3])             \
        : "r"(a0), "r"(a1), "r"(a2), "r"(a3), "r"(b0), "r"(b1))
#define MMA_BF16(acc, a0, a1, a2, a3, b0, b1)                                \
    asm volatile(                                                            \
        "mma.sync.aligned.m16n8k16.row.col.f32.bf16.bf16.f32 "              \
        "{%0,%1,%2,%3}, {%4,%5,%6,%7}, {%8,%9}, {%0,%1,%2,%3};"             \
        : "+f"(acc[0]), "+f"(acc[1]), "+f"(acc[2]), "+f"(acc[3])             \
        : "r"(a0), "r"(a1), "r"(a2), "r"(a3), "r"(b0), "r"(b1))

#define LDSM_OFFS()                                                          \
    const int lrA = lane & 15;                                               \
    const int lcA = (lane >> 4) * 4;                                         \
    const int lrB = ((lane >> 4) << 3) + (lane & 7);                         \
    const int lcB = ((lane >> 3) & 1) * 4

// tf32x3 MMA chain on raw fragments (split in regs)
__device__ __forceinline__ void mma_x3_frag(
    float acc[2][4][4], const uint32_t ar[2][4], const uint32_t br[4][2])
{
    uint32_t ah[2][4], al[2][4], bh[4][2], bl[4][2];
#pragma unroll
    for (int im = 0; im < 2; im++) split4(ar[im], ah[im], al[im]);
#pragma unroll
    for (int in = 0; in < 4; in++) split2(br[in], bh[in], bl[in]);
#pragma unroll
    for (int im = 0; im < 2; im++)
#pragma unroll
        for (int in = 0; in < 4; in++) {
            MMA_TF32(acc[im][in], ah[im][0], ah[im][1], ah[im][2], ah[im][3],
                     bh[in][0], bh[in][1]);
            MMA_TF32(acc[im][in], ah[im][0], ah[im][1], ah[im][2], ah[im][3],
                     bl[in][0], bl[in][1]);
            MMA_TF32(acc[im][in], al[im][0], al[im][1], al[im][2], al[im][3],
                     bh[in][0], bh[in][1]);
        }
}

// =================================================================
// gram: raw-stage tf32x3 + symmetry + 3-stage cp.async, slab 16.
// Stage 10240 B; 3 stages = 30720 B dynamic. Numerics unchanged.
// =================================================================
__global__ __launch_bounds__(128) void gram_x3_sym_kernel(
    const float* __restrict__ nf, const float* __restrict__ sq, float* __restrict__ d2)
{
    extern __shared__ uint32_t DSM[];
    const int b = blockIdx.z;
    const float* Ab = nf + (size_t)b * NNODE * CH;

    int p = blockIdx.x, ti = 0;
    while (p >= 9 - ti) { p -= 9 - ti; ti++; }
    const int tj = ti + p;
    const int r0b = ti * 64, c0b = tj * 64;

    const int tid  = threadIdx.x;
    const int lane = tid & 31, wid = tid >> 5;
    const int wm = (wid >> 1) * 32, wn = (wid & 1) * 32;
    const int row = tid >> 1, kq = (tid & 1) * 8;
    const int g = lane >> 2, cq = lane & 3;
    LDSM_OFFS();
    const uint32_t base = smem_u32(DSM);

    auto fill = [&](int k0, int st) {
        uint32_t sb = base + (uint32_t)st * 10240u;
        const float* ra = Ab + (size_t)(r0b + row) * CH + k0 + kq;
        const float* rb = Ab + (size_t)(c0b + row) * CH + k0 + kq;
#pragma unroll
        for (int i = 0; i < 2; i++) {
            uint32_t off = (uint32_t)(row * 20 + kq + i * 4) * 4;
            cp16(sb + off,        ra + i * 4);
            cp16(sb + 5120 + off, rb + i * 4);
        }
        cp_commit();
    };

    float acc[2][4][4] = {};

    const int NS = CH / 16;   // 12
    fill(0, 0);
    fill(16, 1);
    for (int s = 0; s < NS; s++) {
        if (s + 2 < NS) fill((s + 2) * 16, (s + 2) % 3);
        if (s + 2 < NS) cp_wait2();
        else if (s + 1 < NS) cp_wait1();
        else cp_wait0();
        __syncthreads();

        uint32_t sb = base + (uint32_t)(s % 3) * 10240u;
        const uint32_t bA = sb, bB = sb + 5120;
#pragma unroll
        for (int kk = 0; kk < 16; kk += 8) {
            uint32_t ar[2][4], br[4][2];
#pragma unroll
            for (int im = 0; im < 2; im++) {
                uint32_t off = ((wm + im * 16 + lrA) * 20 + kk + lcA) * 4;
                ldsm4(ar[im][0], ar[im][1], ar[im][2], ar[im][3], bA + off);
            }
#pragma unroll
            for (int q = 0; q < 2; q++) {
                uint32_t off = ((wn + q * 16 + lrB) * 20 + kk + lcB) * 4;
                ldsm4(br[2*q][0], br[2*q][1], br[2*q+1][0], br[2*q+1][1], bB + off);
            }
            mma_x3_frag(acc, ar, br);
        }
        __syncthreads();
    }

#pragma unroll
    for (int im = 0; im < 2; im++)
#pragma unroll
        for (int in = 0; in < 4; in++) {
            int cbase = c0b + wn + in * 8 + 2 * cq;
#pragma unroll
            for (int half = 0; half < 2; half++) {
                int r = r0b + wm + im * 16 + g + half * 8;
#pragma unroll
                for (int jj = 0; jj < 2; jj++) {
                    int c = cbase + jj;
                    float v = sq[b * NNODE + c] - 2.0f * acc[im][in][half * 2 + jj];
                    if (r == c) v = 3.0e38f;
                    d2[((size_t)b * NNODE + r) * NNODE + c] = v;
                }
            }
        }

    if (ti != tj) {
        float* T = (float*)DSM;   // 64x68 floats = 17408 B <= 30720
#pragma unroll
        for (int im = 0; im < 2; im++)
#pragma unroll
            for (int in = 0; in < 4; in++) {
                int cl = wn + in * 8 + 2 * cq;
#pragma unroll
                for (int half = 0; half < 2; half++) {
                    int rl = wm + im * 16 + g + half * 8;
                    T[(cl    ) * 68 + rl] = acc[im][in][half * 2 + 0];
                    T[(cl + 1) * 68 + rl] = acc[im][in][half * 2 + 1];
                }
            }
        __syncthreads();
        for (int i = tid; i < 64 * 16; i += 128) {
            int cl = i >> 4;
            int r4 = (i & 15) * 4;
            float4 dv = *(const float4*)&T[cl * 68 + r4];
            float4 sv = *(const float4*)&sq[b * NNODE + r0b + r4];
            float4 o;
            o.x = sv.x - 2.0f * dv.x;
            o.y = sv.y - 2.0f * dv.y;
            o.z = sv.z - 2.0f * dv.z;
            o.w = sv.w - 2.0f * dv.w;
            *(float4*)&d2[((size_t)b * NNODE + c0b + cl) * NNODE + r0b + r4] = o;
        }
    }
}

// =================================================================
// stem: raw-stage tf32x3 + cp.async pipeline, slab 16 (R15 WIN).
// =================================================================
__global__ __launch_bounds__(256) void stem_x3_kernel(
    const float* __restrict__ X, const float* __restrict__ Bw, float* __restrict__ C,
    uint32_t* __restrict__ Ch,
    const float* __restrict__ bias, const float* __restrict__ pos)
{
    extern __shared__ uint32_t DSM[];
    const int Nd = 192, Kd = 768;
    const int tid  = threadIdx.x;
    const int lane = tid & 31, wid = tid >> 5;
    const int wm = (wid >> 1) * 32, wn = (wid & 1) * 32;
    const int m0 = blockIdx.y * 128, n0 = blockIdx.x * 64;
    const int a_row = tid >> 1, kq = (tid & 1) * 8;
    const int b_n = tid & 63, b_k0 = (tid >> 6) * 4;
    const int g = lane >> 2, cq = lane & 3;
    LDSM_OFFS();
    const uint32_t base = smem_u32(DSM);

    const int m = m0 + a_row;
    const int bimg = m / NNODE;
    const int nsp = m % NNODE;
    const int py = nsp / HGRID, px = nsp % HGRID;
    const float* xbase = X + (size_t)bimg * 3 * IMGSZ * IMGSZ
                           + (size_t)(py * PATCH) * IMGSZ + px * PATCH;

    auto fill = [&](int k0, int st) {
        uint32_t sb = base + (uint32_t)st * 15360u;
        int kg = k0 + kq;
        int ci = kg >> 8, ky = (kg >> 4) & 15, kx = kg & 15;
        const float* xr = xbase + (size_t)ci * IMGSZ * IMGSZ + ky * IMGSZ + kx;
#pragma unroll
        for (int i = 0; i < 2; i++) {
            uint32_t off = (uint32_t)(a_row * 20 + kq + i * 4) * 4;
            cp16(sb + off, xr + i * 4);
        }
#pragma unroll
        for (int i = 0; i < 4; i++) {
            uint32_t off = (uint32_t)(b_n * 20 + b_k0 + i) * 4;
            cp4(sb + 10240 + off, Bw + (size_t)(k0 + b_k0 + i) * Nd + n0 + b_n);
        }
        cp_commit();
    };

    float acc[2][4][4] = {};

    const int NS = Kd / 16;   // 48
    fill(0, 0);
    for (int s = 0; s < NS; s++) {
        if (s + 1 < NS) fill((s + 1) * 16, (s + 1) & 1);
        if (s + 1 < NS) cp_wait1(); else cp_wait0();
        __syncthreads();

        uint32_t sb = base + (uint32_t)(s & 1) * 15360u;
        const uint32_t bA = sb, bB = sb + 10240;
#pragma unroll
        for (int kk = 0; kk < 16; kk += 8) {
            uint32_t ar[2][4], br[4][2];
#pragma unroll
            for (int im = 0; im < 2; im++) {
                uint32_t off = ((wm + im * 16 + lrA) * 20 + kk + lcA) * 4;
                ldsm4(ar[im][0], ar[im][1], ar[im][2], ar[im][3], bA + off);
            }
#pragma unroll
            for (int q = 0; q < 2; q++) {
                uint32_t off = ((wn + q * 16 + lrB) * 20 + kk + lcB) * 4;
                ldsm4(br[2*q][0], br[2*q][1], br[2*q+1][0], br[2*q+1][1], bB + off);
            }
            mma_x3_frag(acc, ar, br);
        }
        __syncthreads();
    }

#pragma unroll
    for (int im = 0; im < 2; im++)
#pragma unroll
        for (int in = 0; in < 4; in++) {
            int cbase = n0 + wn + in * 8 + 2 * cq;
#pragma unroll
            for (int half = 0; half < 2; half++) {
                int mm = m0 + wm + im * 16 + g + half * 8;
                int sp = mm % NNODE;
#pragma unroll
                for (int jj = 0; jj < 2; jj++) {
                    int n = cbase + jj;
                    float v = acc[im][in][half * 2 + jj] + bias[n] + pos[n * NNODE + sp];
                    C[(size_t)mm * CH + n] = v;
                    Ch[(size_t)mm * CH + n] = f2tf32(v);
                }
            }
        }
}

// =================================================================
// P/Q tf32 GEMM: cp.async pipelined, slab 16. A = pre-converted
// tf32 hi (pure copy); B staged raw, f2tf32 in regs after ldmatrix
// -> P/Q bit-identical to R15.
// Stage = A 128x20 (10240B) + B 64x20 (5120B) = 15360 B; x2 stages.
// =================================================================
template <int EPI>
__global__ __launch_bounds__(256) void tf32gemm_pipe_kernel(
    const uint32_t* __restrict__ Ai, const float* __restrict__ B, float* __restrict__ C,
    int M, int N, int K,
    const float* __restrict__ bias)
{
    extern __shared__ uint32_t DSM[];
    const int tid  = threadIdx.x;
    const int lane = tid & 31, wid = tid >> 5;
    const int wm = (wid >> 1) * 32, wn = (wid & 1) * 32;
    const int m0 = blockIdx.y * 128, n0 = blockIdx.x * 64;
    const int a_row = tid >> 1, kq = (tid & 1) * 8;
    const int b_n = tid & 63, b_k0 = (tid >> 6) * 4;
    const int g = lane >> 2, cq = lane & 3;
    LDSM_OFFS();
    const uint32_t base = smem_u32(DSM);

    auto fill = [&](int k0, int st) {
        uint32_t sb = base + (uint32_t)st * 15360u;
        const uint32_t* ra = Ai + (size_t)(m0 + a_row) * K + k0 + kq;
#pragma unroll
        for (int i = 0; i < 2; i++) {
            uint32_t off = (uint32_t)(a_row * 20 + kq + i * 4) * 4;
            cp16(sb + off, ra + i * 4);
        }
#pragma unroll
        for (int i = 0; i < 4; i++) {
            uint32_t off = (uint32_t)(b_n * 20 + b_k0 + i) * 4;
            cp4(sb + 10240 + off, B + (size_t)(k0 + b_k0 + i) * N + n0 + b_n);
        }
        cp_commit();
    };

    float acc[2][4][4] = {};

    const int NS = K / 16;
    fill(0, 0);
    for (int s = 0; s < NS; s++) {
        if (s + 1 < NS) fill((s + 1) * 16, (s + 1) & 1);
        if (s + 1 < NS) cp_wait1(); else cp_wait0();
        __syncthreads();

        uint32_t sb = base + (uint32_t)(s & 1) * 15360u;
        const uint32_t bA = sb, bB = sb + 10240;
#pragma unroll
        for (int kk = 0; kk < 16; kk += 8) {
            uint32_t af[2][4], br[4][2], bf[4][2];
#pragma unroll
            for (int im = 0; im < 2; im++) {
                uint32_t off = ((wm + im * 16 + lrA) * 20 + kk + lcA) * 4;
                ldsm4(af[im][0], af[im][1], af[im][2], af[im][3], bA + off);
            }
#pragma unroll
            for (int q = 0; q < 2; q++) {
                uint32_t off = ((wn + q * 16 + lrB) * 20 + kk + lcB) * 4;
                ldsm4(br[2*q][0], br[2*q][1], br[2*q+1][0], br[2*q+1][1], bB + off);
            }
#pragma unroll
            for (int in = 0; in < 4; in++) {
                bf[in][0] = f2tf32(__uint_as_float(br[in][0]));
                bf[in][1] = f2tf32(__uint_as_float(br[in][1]));
            }
#pragma unroll
            for (int im = 0; im < 2; im++)
#pragma unroll
                for (int in = 0; in < 4; in++)
                    MMA_TF32(acc[im][in], af[im][0], af[im][1], af[im][2], af[im][3],
                             bf[in][0], bf[in][1]);
        }
        __syncthreads();
    }

#pragma unroll
    for (int im = 0; im < 2; im++)
#pragma unroll
        for (int in = 0; in < 4; in++) {
            int cbase = n0 + wn + in * 8 + 2 * cq;
#pragma unroll
            for (int half = 0; half < 2; half++) {
                int m = m0 + wm + im * 16 + g + half * 8;
#pragma unroll
                for (int jj = 0; jj < 2; jj++) {
                    int n = cbase + jj;
                    float v = acc[im][in][half * 2 + jj];
                    if (EPI == 1) v += bias[n];
                    C[(size_t)m * N + n] = v;
                }
            }
        }
}

// =================================================================
// bf16 GEMM (prediction path; unchanged)
// =================================================================
template <int EPI>
__global__ __launch_bounds__(256) void bf16gemm_kernel(
    const float* __restrict__ A, const float* __restrict__ B, float* __restrict__ C,
    int M, int N, int K,
    const float* __restrict__ bias, const float* __restrict__ gam,
    const float* __restrict__ bet,  const float* __restrict__ res)
{
    __shared__ __nv_bfloat16 As[128][40];
    __shared__ __nv_bfloat16 Bs[64][40];
    const int tid  = threadIdx.x;
    const int lane = tid & 31, wid = tid >> 5;
    const int wm = (wid >> 1) * 32;
    const int wn = (wid & 1) * 32;
    const int m0 = blockIdx.y * 128, n0 = blockIdx.x * 64;
    const int a_row = tid >> 1, a_k0 = (tid & 1) * 16;
    const int b_n = tid & 63, b_k0 = (tid >> 6) * 8;
    const int g = lane >> 2, cq = lane & 3;
    const int lrA = lane & 15;
    const int lcA = (lane >> 4) * 8;
    const int lrB = ((lane >> 4) << 3) + (lane & 7);
    const int lcB = ((lane >> 3) & 1) * 8;
    const uint32_t bA = smem_u32(&As[0][0]), bB = smem_u32(&Bs[0][0]);

    float acc[2][4][4] = {};

    for (int k0 = 0; k0 < K; k0 += 32) {
        {
            const float* Ap = &A[(size_t)(m0 + a_row) * K + k0 + a_k0];
            float4 v0 = *(const float4*)(Ap + 0);
            float4 v1 = *(const float4*)(Ap + 4);
            float4 v2 = *(const float4*)(Ap + 8);
            float4 v3 = *(const float4*)(Ap + 12);
            uint4 u0, u1;
            u0.x = pkbf2(v0.x, v0.y); u0.y = pkbf2(v0.z, v0.w);
            u0.z = pkbf2(v1.x, v1.y); u0.w = pkbf2(v1.z, v1.w);
            u1.x = pkbf2(v2.x, v2.y); u1.y = pkbf2(v2.z, v2.w);
            u1.z = pkbf2(v3.x, v3.y); u1.w = pkbf2(v3.z, v3.w);
            *(uint4*)&As[a_row][a_k0 + 0] = u0;
            *(uint4*)&As[a_row][a_k0 + 8] = u1;
        }
        {
            float v[8];
#pragma unroll
            for (int i = 0; i < 8; i++)
                v[i] = B[(size_t)(k0 + b_k0 + i) * N + n0 + b_n];
            uint4 u;
            u.x = pkbf2(v[0], v[1]); u.y = pkbf2(v[2], v[3]);
            u.z = pkbf2(v[4], v[5]); u.w = pkbf2(v[6], v[7]);
            *(uint4*)&Bs[b_n][b_k0] = u;
        }
        __syncthreads();

#pragma unroll
        for (int kk = 0; kk < 32; kk += 16) {
            uint32_t af[2][4], bf[4][2];
#pragma unroll
            for (int im = 0; im < 2; im++) {
                uint32_t off = ((wm + im * 16 + lrA) * 40 + kk + lcA) * 2;
                ldsm4(af[im][0], af[im][1], af[im][2], af[im][3], bA + off);
            }
#pragma unroll
            for (int q = 0; q < 2; q++) {
                uint32_t off = ((wn + q * 16 + lrB) * 40 + kk + lcB) * 2;
                ldsm4(bf[2*q][0], bf[2*q][1], bf[2*q+1][0], bf[2*q+1][1], bB + off);
            }
#pragma unroll
            for (int im = 0; im < 2; im++)
#pragma unroll
                for (int in = 0; in < 4; in++)
                    MMA_BF16(acc[im][in], af[im][0], af[im][1], af[im][2], af[im][3],
                             bf[in][0], bf[in][1]);
        }
        __syncthreads();
    }

#pragma unroll
    for (int im = 0; im < 2; im++)
#pragma unroll
        for (int in = 0; in < 4; in++) {
            int cbase = n0 + wn + in * 8 + 2 * cq;
#pragma unroll
            for (int half = 0; half < 2; half++) {
                int m = m0 + wm + im * 16 + g + half * 8;
#pragma unroll
                for (int jj = 0; jj < 2; jj++) {
                    int n = cbase + jj;
                    float v = acc[im][in][half * 2 + jj];
                    if (EPI == 1) v += bias[n];
                    if (EPI == 2) v = fmaxf(v + bias[n], 0.0f);
                    if (EPI == 3) v = gelu_exact((v + bias[n]) * gam[n] + bet[n]);
                    if (EPI == 4) v = res[(size_t)m * N + n] + (v + bias[n]) * gam[n] + bet[n];
                    C[(size_t)m * N + n] = v;
                }
            }
        }
}

// ---------------- small-M SGEMM for pred head (M=64) ----------------
#define BM 64
#define BNT 64
#define BKT 16
template <int EPI>
__global__ __launch_bounds__(256) void sgemm_kernel(
    const float* __restrict__ A, const float* __restrict__ B, float* __restrict__ C,
    int M, int N, int K,
    const float* __restrict__ bias, const float* __restrict__ gam,
    const float* __restrict__ bet,  const float* __restrict__ res)
{
    __shared__ float As[BKT][BM];
    __shared__ float Bs[BKT][BNT];
    const int tid = threadIdx.x;
    const int tx = tid & 15, ty = tid >> 4;
    const int m0 = blockIdx.y * BM, n0 = blockIdx.x * BNT;
    const int a_m = tid >> 2, a_k = (tid & 3) * 4;
    const int b_k = tid >> 4, b_n = (tid & 15) * 4;

    float acc[4][4] = {};
    for (int k0 = 0; k0 < K; k0 += BKT) {
        float4 av = *(const float4*)&A[(size_t)(m0 + a_m) * K + k0 + a_k];
        As[a_k + 0][a_m] = av.x; As[a_k + 1][a_m] = av.y;
        As[a_k + 2][a_m] = av.z; As[a_k + 3][a_m] = av.w;
        float4 bv = *(const float4*)&B[(size_t)(k0 + b_k) * N + n0 + b_n];
        *(float4*)&Bs[b_k][b_n] = bv;
        __syncthreads();
#pragma unroll
        for (int k = 0; k < BKT; k++) {
            float ar[4], br[4];
#pragma unroll
            for (int i = 0; i < 4; i++) ar[i] = As[k][ty * 4 + i];
#pragma unroll
            for (int j = 0; j < 4; j++) br[j] = Bs[k][tx * 4 + j];
#pragma unroll
            for (int i = 0; i < 4; i++)
#pragma unroll
                for (int j = 0; j < 4; j++) acc[i][j] = fmaf(ar[i], br[j], acc[i][j]);
        }
        __syncthreads();
    }
#pragma unroll
    for (int i = 0; i < 4; i++) {
        int m = m0 + ty * 4 + i;
#pragma unroll
        for (int j = 0; j < 4; j++) {
            int n = n0 + tx * 4 + j;
            float v = acc[i][j];
            if (EPI == 1) v += bias[n];
            if (EPI == 2) v = fmaxf(v + bias[n], 0.0f);
            if (EPI == 3) v = gelu_exact((v + bias[n]) * gam[n] + bet[n]);
            if (EPI == 4) v = res[(size_t)m * N + n] + (v + bias[n]) * gam[n] + bet[n];
            C[(size_t)m * N + n] = v;
        }
    }
}

// ---------------- auxiliary kernels ----------------
__global__ void transpose_w_kernel(const float* __restrict__ w, float* __restrict__ wt) {
    int i = blockIdx.x * blockDim.x + threadIdx.x;
    if (i >= 192 * 768) return;
    int n = i / 768, k = i % 768;
    wt[k * 192 + n] = w[i];
}

__global__ void sq_kernel(const float* __restrict__ nf, float* __restrict__ sq) {
    int node = (blockIdx.x * blockDim.x + threadIdx.x) >> 5;
    int lane = threadIdx.x & 31;
    if (node >= BN) return;
    float s = 0.f;
#pragma unroll
    for (int j = 0; j < 6; j++) {
        float x = nf[(size_t)node * CH + lane + 32 * j];
        s = fmaf(x, x, s);
    }
#pragma unroll
    for (int off = 16; off; off >>= 1) s += __shfl_down_sync(0xffffffffu, s, off);
    if (lane == 0) sq[node] = s;
}

__global__ void topk_kernel(const float* __restrict__ d2, int* __restrict__ idx) {
    int row = (blockIdx.x * blockDim.x + threadIdx.x) >> 5;
    int lane = threadIdx.x & 31;
    if (row >= BN) return;
    const float* r = d2 + (size_t)row * NNODE;
    float v[18];
#pragma unroll
    for (int j = 0; j < 18; j++) v[j] = r[lane + 32 * j];
    int bimg = row / NNODE;
#pragma unroll
    for (int s = 0; s < 5; s++) {
        float bv = 3.4e38f; int bc = 1 << 30;
#pragma unroll
        for (int j = 0; j < 18; j++) {
            int c = lane + 32 * j;
            if (v[j] < bv) { bv = v[j]; bc = c; }
        }
#pragma unroll
        for (int off = 16; off; off >>= 1) {
            float ov = __shfl_down_sync(0xffffffffu, bv, off);
            int   oc = __shfl_down_sync(0xffffffffu, bc, off);
            if (ov < bv || (ov == bv && oc < bc)) { bv = ov; bc = oc; }
        }
        bc = __shfl_sync(0xffffffffu, bc, 0);
        if ((bc & 31) == lane) v[bc >> 5] = 3.4e38f;
        if (lane == 0) idx[row * KNN + s] = bimg * NNODE + bc;
    }
}

__global__ void edge_kernel(const float* __restrict__ P, const float* __restrict__ Q,
                            const int* __restrict__ idx,
                            const float* __restrict__ w2, const float* __restrict__ b2,
                            float* __restrict__ att, float* __restrict__ out)
{
    int node = (blockIdx.x * blockDim.x + threadIdx.x) >> 5;
    int lane = threadIdx.x & 31;
    if (node >= BN) return;
    float q[6], w[6];
#pragma unroll
    for (int j = 0; j < 6; j++) {
        q[j] = Q[(size_t)node * CH + lane + 32 * j];
        w[j] = w2[lane + 32 * j];
    }
    const float b2v = b2[0];
#pragma unroll
    for (int k = 0; k < KNN; k++) {
        int e = node * KNN + k;
        int src = idx[e];
        float s = 0.f;
#pragma unroll
        for (int j = 0; j < 6; j++) {
            float x = P[(size_t)src * CH + lane + 32 * j] + q[j];
            x = fmaxf(x, 0.f);
            s = fmaf(x, w[j], s);
        }
#pragma unroll
        for (int off = 16; off; off >>= 1) s += __shfl_down_sync(0xffffffffu, s, off);
        if (lane == 0) {
            float a = 1.0f / (1.0f + expf(-(s + b2v)));
            att[e] = a;
            out[e] = a;
        }
    }
}

__global__ void agg_kernel(const float* __restrict__ h, const int* __restrict__ idx,
                           const float* __restrict__ att, float* __restrict__ hm)
{
    int i = blockIdx.x;
    int c = threadIdx.x;
    float acc = h[(size_t)i * CH + c];
#pragma unroll
    for (int k = 0; k < KNN; k++) {
        int nb = idx[i * KNN + k];
        float a = att[i * KNN + k];
        acc = fmaf(a, h[(size_t)nb * CH + c], acc);
    }
    hm[(size_t)i * CH + c] = acc;
}

__global__ void pool_kernel(const float* __restrict__ t, float* __restrict__ g) {
    int b = blockIdx.x, c = threadIdx.x;
    float acc = 0.f;
    for (int n = 0; n < NNODE; n++) acc += t[((size_t)b * NNODE + n) * CH + c];
    g[b * CH + c] = acc * (1.0f / NNODE);
}

__global__ void pred_final_kernel(const float* __restrict__ p, const float* __restrict__ w2,
                                  const float* __restrict__ b2, float* __restrict__ out)
{
    int b = blockIdx.x, tid = threadIdx.x;
    float s = 0.f;
    for (int i = tid; i < PHID; i += 256) s = fmaf(p[(size_t)b * PHID + i], w2[i], s);
    __shared__ float red[256];
    red[tid] = s; __syncthreads();
    for (int st = 128; st; st >>= 1) { if (tid < st) red[tid] += red[tid + st]; __syncthreads(); }
    if (tid == 0) out[b] = red[0] + b2[0];
}

// ---------------- host launch ----------------
extern "C" void kernel_launch(void* const* d_in, const int* in_sizes, int n_in,
                              void* d_out, int out_size)
{
    const float* x        = (const float*)d_in[0];
    const float* stem_w   = (const float*)d_in[1];
    const float* stem_b   = (const float*)d_in[2];
    const float* pos      = (const float*)d_in[3];
    const float* att_w1   = (const float*)d_in[4];
    const float* att_b1   = (const float*)d_in[5];
    const float* att_w2   = (const float*)d_in[6];
    const float* att_b2   = (const float*)d_in[7];
    const float* gnn_w1   = (const float*)d_in[8];
    const float* gnn_b1   = (const float*)d_in[9];
    const float* gnn_w2   = (const float*)d_in[10];
    const float* gnn_b2   = (const float*)d_in[11];
    const float* ffn_w1   = (const float*)d_in[12];
    const float* ffn_b1   = (const float*)d_in[13];
    const float* ffn_g1   = (const float*)d_in[14];
    const float* ffn_be1  = (const float*)d_in[15];
    const float* ffn_w2   = (const float*)d_in[16];
    const float* ffn_b2   = (const float*)d_in[17];
    const float* ffn_g2   = (const float*)d_in[18];
    const float* ffn_be2  = (const float*)d_in[19];
    const float* pred_w1  = (const float*)d_in[20];
    const float* pred_b1  = (const float*)d_in[21];
    const float* pred_g   = (const float*)d_in[22];
    const float* pred_be  = (const float*)d_in[23];
    const float* pred_w2  = (const float*)d_in[24];
    const float* pred_b2  = (const float*)d_in[25];
    float* out = (float*)d_out;

    float *p_wt, *p_nf, *p_sq, *p_d2, *p_P, *p_Q, *p_att, *p_h, *p_hm, *p_u, *p_t, *p_g, *p_p;
    uint32_t *p_nfh;
    int* p_idx;
    cudaGetSymbolAddress((void**)&p_wt,  g_wt);
    cudaGetSymbolAddress((void**)&p_nf,  g_nf);
    cudaGetSymbolAddress((void**)&p_nfh, g_nfh);
    cudaGetSymbolAddress((void**)&p_sq,  g_sq);
    cudaGetSymbolAddress((void**)&p_d2,  g_d2);
    cudaGetSymbolAddress((void**)&p_idx, g_idx);
    cudaGetSymbolAddress((void**)&p_P,   g_P);
    cudaGetSymbolAddress((void**)&p_Q,   g_Q);
    cudaGetSymbolAddress((void**)&p_att, g_att);
    cudaGetSymbolAddress((void**)&p_h,   g_h);
    cudaGetSymbolAddress((void**)&p_hm,  g_hm);
    cudaGetSymbolAddress((void**)&p_u,   g_u);
    cudaGetSymbolAddress((void**)&p_t,   g_t);
    cudaGetSymbolAddress((void**)&p_g,   g_g);
    cudaGetSymbolAddress((void**)&p_p,   g_p);

    cudaFuncSetAttribute(gram_x3_sym_kernel,
                         cudaFuncAttributeMaxDynamicSharedMemorySize, 30720);
    cudaFuncSetAttribute(stem_x3_kernel,
                         cudaFuncAttributeMaxDynamicSharedMemorySize, 30720);
    cudaFuncSetAttribute(tf32gemm_pipe_kernel<0>,
                         cudaFuncAttributeMaxDynamicSharedMemorySize, 30720);
    cudaFuncSetAttribute(tf32gemm_pipe_kernel<1>,
                         cudaFuncAttributeMaxDynamicSharedMemorySize, 30720);

    transpose_w_kernel<<<(192 * 768 + 255) / 256, 256>>>(stem_w, p_wt);

    // ---- graph path ----
    stem_x3_kernel<<<dim3(CH / 64, BN / 128), 256, 30720>>>(
        x, p_wt, p_nf, p_nfh, stem_b, pos);
    sq_kernel<<<(BN * 32 + 255) / 256, 256>>>(p_nf, p_sq);
    gram_x3_sym_kernel<<<dim3(45, 1, Bsz), 128, 30720>>>(p_nf, p_sq, p_d2);
    topk_kernel<<<(BN * 32 + 255) / 256, 256>>>(p_d2, p_idx);

    // ---- edge attention (tf32; pipelined, bit-identical) ----
    tf32gemm_pipe_kernel<0><<<dim3(CH / 64, BN / 128), 256, 30720>>>(
        p_nfh, att_w1, p_P, BN, CH, CH, nullptr);
    tf32gemm_pipe_kernel<1><<<dim3(CH / 64, BN / 128), 256, 30720>>>(
        p_nfh, att_w1 + 192 * 192, p_Q, BN, CH, CH, att_b1);
    edge_kernel<<<(BN * 32 + 255) / 256, 256>>>(p_P, p_Q, p_idx, att_w2, att_b2, p_att, out);

    // ---- prediction path (bf16) ----
    agg_kernel<<<BN, CH>>>(p_nf, p_idx, p_att, p_hm);
    bf16gemm_kernel<2><<<dim3(CH / 64, BN / 128), 256>>>(p_hm, gnn_w1, p_h, BN, CH, CH,
                                                         gnn_b1, nullptr, nullptr, nullptr);
    agg_kernel<<<BN, CH>>>(p_h, p_idx, p_att, p_hm);
    bf16gemm_kernel<2><<<dim3(CH / 64, BN / 128), 256>>>(p_hm, gnn_w2, p_h, BN, CH, CH,
                                                         gnn_b2, nullptr, nullptr, nullptr);
    bf16gemm_kernel<3><<<dim3(HID / 64, BN / 128), 256>>>(p_h, ffn_w1, p_u, BN, HID, CH,
                                                          ffn_b1, ffn_g1, ffn_be1, nullptr);
    bf16gemm_kernel<4><<<dim3(CH / 64, BN / 128), 256>>>(p_u, ffn_w2, p_t, BN, CH, HID,
                                                         ffn_b2, ffn_g2, ffn_be2, p_h);

    pool_kernel<<<Bsz, CH>>>(p_t, p_g);
    sgemm_kernel<3><<<dim3(PHID / BNT, Bsz / BM), 256>>>(p_g, pred_w1, p_p, Bsz, PHID, CH,
                                                         pred_b1, pred_g, pred_be, nullptr);
    pred_final_kernel<<<Bsz, 256>>>(p_p, pred_w2, pred_b2, out + EDG);
}

// round 17
// speedup vs baseline: 1.2682x; 1.0154x over previous
#include <cuda_runtime.h>
#include <cuda_bf16.h>
#include <math.h>
#include <stdint.h>

// ---------------- problem constants ----------------
#define Bsz   64
#define IMGSZ 384
#define PATCH 16
#define CH    192
#define KNN   5
#define HGRID 24
#define NNODE 576
#define BN    (Bsz * NNODE)  // 36864
#define EDG   (BN * KNN)     // 184320
#define HID   768
#define PHID  1024

// ---------------- scratch ----------------
__device__ float    g_wt  [768 * 192];
__device__ float    g_nf  [(size_t)BN * CH];
__device__ uint32_t g_nfh [(size_t)BN * CH];
__device__ float    g_sq  [BN];
__device__ float    g_d2  [(size_t)Bsz * NNODE * NNODE];
__device__ int      g_idx [BN * KNN];
__device__ float    g_P   [(size_t)BN * CH];
__device__ float    g_Q   [(size_t)BN * CH];
__device__ float    g_att [EDG];
__device__ float    g_h   [(size_t)BN * CH];
__device__ float    g_hm  [(size_t)BN * CH];
__device__ float    g_u   [(size_t)BN * HID];
__device__ float    g_t   [(size_t)BN * CH];
__device__ float    g_g   [Bsz * CH];
__device__ float    g_p   [Bsz * PHID];

__device__ __forceinline__ float gelu_exact(float v) {
    return 0.5f * v * (1.0f + erff(v * 0.70710678118654752f));
}
__device__ __forceinline__ uint32_t f2tf32(float x) {
    uint32_t r; asm("cvt.rna.tf32.f32 %0, %1;" : "=r"(r) : "f"(x)); return r;
}
__device__ __forceinline__ void split_tf32(float x, uint32_t& hi, uint32_t& lo) {
    hi = f2tf32(x);
    lo = f2tf32(x - __uint_as_float(hi));
}
__device__ __forceinline__ void split4(const uint32_t* r, uint32_t* h, uint32_t* l) {
#pragma unroll
    for (int i = 0; i < 4; i++) {
        float v = __uint_as_float(r[i]);
        split_tf32(v, h[i], l[i]);
    }
}
__device__ __forceinline__ void split2(const uint32_t* r, uint32_t* h, uint32_t* l) {
#pragma unroll
    for (int i = 0; i < 2; i++) {
        float v = __uint_as_float(r[i]);
        split_tf32(v, h[i], l[i]);
    }
}
__device__ __forceinline__ uint32_t smem_u32(const void* p) {
    return (uint32_t)__cvta_generic_to_shared(p);
}
__device__ __forceinline__ void ldsm4(uint32_t& r0, uint32_t& r1, uint32_t& r2,
                                      uint32_t& r3, uint32_t a) {
    asm volatile("ldmatrix.sync.aligned.m8n8.x4.shared.b16 {%0,%1,%2,%3}, [%4];"
                 : "=r"(r0), "=r"(r1), "=r"(r2), "=r"(r3) : "r"(a));
}
__device__ __forceinline__ uint32_t pkbf2(float a, float b) {
    __nv_bfloat162 t = __floats2bfloat162_rn(a, b);
    return *(uint32_t*)&t;
}
__device__ __forceinline__ void cp16(uint32_t dst, const void* src) {
    asm volatile("cp.async.cg.shared.global [%0], [%1], 16;" :: "r"(dst), "l"(src));
}
__device__ __forceinline__ void cp4(uint32_t dst, const void* src) {
    asm volatile("cp.async.ca.shared.global [%0], [%1], 4;" :: "r"(dst), "l"(src));
}
__device__ __forceinline__ void cp_commit() { asm volatile("cp.async.commit_group;"); }
__device__ __forceinline__ void cp_wait1()  { asm volatile("cp.async.wait_group 1;"); }
__device__ __forceinline__ void cp_wait0()  { asm volatile("cp.async.wait_group 0;"); }

#define MMA_TF32(acc, a0, a1, a2, a3, b0, b1)                                \
    asm volatile(                                                            \
        "mma.sync.aligned.m16n8k8.row.col.f32.tf32.tf32.f32 "               \
        "{%0,%1,%2,%3}, {%4,%5,%6,%7}, {%8,%9}, {%0,%1,%2,%3};"             \
        : "+f"(acc[0]), "+f"(acc[1]), "+f"(acc[2]), "+f"(acc[3])             \
        : "r"(a0), "r"(a1), "r"(a2), "r"(a3), "r"(b0), "r"(b1))
#define MMA_BF16(acc, a0, a1, a2, a3, b0, b1)                                \
    asm volatile(                                                            \
        "mma.sync.aligned.m16n8k16.row.col.f32.bf16.bf16.f32 "              \
        "{%0,%1,%2,%3}, {%4,%5,%6,%7}, {%8,%9}, {%0,%1,%2,%3};"             \
        : "+f"(acc[0]), "+f"(acc[1]), "+f"(acc[2]), "+f"(acc[3])             \
        : "r"(a0), "r"(a1), "r"(a2), "r"(a3), "r"(b0), "r"(b1))

#define LDSM_OFFS()                                                          \
    const int lrA = lane & 15;                                               \
    const int lcA = (lane >> 4) * 4;                                         \
    const int lrB = ((lane >> 4) << 3) + (lane & 7);                         \
    const int lcB = ((lane >> 3) & 1) * 4

__device__ __forceinline__ void mma_x3_frag(
    float acc[2][4][4], const uint32_t ar[2][4], const uint32_t br[4][2])
{
    uint32_t ah[2][4], al[2][4], bh[4][2], bl[4][2];
#pragma unroll
    for (int im = 0; im < 2; im++) split4(ar[im], ah[im], al[im]);
#pragma unroll
    for (int in = 0; in < 4; in++) split2(br[in], bh[in], bl[in]);
#pragma unroll
    for (int im = 0; im < 2; im++)
#pragma unroll
        for (int in = 0; in < 4; in++) {
            MMA_TF32(acc[im][in], ah[im][0], ah[im][1], ah[im][2], ah[im][3],
                     bh[in][0], bh[in][1]);
            MMA_TF32(acc[im][in], ah[im][0], ah[im][1], ah[im][2], ah[im][3],
                     bl[in][0], bl[in][1]);
            MMA_TF32(acc[im][in], al[im][0], al[im][1], al[im][2], al[im][3],
                     bh[in][0], bh[in][1]);
        }
}

// =================================================================
// gram: raw-stage tf32x3 + symmetry + 2-stage cp.async (R15 WIN).
// Stage 10240 B; 2 stages = 20480 B dynamic.
// =================================================================
__global__ __launch_bounds__(128) void gram_x3_sym_kernel(
    const float* __restrict__ nf, const float* __restrict__ sq, float* __restrict__ d2)
{
    extern __shared__ uint32_t DSM[];
    const int b = blockIdx.z;
    const float* Ab = nf + (size_t)b * NNODE * CH;

    int p = blockIdx.x, ti = 0;
    while (p >= 9 - ti) { p -= 9 - ti; ti++; }
    const int tj = ti + p;
    const int r0b = ti * 64, c0b = tj * 64;

    const int tid  = threadIdx.x;
    const int lane = tid & 31, wid = tid >> 5;
    const int wm = (wid >> 1) * 32, wn = (wid & 1) * 32;
    const int row = tid >> 1, kq = (tid & 1) * 8;
    const int g = lane >> 2, cq = lane & 3;
    LDSM_OFFS();
    const uint32_t base = smem_u32(DSM);

    auto fill = [&](int k0, int st) {
        uint32_t sb = base + (uint32_t)st * 10240u;
        const float* ra = Ab + (size_t)(r0b + row) * CH + k0 + kq;
        const float* rb = Ab + (size_t)(c0b + row) * CH + k0 + kq;
#pragma unroll
        for (int i = 0; i < 2; i++) {
            uint32_t off = (uint32_t)(row * 20 + kq + i * 4) * 4;
            cp16(sb + off,        ra + i * 4);
            cp16(sb + 5120 + off, rb + i * 4);
        }
        cp_commit();
    };

    float acc[2][4][4] = {};

    const int NS = CH / 16;   // 12
    fill(0, 0);
    for (int s = 0; s < NS; s++) {
        if (s + 1 < NS) fill((s + 1) * 16, (s + 1) & 1);
        if (s + 1 < NS) cp_wait1(); else cp_wait0();
        __syncthreads();

        uint32_t sb = base + (uint32_t)(s & 1) * 10240u;
        const uint32_t bA = sb, bB = sb + 5120;
#pragma unroll
        for (int kk = 0; kk < 16; kk += 8) {
            uint32_t ar[2][4], br[4][2];
#pragma unroll
            for (int im = 0; im < 2; im++) {
                uint32_t off = ((wm + im * 16 + lrA) * 20 + kk + lcA) * 4;
                ldsm4(ar[im][0], ar[im][1], ar[im][2], ar[im][3], bA + off);
            }
#pragma unroll
            for (int q = 0; q < 2; q++) {
                uint32_t off = ((wn + q * 16 + lrB) * 20 + kk + lcB) * 4;
                ldsm4(br[2*q][0], br[2*q][1], br[2*q+1][0], br[2*q+1][1], bB + off);
            }
            mma_x3_frag(acc, ar, br);
        }
        __syncthreads();
    }

#pragma unroll
    for (int im = 0; im < 2; im++)
#pragma unroll
        for (int in = 0; in < 4; in++) {
            int cbase = c0b + wn + in * 8 + 2 * cq;
#pragma unroll
            for (int half = 0; half < 2; half++) {
                int r = r0b + wm + im * 16 + g + half * 8;
#pragma unroll
                for (int jj = 0; jj < 2; jj++) {
                    int c = cbase + jj;
                    float v = sq[b * NNODE + c] - 2.0f * acc[im][in][half * 2 + jj];
                    if (r == c) v = 3.0e38f;
                    d2[((size_t)b * NNODE + r) * NNODE + c] = v;
                }
            }
        }

    if (ti != tj) {
        float* T = (float*)DSM;   // 64x68 floats = 17408 B <= 20480
#pragma unroll
        for (int im = 0; im < 2; im++)
#pragma unroll
            for (int in = 0; in < 4; in++) {
                int cl = wn + in * 8 + 2 * cq;
#pragma unroll
                for (int half = 0; half < 2; half++) {
                    int rl = wm + im * 16 + g + half * 8;
                    T[(cl    ) * 68 + rl] = acc[im][in][half * 2 + 0];
                    T[(cl + 1) * 68 + rl] = acc[im][in][half * 2 + 1];
                }
            }
        __syncthreads();
        for (int i = tid; i < 64 * 16; i += 128) {
            int cl = i >> 4;
            int r4 = (i & 15) * 4;
            float4 dv = *(const float4*)&T[cl * 68 + r4];
            float4 sv = *(const float4*)&sq[b * NNODE + r0b + r4];
            float4 o;
            o.x = sv.x - 2.0f * dv.x;
            o.y = sv.y - 2.0f * dv.y;
            o.z = sv.z - 2.0f * dv.z;
            o.w = sv.w - 2.0f * dv.w;
            *(float4*)&d2[((size_t)b * NNODE + c0b + cl) * NNODE + r0b + r4] = o;
        }
    }
}

// =================================================================
// stem: raw-stage tf32x3 + cp.async pipeline, slab 16 (R15 WIN).
// =================================================================
__global__ __launch_bounds__(256) void stem_x3_kernel(
    const float* __restrict__ X, const float* __restrict__ Bw, float* __restrict__ C,
    uint32_t* __restrict__ Ch,
    const float* __restrict__ bias, const float* __restrict__ pos)
{
    extern __shared__ uint32_t DSM[];
    const int Nd = 192, Kd = 768;
    const int tid  = threadIdx.x;
    const int lane = tid & 31, wid = tid >> 5;
    const int wm = (wid >> 1) * 32, wn = (wid & 1) * 32;
    const int m0 = blockIdx.y * 128, n0 = blockIdx.x * 64;
    const int a_row = tid >> 1, kq = (tid & 1) * 8;
    const int b_n = tid & 63, b_k0 = (tid >> 6) * 4;
    const int g = lane >> 2, cq = lane & 3;
    LDSM_OFFS();
    const uint32_t base = smem_u32(DSM);

    const int m = m0 + a_row;
    const int bimg = m / NNODE;
    const int nsp = m % NNODE;
    const int py = nsp / HGRID, px = nsp % HGRID;
    const float* xbase = X + (size_t)bimg * 3 * IMGSZ * IMGSZ
                           + (size_t)(py * PATCH) * IMGSZ + px * PATCH;

    auto fill = [&](int k0, int st) {
        uint32_t sb = base + (uint32_t)st * 15360u;
        int kg = k0 + kq;
        int ci = kg >> 8, ky = (kg >> 4) & 15, kx = kg & 15;
        const float* xr = xbase + (size_t)ci * IMGSZ * IMGSZ + ky * IMGSZ + kx;
#pragma unroll
        for (int i = 0; i < 2; i++) {
            uint32_t off = (uint32_t)(a_row * 20 + kq + i * 4) * 4;
            cp16(sb + off, xr + i * 4);
        }
#pragma unroll
        for (int i = 0; i < 4; i++) {
            uint32_t off = (uint32_t)(b_n * 20 + b_k0 + i) * 4;
            cp4(sb + 10240 + off, Bw + (size_t)(k0 + b_k0 + i) * Nd + n0 + b_n);
        }
        cp_commit();
    };

    float acc[2][4][4] = {};

    const int NS = Kd / 16;   // 48
    fill(0, 0);
    for (int s = 0; s < NS; s++) {
        if (s + 1 < NS) fill((s + 1) * 16, (s + 1) & 1);
        if (s + 1 < NS) cp_wait1(); else cp_wait0();
        __syncthreads();

        uint32_t sb = base + (uint32_t)(s & 1) * 15360u;
        const uint32_t bA = sb, bB = sb + 10240;
#pragma unroll
        for (int kk = 0; kk < 16; kk += 8) {
            uint32_t ar[2][4], br[4][2];
#pragma unroll
            for (int im = 0; im < 2; im++) {
                uint32_t off = ((wm + im * 16 + lrA) * 20 + kk + lcA) * 4;
                ldsm4(ar[im][0], ar[im][1], ar[im][2], ar[im][3], bA + off);
            }
#pragma unroll
            for (int q = 0; q < 2; q++) {
                uint32_t off = ((wn + q * 16 + lrB) * 20 + kk + lcB) * 4;
                ldsm4(br[2*q][0], br[2*q][1], br[2*q+1][0], br[2*q+1][1], bB + off);
            }
            mma_x3_frag(acc, ar, br);
        }
        __syncthreads();
    }

#pragma unroll
    for (int im = 0; im < 2; im++)
#pragma unroll
        for (int in = 0; in < 4; in++) {
            int cbase = n0 + wn + in * 8 + 2 * cq;
#pragma unroll
            for (int half = 0; half < 2; half++) {
                int mm = m0 + wm + im * 16 + g + half * 8;
                int sp = mm % NNODE;
#pragma unroll
                for (int jj = 0; jj < 2; jj++) {
                    int n = cbase + jj;
                    float v = acc[im][in][half * 2 + jj] + bias[n] + pos[n * NNODE + sp];
                    C[(size_t)mm * CH + n] = v;
                    Ch[(size_t)mm * CH + n] = f2tf32(v);
                }
            }
        }
}

// =================================================================
// P/Q tf32 GEMM: cp.async pipelined (R16 version, bit-identical)
// =================================================================
template <int EPI>
__global__ __launch_bounds__(256) void tf32gemm_pipe_kernel(
    const uint32_t* __restrict__ Ai, const float* __restrict__ B, float* __restrict__ C,
    int M, int N, int K,
    const float* __restrict__ bias)
{
    extern __shared__ uint32_t DSM[];
    const int tid  = threadIdx.x;
    const int lane = tid & 31, wid = tid >> 5;
    const int wm = (wid >> 1) * 32, wn = (wid & 1) * 32;
    const int m0 = blockIdx.y * 128, n0 = blockIdx.x * 64;
    const int a_row = tid >> 1, kq = (tid & 1) * 8;
    const int b_n = tid & 63, b_k0 = (tid >> 6) * 4;
    const int g = lane >> 2, cq = lane & 3;
    LDSM_OFFS();
    const uint32_t base = smem_u32(DSM);

    auto fill = [&](int k0, int st) {
        uint32_t sb = base + (uint32_t)st * 15360u;
        const uint32_t* ra = Ai + (size_t)(m0 + a_row) * K + k0 + kq;
#pragma unroll
        for (int i = 0; i < 2; i++) {
            uint32_t off = (uint32_t)(a_row * 20 + kq + i * 4) * 4;
            cp16(sb + off, ra + i * 4);
        }
#pragma unroll
        for (int i = 0; i < 4; i++) {
            uint32_t off = (uint32_t)(b_n * 20 + b_k0 + i) * 4;
            cp4(sb + 10240 + off, B + (size_t)(k0 + b_k0 + i) * N + n0 + b_n);
        }
        cp_commit();
    };

    float acc[2][4][4] = {};

    const int NS = K / 16;
    fill(0, 0);
    for (int s = 0; s < NS; s++) {
        if (s + 1 < NS) fill((s + 1) * 16, (s + 1) & 1);
        if (s + 1 < NS) cp_wait1(); else cp_wait0();
        __syncthreads();

        uint32_t sb = base + (uint32_t)(s & 1) * 15360u;
        const uint32_t bA = sb, bB = sb + 10240;
#pragma unroll
        for (int kk = 0; kk < 16; kk += 8) {
            uint32_t af[2][4], br[4][2], bf[4][2];
#pragma unroll
            for (int im = 0; im < 2; im++) {
                uint32_t off = ((wm + im * 16 + lrA) * 20 + kk + lcA) * 4;
                ldsm4(af[im][0], af[im][1], af[im][2], af[im][3], bA + off);
            }
#pragma unroll
            for (int q = 0; q < 2; q++) {
                uint32_t off = ((wn + q * 16 + lrB) * 20 + kk + lcB) * 4;
                ldsm4(br[2*q][0], br[2*q][1], br[2*q+1][0], br[2*q+1][1], bB + off);
            }
#pragma unroll
            for (int in = 0; in < 4; in++) {
                bf[in][0] = f2tf32(__uint_as_float(br[in][0]));
                bf[in][1] = f2tf32(__uint_as_float(br[in][1]));
            }
#pragma unroll
            for (int im = 0; im < 2; im++)
#pragma unroll
                for (int in = 0; in < 4; in++)
                    MMA_TF32(acc[im][in], af[im][0], af[im][1], af[im][2], af[im][3],
                             bf[in][0], bf[in][1]);
        }
        __syncthreads();
    }

#pragma unroll
    for (int im = 0; im < 2; im++)
#pragma unroll
        for (int in = 0; in < 4; in++) {
            int cbase = n0 + wn + in * 8 + 2 * cq;
#pragma unroll
            for (int half = 0; half < 2; half++) {
                int m = m0 + wm + im * 16 + g + half * 8;
#pragma unroll
                for (int jj = 0; jj < 2; jj++) {
                    int n = cbase + jj;
                    float v = acc[im][in][half * 2 + jj];
                    if (EPI == 1) v += bias[n];
                    C[(size_t)m * N + n] = v;
                }
            }
        }
}

// =================================================================
// bf16 GEMM (prediction path) with register-prefetch double buffer:
// next slab's raw A/B loaded into regs during current MMA; packed
// values identical -> outputs bit-identical to R16.
// =================================================================
template <int EPI>
__global__ __launch_bounds__(256) void bf16gemm_kernel(
    const float* __restrict__ A, const float* __restrict__ B, float* __restrict__ C,
    int M, int N, int K,
    const float* __restrict__ bias, const float* __restrict__ gam,
    const float* __restrict__ bet,  const float* __restrict__ res)
{
    __shared__ __nv_bfloat16 As[2][128][40];
    __shared__ __nv_bfloat16 Bs[2][64][40];
    const int tid  = threadIdx.x;
    const int lane = tid & 31, wid = tid >> 5;
    const int wm = (wid >> 1) * 32;
    const int wn = (wid & 1) * 32;
    const int m0 = blockIdx.y * 128, n0 = blockIdx.x * 64;
    const int a_row = tid >> 1, a_k0 = (tid & 1) * 16;
    const int b_n = tid & 63, b_k0 = (tid >> 6) * 8;
    const int g = lane >> 2, cq = lane & 3;
    const int lrA = lane & 15;
    const int lcA = (lane >> 4) * 8;
    const int lrB = ((lane >> 4) << 3) + (lane & 7);
    const int lcB = ((lane >> 3) & 1) * 8;

    float acc[2][4][4] = {};
    float4 ra[4];
    float rb[8];

    auto load_regs = [&](int k0) {
        const float* Ap = &A[(size_t)(m0 + a_row) * K + k0 + a_k0];
        ra[0] = *(const float4*)(Ap + 0);
        ra[1] = *(const float4*)(Ap + 4);
        ra[2] = *(const float4*)(Ap + 8);
        ra[3] = *(const float4*)(Ap + 12);
#pragma unroll
        for (int i = 0; i < 8; i++)
            rb[i] = B[(size_t)(k0 + b_k0 + i) * N + n0 + b_n];
    };
    auto store_smem = [&](int buf) {
        uint4 u0, u1;
        u0.x = pkbf2(ra[0].x, ra[0].y); u0.y = pkbf2(ra[0].z, ra[0].w);
        u0.z = pkbf2(ra[1].x, ra[1].y); u0.w = pkbf2(ra[1].z, ra[1].w);
        u1.x = pkbf2(ra[2].x, ra[2].y); u1.y = pkbf2(ra[2].z, ra[2].w);
        u1.z = pkbf2(ra[3].x, ra[3].y); u1.w = pkbf2(ra[3].z, ra[3].w);
        *(uint4*)&As[buf][a_row][a_k0 + 0] = u0;
        *(uint4*)&As[buf][a_row][a_k0 + 8] = u1;
        uint4 u;
        u.x = pkbf2(rb[0], rb[1]); u.y = pkbf2(rb[2], rb[3]);
        u.z = pkbf2(rb[4], rb[5]); u.w = pkbf2(rb[6], rb[7]);
        *(uint4*)&Bs[buf][b_n][b_k0] = u;
    };

    load_regs(0);
    int buf = 0;
    for (int k0 = 0; k0 < K; k0 += 32) {
        store_smem(buf);
        __syncthreads();
        if (k0 + 32 < K) load_regs(k0 + 32);

        const uint32_t bA = smem_u32(&As[buf][0][0]);
        const uint32_t bB = smem_u32(&Bs[buf][0][0]);
#pragma unroll
        for (int kk = 0; kk < 32; kk += 16) {
            uint32_t af[2][4], bf[4][2];
#pragma unroll
            for (int im = 0; im < 2; im++) {
                uint32_t off = ((wm + im * 16 + lrA) * 40 + kk + lcA) * 2;
                ldsm4(af[im][0], af[im][1], af[im][2], af[im][3], bA + off);
            }
#pragma unroll
            for (int q = 0; q < 2; q++) {
                uint32_t off = ((wn + q * 16 + lrB) * 40 + kk + lcB) * 2;
                ldsm4(bf[2*q][0], bf[2*q][1], bf[2*q+1][0], bf[2*q+1][1], bB + off);
            }
#pragma unroll
            for (int im = 0; im < 2; im++)
#pragma unroll
                for (int in = 0; in < 4; in++)
                    MMA_BF16(acc[im][in], af[im][0], af[im][1], af[im][2], af[im][3],
                             bf[in][0], bf[in][1]);
        }
        buf ^= 1;
    }

#pragma unroll
    for (int im = 0; im < 2; im++)
#pragma unroll
        for (int in = 0; in < 4; in++) {
            int cbase = n0 + wn + in * 8 + 2 * cq;
#pragma unroll
            for (int half = 0; half < 2; half++) {
                int m = m0 + wm + im * 16 + g + half * 8;
#pragma unroll
                for (int jj = 0; jj < 2; jj++) {
                    int n = cbase + jj;
                    float v = acc[im][in][half * 2 + jj];
                    if (EPI == 1) v += bias[n];
                    if (EPI == 2) v = fmaxf(v + bias[n], 0.0f);
                    if (EPI == 3) v = gelu_exact((v + bias[n]) * gam[n] + bet[n]);
                    if (EPI == 4) v = res[(size_t)m * N + n] + (v + bias[n]) * gam[n] + bet[n];
                    C[(size_t)m * N + n] = v;
                }
            }
        }
}

// ---------------- small-M SGEMM for pred head (M=64) ----------------
#define BM 64
#define BNT 64
#define BKT 16
template <int EPI>
__global__ __launch_bounds__(256) void sgemm_kernel(
    const float* __restrict__ A, const float* __restrict__ B, float* __restrict__ C,
    int M, int N, int K,
    const float* __restrict__ bias, const float* __restrict__ gam,
    const float* __restrict__ bet,  const float* __restrict__ res)
{
    __shared__ float As[BKT][BM];
    __shared__ float Bs[BKT][BNT];
    const int tid = threadIdx.x;
    const int tx = tid & 15, ty = tid >> 4;
    const int m0 = blockIdx.y * BM, n0 = blockIdx.x * BNT;
    const int a_m = tid >> 2, a_k = (tid & 3) * 4;
    const int b_k = tid >> 4, b_n = (tid & 15) * 4;

    float acc[4][4] = {};
    for (int k0 = 0; k0 < K; k0 += BKT) {
        float4 av = *(const float4*)&A[(size_t)(m0 + a_m) * K + k0 + a_k];
        As[a_k + 0][a_m] = av.x; As[a_k + 1][a_m] = av.y;
        As[a_k + 2][a_m] = av.z; As[a_k + 3][a_m] = av.w;
        float4 bv = *(const float4*)&B[(size_t)(k0 + b_k) * N + n0 + b_n];
        *(float4*)&Bs[b_k][b_n] = bv;
        __syncthreads();
#pragma unroll
        for (int k = 0; k < BKT; k++) {
            float ar[4], br[4];
#pragma unroll
            for (int i = 0; i < 4; i++) ar[i] = As[k][ty * 4 + i];
#pragma unroll
            for (int j = 0; j < 4; j++) br[j] = Bs[k][tx * 4 + j];
#pragma unroll
            for (int i = 0; i < 4; i++)
#pragma unroll
                for (int j = 0; j < 4; j++) acc[i][j] = fmaf(ar[i], br[j], acc[i][j]);
        }
        __syncthreads();
    }
#pragma unroll
    for (int i = 0; i < 4; i++) {
        int m = m0 + ty * 4 + i;
#pragma unroll
        for (int j = 0; j < 4; j++) {
            int n = n0 + tx * 4 + j;
            float v = acc[i][j];
            if (EPI == 1) v += bias[n];
            if (EPI == 2) v = fmaxf(v + bias[n], 0.0f);
            if (EPI == 3) v = gelu_exact((v + bias[n]) * gam[n] + bet[n]);
            if (EPI == 4) v = res[(size_t)m * N + n] + (v + bias[n]) * gam[n] + bet[n];
            C[(size_t)m * N + n] = v;
        }
    }
}

// ---------------- auxiliary kernels ----------------
__global__ void transpose_w_kernel(const float* __restrict__ w, float* __restrict__ wt) {
    int i = blockIdx.x * blockDim.x + threadIdx.x;
    if (i >= 192 * 768) return;
    int n = i / 768, k = i % 768;
    wt[k * 192 + n] = w[i];
}

__global__ void sq_kernel(const float* __restrict__ nf, float* __restrict__ sq) {
    int node = (blockIdx.x * blockDim.x + threadIdx.x) >> 5;
    int lane = threadIdx.x & 31;
    if (node >= BN) return;
    float s = 0.f;
#pragma unroll
    for (int j = 0; j < 6; j++) {
        float x = nf[(size_t)node * CH + lane + 32 * j];
        s = fmaf(x, x, s);
    }
#pragma unroll
    for (int off = 16; off; off >>= 1) s += __shfl_down_sync(0xffffffffu, s, off);
    if (lane == 0) sq[node] = s;
}

__global__ void topk_kernel(const float* __restrict__ d2, int* __restrict__ idx) {
    int row = (blockIdx.x * blockDim.x + threadIdx.x) >> 5;
    int lane = threadIdx.x & 31;
    if (row >= BN) return;
    const float* r = d2 + (size_t)row * NNODE;
    float v[18];
#pragma unroll
    for (int j = 0; j < 18; j++) v[j] = r[lane + 32 * j];
    int bimg = row / NNODE;
#pragma unroll
    for (int s = 0; s < 5; s++) {
        float bv = 3.4e38f; int bc = 1 << 30;
#pragma unroll
        for (int j = 0; j < 18; j++) {
            int c = lane + 32 * j;
            if (v[j] < bv) { bv = v[j]; bc = c; }
        }
#pragma unroll
        for (int off = 16; off; off >>= 1) {
            float ov = __shfl_down_sync(0xffffffffu, bv, off);
            int   oc = __shfl_down_sync(0xffffffffu, bc, off);
            if (ov < bv || (ov == bv && oc < bc)) { bv = ov; bc = oc; }
        }
        bc = __shfl_sync(0xffffffffu, bc, 0);
        if ((bc & 31) == lane) v[bc >> 5] = 3.4e38f;
        if (lane == 0) idx[row * KNN + s] = bimg * NNODE + bc;
    }
}

__global__ void edge_kernel(const float* __restrict__ P, const float* __restrict__ Q,
                            const int* __restrict__ idx,
                            const float* __restrict__ w2, const float* __restrict__ b2,
                            float* __restrict__ att, float* __restrict__ out)
{
    int node = (blockIdx.x * blockDim.x + threadIdx.x) >> 5;
    int lane = threadIdx.x & 31;
    if (node >= BN) return;
    float q[6], w[6];
#pragma unroll
    for (int j = 0; j < 6; j++) {
        q[j] = Q[(size_t)node * CH + lane + 32 * j];
        w[j] = w2[lane + 32 * j];
    }
    const float b2v = b2[0];
#pragma unroll
    for (int k = 0; k < KNN; k++) {
        int e = node * KNN + k;
        int src = idx[e];
        float s = 0.f;
#pragma unroll
        for (int j = 0; j < 6; j++) {
            float x = P[(size_t)src * CH + lane + 32 * j] + q[j];
            x = fmaxf(x, 0.f);
            s = fmaf(x, w[j], s);
        }
#pragma unroll
        for (int off = 16; off; off >>= 1) s += __shfl_down_sync(0xffffffffu, s, off);
        if (lane == 0) {
            float a = 1.0f / (1.0f + expf(-(s + b2v)));
            att[e] = a;
            out[e] = a;
        }
    }
}

__global__ void agg_kernel(const float* __restrict__ h, const int* __restrict__ idx,
                           const float* __restrict__ att, float* __restrict__ hm)
{
    int i = blockIdx.x;
    int c = threadIdx.x;
    float acc = h[(size_t)i * CH + c];
#pragma unroll
    for (int k = 0; k < KNN; k++) {
        int nb = idx[i * KNN + k];
        float a = att[i * KNN + k];
        acc = fmaf(a, h[(size_t)nb * CH + c], acc);
    }
    hm[(size_t)i * CH + c] = acc;
}

__global__ void pool_kernel(const float* __restrict__ t, float* __restrict__ g) {
    int b = blockIdx.x, c = threadIdx.x;
    float acc = 0.f;
    for (int n = 0; n < NNODE; n++) acc += t[((size_t)b * NNODE + n) * CH + c];
    g[b * CH + c] = acc * (1.0f / NNODE);
}

__global__ void pred_final_kernel(const float* __restrict__ p, const float* __restrict__ w2,
                                  const float* __restrict__ b2, float* __restrict__ out)
{
    int b = blockIdx.x, tid = threadIdx.x;
    float s = 0.f;
    for (int i = tid; i < PHID; i += 256) s = fmaf(p[(size_t)b * PHID + i], w2[i], s);
    __shared__ float red[256];
    red[tid] = s; __syncthreads();
    for (int st = 128; st; st >>= 1) { if (tid < st) red[tid] += red[tid + st]; __syncthreads(); }
    if (tid == 0) out[b] = red[0] + b2[0];
}

// ---------------- host launch ----------------
extern "C" void kernel_launch(void* const* d_in, const int* in_sizes, int n_in,
                              void* d_out, int out_size)
{
    const float* x        = (const float*)d_in[0];
    const float* stem_w   = (const float*)d_in[1];
    const float* stem_b   = (const float*)d_in[2];
    const float* pos      = (const float*)d_in[3];
    const float* att_w1   = (const float*)d_in[4];
    const float* att_b1   = (const float*)d_in[5];
    const float* att_w2   = (const float*)d_in[6];
    const float* att_b2   = (const float*)d_in[7];
    const float* gnn_w1   = (const float*)d_in[8];
    const float* gnn_b1   = (const float*)d_in[9];
    const float* gnn_w2   = (const float*)d_in[10];
    const float* gnn_b2   = (const float*)d_in[11];
    const float* ffn_w1   = (const float*)d_in[12];
    const float* ffn_b1   = (const float*)d_in[13];
    const float* ffn_g1   = (const float*)d_in[14];
    const float* ffn_be1  = (const float*)d_in[15];
    const float* ffn_w2   = (const float*)d_in[16];
    const float* ffn_b2   = (const float*)d_in[17];
    const float* ffn_g2   = (const float*)d_in[18];
    const float* ffn_be2  = (const float*)d_in[19];
    const float* pred_w1  = (const float*)d_in[20];
    const float* pred_b1  = (const float*)d_in[21];
    const float* pred_g   = (const float*)d_in[22];
    const float* pred_be  = (const float*)d_in[23];
    const float* pred_w2  = (const float*)d_in[24];
    const float* pred_b2  = (const float*)d_in[25];
    float* out = (float*)d_out;

    float *p_wt, *p_nf, *p_sq, *p_d2, *p_P, *p_Q, *p_att, *p_h, *p_hm, *p_u, *p_t, *p_g, *p_p;
    uint32_t *p_nfh;
    int* p_idx;
    cudaGetSymbolAddress((void**)&p_wt,  g_wt);
    cudaGetSymbolAddress((void**)&p_nf,  g_nf);
    cudaGetSymbolAddress((void**)&p_nfh, g_nfh);
    cudaGetSymbolAddress((void**)&p_sq,  g_sq);
    cudaGetSymbolAddress((void**)&p_d2,  g_d2);
    cudaGetSymbolAddress((void**)&p_idx, g_idx);
    cudaGetSymbolAddress((void**)&p_P,   g_P);
    cudaGetSymbolAddress((void**)&p_Q,   g_Q);
    cudaGetSymbolAddress((void**)&p_att, g_att);
    cudaGetSymbolAddress((void**)&p_h,   g_h);
    cudaGetSymbolAddress((void**)&p_hm,  g_hm);
    cudaGetSymbolAddress((void**)&p_u,   g_u);
    cudaGetSymbolAddress((void**)&p_t,   g_t);
    cudaGetSymbolAddress((void**)&p_g,   g_g);
    cudaGetSymbolAddress((void**)&p_p,   g_p);

    cudaFuncSetAttribute(gram_x3_sym_kernel,
                         cudaFuncAttributeMaxDynamicSharedMemorySize, 20480);
    cudaFuncSetAttribute(stem_x3_kernel,
                         cudaFuncAttributeMaxDynamicSharedMemorySize, 30720);
    cudaFuncSetAttribute(tf32gemm_pipe_kernel<0>,
                         cudaFuncAttributeMaxDynamicSharedMemorySize, 30720);
    cudaFuncSetAttribute(tf32gemm_pipe_kernel<1>,
                         cudaFuncAttributeMaxDynamicSharedMemorySize, 30720);

    transpose_w_kernel<<<(192 * 768 + 255) / 256, 256>>>(stem_w, p_wt);

    // ---- graph path ----
    stem_x3_kernel<<<dim3(CH / 64, BN / 128), 256, 30720>>>(
        x, p_wt, p_nf, p_nfh, stem_b, pos);
    sq_kernel<<<(BN * 32 + 255) / 256, 256>>>(p_nf, p_sq);
    gram_x3_sym_kernel<<<dim3(45, 1, Bsz), 128, 20480>>>(p_nf, p_sq, p_d2);
    topk_kernel<<<(BN * 32 + 255) / 256, 256>>>(p_d2, p_idx);

    // ---- edge attention (tf32; pipelined) ----
    tf32gemm_pipe_kernel<0><<<dim3(CH / 64, BN / 128), 256, 30720>>>(
        p_nfh, att_w1, p_P, BN, CH, CH, nullptr);
    tf32gemm_pipe_kernel<1><<<dim3(CH / 64, BN / 128), 256, 30720>>>(
        p_nfh, att_w1 + 192 * 192, p_Q, BN, CH, CH, att_b1);
    edge_kernel<<<(BN * 32 + 255) / 256, 256>>>(p_P, p_Q, p_idx, att_w2, att_b2, p_att, out);

    // ---- prediction path (bf16, reg-prefetch pipelined) ----
    agg_kernel<<<BN, CH>>>(p_nf, p_idx, p_att, p_hm);
    bf16gemm_kernel<2><<<dim3(CH / 64, BN / 128), 256>>>(p_hm, gnn_w1, p_h, BN, CH, CH,
                                                         gnn_b1, nullptr, nullptr, nullptr);
    agg_kernel<<<BN, CH>>>(p_h, p_idx, p_att, p_hm);
    bf16gemm_kernel<2><<<dim3(CH / 64, BN / 128), 256>>>(p_hm, gnn_w2, p_h, BN, CH, CH,
                                                         gnn_b2, nullptr, nullptr, nullptr);
    bf16gemm_kernel<3><<<dim3(HID / 64, BN / 128), 256>>>(p_h, ffn_w1, p_u, BN, HID, CH,
                                                          ffn_b1, ffn_g1, ffn_be1, nullptr);
    bf16gemm_kernel<4><<<dim3(CH / 64, BN / 128), 256>>>(p_u, ffn_w2, p_t, BN, CH, HID,
                                                         ffn_b2, ffn_g2, ffn_be2, p_h);

    pool_kernel<<<Bsz, CH>>>(p_t, p_g);
    sgemm_kernel<3><<<dim3(PHID / BNT, Bsz / BM), 256>>>(p_g, pred_w1, p_p, Bsz, PHID, CH,
                                                         pred_b1, pred_g, pred_be, nullptr);
    pred_final_kernel<<<Bsz, 256>>>(p_p, pred_w2, pred_b2, out + EDG);
}